// round 13
// baseline (speedup 1.0000x reference)
#include <cuda_runtime.h>
#include <cuda_bf16.h>
#include <cstdint>

#define B_ 32
#define S_ 257
#define D_ 1024
#define H_ 16
#define HD_ 64
#define E_ 8
#define R_ 16
#define KE_ 2
#define MTOT (B_*S_)
#define BH_ 16
#define MH_ (BH_*S_)
#define SCALE_Q 0.125f

// ---------------- scratch (device globals: allocation-free) ----------------
__device__ float g_tmp[(size_t)3 * MTOT * D_];
__device__ float g_x2 [(size_t)MTOT * D_];
__device__ float g_xa [(size_t)3 * B_ * KE_ * S_ * R_];
__device__ __nv_bfloat16 g_xhi[(size_t)MTOT * D_];
__device__ __nv_bfloat16 g_xlo[(size_t)MTOT * D_];
__device__ __nv_bfloat16 g_whi[(size_t)4 * D_ * D_];
__device__ __nv_bfloat16 g_wlo[(size_t)4 * D_ * D_];
__device__ __nv_bfloat16 g_qhi[(size_t)MTOT * D_];
__device__ __nv_bfloat16 g_qlo[(size_t)MTOT * D_];
__device__ __nv_bfloat16 g_khi[(size_t)MTOT * D_];
__device__ __nv_bfloat16 g_klo[(size_t)MTOT * D_];
__device__ __nv_bfloat16 g_vhi[(size_t)MTOT * D_];
__device__ __nv_bfloat16 g_vlo[(size_t)MTOT * D_];

// ========================= helpers ==========================================
__device__ __forceinline__ uint32_t smem_u32(const void* p) {
    uint32_t a;
    asm("{ .reg .u64 t; cvta.to.shared.u64 t, %1; cvt.u32.u64 %0, t; }"
        : "=r"(a) : "l"(p));
    return a;
}

#define LDSM4(r0, r1, r2, r3, addr) \
    asm volatile("ldmatrix.sync.aligned.m8n8.x4.shared.b16 {%0,%1,%2,%3}, [%4];" \
        : "=r"(r0), "=r"(r1), "=r"(r2), "=r"(r3) : "r"(addr))

#define LDSM4T(r0, r1, r2, r3, addr) \
    asm volatile("ldmatrix.sync.aligned.m8n8.x4.trans.shared.b16 {%0,%1,%2,%3}, [%4];" \
        : "=r"(r0), "=r"(r1), "=r"(r2), "=r"(r3) : "r"(addr))

#define MMA16816(d, a, b0, b1) \
    asm("mma.sync.aligned.m16n8k16.row.col.f32.bf16.bf16.f32 " \
        "{%0,%1,%2,%3}, {%4,%5,%6,%7}, {%8,%9}, {%0,%1,%2,%3};" \
        : "+f"((d)[0]), "+f"((d)[1]), "+f"((d)[2]), "+f"((d)[3]) \
        : "r"((a)[0]), "r"((a)[1]), "r"((a)[2]), "r"((a)[3]), "r"(b0), "r"(b1))

#define CP_ASYNC16(dst, src, sz) \
    asm volatile("cp.async.cg.shared.global [%0], [%1], 16, %2;" \
        :: "r"(dst), "l"(src), "r"(sz))
#define CP_COMMIT()  asm volatile("cp.async.commit_group;" ::: "memory")
#define CP_WAIT0()   asm volatile("cp.async.wait_group 0;" ::: "memory")

__device__ __forceinline__ float fexp(float x) {
    x = fmaxf(x, -80.f);
    float t = x * 1.4426950408889634f;
    float z = t + 12582912.f;
    int   k = __float_as_int(z) - 0x4B400000;
    float f = t - (z - 12582912.f);
    float p = 1.3333558146428443e-3f;
    p = fmaf(p, f, 9.6181291076284772e-3f);
    p = fmaf(p, f, 5.5504108664821580e-2f);
    p = fmaf(p, f, 2.4022650695910071e-1f);
    p = fmaf(p, f, 6.9314718055994531e-1f);
    p = fmaf(p, f, 1.0f);
    return __int_as_float(__float_as_int(p) + (k << 23));
}

// ============================================================================
// split fp32 -> (bf16 hi, bf16 lo)
// ============================================================================
__device__ __forceinline__ void split_one(
    const float4* __restrict__ x, uint2* __restrict__ hi, uint2* __restrict__ lo, int i)
{
    float4 v = x[i];
    __nv_bfloat162 h01 = __floats2bfloat162_rn(v.x, v.y);
    __nv_bfloat162 h23 = __floats2bfloat162_rn(v.z, v.w);
    float lx = v.x - __bfloat162float(h01.x);
    float ly = v.y - __bfloat162float(h01.y);
    float lz = v.z - __bfloat162float(h23.x);
    float lw = v.w - __bfloat162float(h23.y);
    __nv_bfloat162 l01 = __floats2bfloat162_rn(lx, ly);
    __nv_bfloat162 l23 = __floats2bfloat162_rn(lz, lw);
    uint2 hv, lv;
    hv.x = *(uint32_t*)&h01; hv.y = *(uint32_t*)&h23;
    lv.x = *(uint32_t*)&l01; lv.y = *(uint32_t*)&l23;
    hi[i] = hv; lo[i] = lv;
}

__global__ __launch_bounds__(256) void split_bf16(
    const float4* __restrict__ x, uint2* __restrict__ hi, uint2* __restrict__ lo, int n4)
{
    int i = blockIdx.x * 256 + threadIdx.x;
    if (i < n4) split_one(x, hi, lo, i);
}

__global__ __launch_bounds__(256) void split_w4(
    const float4* __restrict__ w0, const float4* __restrict__ w1,
    const float4* __restrict__ w2, const float4* __restrict__ w3,
    uint2* __restrict__ hi, uint2* __restrict__ lo)
{
    const int n4 = D_ * D_ / 4;
    int i = blockIdx.x * 256 + threadIdx.x;
    if (i >= n4) return;
    int z = blockIdx.y;
    const float4* src = (z == 0) ? w0 : (z == 1) ? w1 : (z == 2) ? w2 : w3;
    split_one(src, hi + (size_t)z * n4, lo + (size_t)z * n4, i);
}

// ============================================================================
// HMMA GEMM via bf16x3 split — 128x256 block tile, 8 warps (64x64 each), occ 1
// smem stage: A-hi(10240) A-lo(10240) B-hi(20480) B-lo(20480) = 61440 B
// ============================================================================
#define APITCH 80
#define ATILEB (128 * APITCH)          // 10240
#define BTILEB (256 * APITCH)          // 20480
#define STAGEB (2 * ATILEB + 2 * BTILEB)  // 61440
#define GEMM_SMEM (2 * STAGEB)         // 122880

__device__ __forceinline__ void stage_load(
    uint32_t sb, int buf, int c, int tm, int tn, int tid, int mmax,
    const __nv_bfloat16* __restrict__ Xhi, const __nv_bfloat16* __restrict__ Xlo,
    const __nv_bfloat16* __restrict__ Whi, const __nv_bfloat16* __restrict__ Wlo)
{
    uint32_t st = sb + buf * STAGEB;
    #pragma unroll
    for (int j = 0; j < 12; ++j) {
        int g = tid + j * 256;
        if (g < 1024) {              // A tiles: 2 x 512 vecs
            int tile = g >> 9, i = g & 511, row = i >> 2, seg = i & 3;
            const __nv_bfloat16* base = tile ? Xlo : Xhi;
            const void* src = base + (size_t)(tm + row) * D_ + c * 32 + seg * 8;
            uint32_t dst = st + tile * ATILEB + row * APITCH + seg * 16;
            CP_ASYNC16(dst, src, (tm + row) < mmax ? 16 : 0);
        } else {                     // B tiles: 2 x 1024 vecs
            int gb = g - 1024;
            int tile = gb >> 10, i = gb & 1023, row = i >> 2, seg = i & 3;
            const __nv_bfloat16* base = tile ? Wlo : Whi;
            const void* src = base + (size_t)(tn + row) * D_ + c * 32 + seg * 8;
            uint32_t dst = st + 2 * ATILEB + tile * BTILEB + row * APITCH + seg * 16;
            CP_ASYNC16(dst, src, 16);
        }
    }
}

__device__ __forceinline__ void gemm_body(
    const __nv_bfloat16* __restrict__ Xhi, const __nv_bfloat16* __restrict__ Xlo,
    const __nv_bfloat16* __restrict__ Whi, const __nv_bfloat16* __restrict__ Wlo,
    const float* __restrict__ bias, float* __restrict__ Y, float scale,
    int m0g, int mmax)
{
    extern __shared__ char smem[];
    const uint32_t sb = smem_u32(smem);
    const int tid = threadIdx.x;
    const int wid = tid >> 5, lane = tid & 31;
    const int tm = m0g + (blockIdx.y << 7), tn = blockIdx.x << 8;
    const int wm = (wid & 1) * 64, wn = (wid >> 1) * 64;

    const int lrow = lane & 15;
    const int lk   = lane >> 4;
    const int brow = ((lane >> 4) << 3) + (lane & 7);
    const int bk   = (lane >> 3) & 1;

    float acc[4][8][4] = {};

    stage_load(sb, 0, 0, tm, tn, tid, mmax, Xhi, Xlo, Whi, Wlo);
    CP_COMMIT();

    for (int c = 0; c < 32; ++c) {
        const int buf = c & 1;
        CP_WAIT0();
        __syncthreads();
        if (c + 1 < 32) {
            stage_load(sb, buf ^ 1, c + 1, tm, tn, tid, mmax, Xhi, Xlo, Whi, Wlo);
            CP_COMMIT();
        }

        const uint32_t Ah = sb + buf * STAGEB;
        const uint32_t Al = Ah + ATILEB;
        const uint32_t Bh = Ah + 2 * ATILEB;
        const uint32_t Bl = Bh + BTILEB;

        #pragma unroll
        for (int kk2 = 0; kk2 < 2; ++kk2) {
            const int kkb = kk2 * 32;
            uint32_t fa[4][4], fb[4][4], fc[4][4];
            const uint32_t aoff = (uint32_t)(wm + lrow) * APITCH + kkb + lk * 16;
            const uint32_t boff = (uint32_t)(wn + brow) * APITCH + kkb + bk * 16;
            #pragma unroll
            for (int mt = 0; mt < 4; ++mt)
                LDSM4(fa[mt][0], fa[mt][1], fa[mt][2], fa[mt][3],
                      Ah + aoff + mt * (16 * APITCH));
            #pragma unroll
            for (int p = 0; p < 4; ++p)
                LDSM4(fb[p][0], fb[p][1], fb[p][2], fb[p][3],
                      Bh + boff + p * (16 * APITCH));
            // phase 1: hi * hi
            #pragma unroll
            for (int mt = 0; mt < 4; ++mt)
                #pragma unroll
                for (int nt = 0; nt < 8; ++nt) {
                    const int p = nt >> 1, h = (nt & 1) * 2;
                    MMA16816(acc[mt][nt], fa[mt], fb[p][h], fb[p][h + 1]);
                }
            // load B-lo, phase 2: hi * lo
            #pragma unroll
            for (int p = 0; p < 4; ++p)
                LDSM4(fc[p][0], fc[p][1], fc[p][2], fc[p][3],
                      Bl + boff + p * (16 * APITCH));
            #pragma unroll
            for (int mt = 0; mt < 4; ++mt)
                #pragma unroll
                for (int nt = 0; nt < 8; ++nt) {
                    const int p = nt >> 1, h = (nt & 1) * 2;
                    MMA16816(acc[mt][nt], fa[mt], fc[p][h], fc[p][h + 1]);
                }
            // reload A with lo, phase 3: lo * hi
            #pragma unroll
            for (int mt = 0; mt < 4; ++mt)
                LDSM4(fa[mt][0], fa[mt][1], fa[mt][2], fa[mt][3],
                      Al + aoff + mt * (16 * APITCH));
            #pragma unroll
            for (int mt = 0; mt < 4; ++mt)
                #pragma unroll
                for (int nt = 0; nt < 8; ++nt) {
                    const int p = nt >> 1, h = (nt & 1) * 2;
                    MMA16816(acc[mt][nt], fa[mt], fb[p][h], fb[p][h + 1]);
                }
        }
        __syncthreads();
    }

    const int erow = lane >> 2, ecol = (lane & 3) * 2;
    #pragma unroll
    for (int mt = 0; mt < 4; ++mt) {
        #pragma unroll
        for (int nt = 0; nt < 8; ++nt) {
            int m0 = tm + wm + mt * 16 + erow;
            int n0 = tn + wn + nt * 8 + ecol;
            float bx = bias[n0], by = bias[n0 + 1];
            if (m0 < mmax) {
                float2 o;
                o.x = (acc[mt][nt][0] + bx) * scale;
                o.y = (acc[mt][nt][1] + by) * scale;
                *(float2*)(Y + (size_t)m0 * D_ + n0) = o;
            }
            if (m0 + 8 < mmax) {
                float2 o;
                o.x = (acc[mt][nt][2] + bx) * scale;
                o.y = (acc[mt][nt][3] + by) * scale;
                *(float2*)(Y + (size_t)(m0 + 8) * D_ + n0) = o;
            }
        }
    }
}

__global__ __launch_bounds__(256, 1) void mma_gemm_qkv(
    const __nv_bfloat16* __restrict__ Xhi, const __nv_bfloat16* __restrict__ Xlo,
    const __nv_bfloat16* __restrict__ Whi, const __nv_bfloat16* __restrict__ Wlo,
    const float* __restrict__ bq, const float* __restrict__ bk,
    const float* __restrict__ bv, float* __restrict__ Y, int m0g, int mmax)
{
    const int z = blockIdx.z;
    const size_t wo = (size_t)z * D_ * D_;
    const float* bias = (z == 0) ? bq : (z == 1) ? bk : bv;
    gemm_body(Xhi, Xlo, Whi + wo, Wlo + wo, bias,
              Y + (size_t)z * MTOT * D_, (z == 0) ? SCALE_Q : 1.f, m0g, mmax);
}

__global__ __launch_bounds__(256, 1) void mma_gemm(
    const __nv_bfloat16* __restrict__ Xhi, const __nv_bfloat16* __restrict__ Xlo,
    const __nv_bfloat16* __restrict__ Whi, const __nv_bfloat16* __restrict__ Wlo,
    const float* __restrict__ bias, float* __restrict__ Y, float scale,
    int m0g, int mmax)
{
    gemm_body(Xhi, Xlo, Whi, Wlo, bias, Y, scale, m0g, mmax);
}

// ============================================================================
// Fused flash attention: 64-row Q tiles, 128 threads.
// ============================================================================
#define FPITCH 144
#define KVROWB (64 * FPITCH)
#define KVSTG  (4 * KVROWB)
#define FA_SMEM (2 * KVSTG)

__device__ __forceinline__ void load_kv(
    uint32_t st, int t0, size_t kvbase, int tid,
    const __nv_bfloat16* __restrict__ khi, const __nv_bfloat16* __restrict__ klo,
    const __nv_bfloat16* __restrict__ vhi, const __nv_bfloat16* __restrict__ vlo)
{
    #pragma unroll
    for (int j = 0; j < 16; ++j) {
        int g = tid + j * 128;
        int tens = g >> 9, i = g & 511, row = i >> 3, seg = i & 7;
        const __nv_bfloat16* bp = (tens == 0) ? khi : (tens == 1) ? klo
                                 : (tens == 2) ? vhi : vlo;
        const void* src = bp + kvbase + (size_t)(t0 + row) * D_ + seg * 8;
        uint32_t dst = st + tens * KVROWB + row * FPITCH + seg * 16;
        CP_ASYNC16(dst, src, (t0 + row) < S_ ? 16 : 0);
    }
}

__global__ __launch_bounds__(128) void flash_attn(
    const __nv_bfloat16* __restrict__ qhi, const __nv_bfloat16* __restrict__ qlo,
    const __nv_bfloat16* __restrict__ khi, const __nv_bfloat16* __restrict__ klo,
    const __nv_bfloat16* __restrict__ vhi, const __nv_bfloat16* __restrict__ vlo,
    float* __restrict__ Xo,
    __nv_bfloat16* __restrict__ Xhi, __nv_bfloat16* __restrict__ Xlo, int bh0)
{
    extern __shared__ char smem[];
    const uint32_t sb = smem_u32(smem);
    const int tid = threadIdx.x, wid = tid >> 5, lane = tid & 31;
    const int bh = bh0 + blockIdx.x, b = bh >> 4, h = bh & 15;
    const int m0 = blockIdx.y * 64;
    const size_t kvbase = (size_t)b * S_ * D_ + h * HD_;

    #pragma unroll
    for (int j = 0; j < 8; ++j) {
        int g = tid + j * 128;
        int half = g >> 9, i = g & 511, row = i >> 3, seg = i & 7;
        const __nv_bfloat16* src = (half ? qlo : qhi) + kvbase
                                 + (size_t)(m0 + row) * D_ + seg * 8;
        uint32_t dst = sb + half * KVSTG + row * FPITCH + seg * 16;
        CP_ASYNC16(dst, src, (m0 + row) < S_ ? 16 : 0);
    }
    CP_COMMIT(); CP_WAIT0();
    __syncthreads();

    uint32_t qh[4][4], ql[4][4];
    {
        const uint32_t base = sb + (uint32_t)(wid * 16 + (lane & 15)) * FPITCH
                            + (lane >> 4) * 16;
        #pragma unroll
        for (int kk = 0; kk < 4; ++kk) {
            LDSM4(qh[kk][0], qh[kk][1], qh[kk][2], qh[kk][3], base + kk * 32);
            LDSM4(ql[kk][0], ql[kk][1], ql[kk][2], ql[kk][3], base + KVSTG + kk * 32);
        }
    }
    __syncthreads();

    float acc_o[8][4] = {};
    float mrow[2] = {-1e30f, -1e30f}, lrow[2] = {0.f, 0.f};
    const int brow = ((lane >> 4) << 3) + (lane & 7);
    const int bk   = (lane >> 3) & 1;
    const int quad = lane & 3;

    load_kv(sb, 0, kvbase, tid, khi, klo, vhi, vlo);
    CP_COMMIT();

    #pragma unroll 1
    for (int kv = 0; kv < 5; ++kv) {
        CP_WAIT0();
        __syncthreads();
        const uint32_t Ks = sb + (kv & 1) * KVSTG;
        const uint32_t Vs = Ks + 2 * KVROWB;
        if (kv < 4) {
            load_kv(sb + ((kv + 1) & 1) * KVSTG, (kv + 1) * 64, kvbase, tid,
                    khi, klo, vhi, vlo);
            CP_COMMIT();
        }

        float s[8][4] = {};
        #pragma unroll
        for (int kk = 0; kk < 4; ++kk) {
            uint32_t kh[4][4], kl[4][4];
            #pragma unroll
            for (int p = 0; p < 4; ++p) {
                uint32_t ko = Ks + (uint32_t)(p * 16 + brow) * FPITCH + kk * 32 + bk * 16;
                LDSM4(kh[p][0], kh[p][1], kh[p][2], kh[p][3], ko);
                LDSM4(kl[p][0], kl[p][1], kl[p][2], kl[p][3], ko + KVROWB);
            }
            #pragma unroll
            for (int p = 0; p < 4; ++p) {
                MMA16816(s[2*p],   qh[kk], kh[p][0], kh[p][1]);
                MMA16816(s[2*p+1], qh[kk], kh[p][2], kh[p][3]);
                MMA16816(s[2*p],   qh[kk], kl[p][0], kl[p][1]);
                MMA16816(s[2*p+1], qh[kk], kl[p][2], kl[p][3]);
                MMA16816(s[2*p],   ql[kk], kh[p][0], kh[p][1]);
                MMA16816(s[2*p+1], ql[kk], kh[p][2], kh[p][3]);
            }
        }

        if (kv == 4) {
            #pragma unroll
            for (int nt = 0; nt < 8; ++nt)
                #pragma unroll
                for (int rg = 0; rg < 4; ++rg) {
                    int col = 256 + nt * 8 + quad * 2 + (rg & 1);
                    if (col >= S_) s[nt][rg] = -1e30f;
                }
        }

        #pragma unroll
        for (int rr = 0; rr < 2; ++rr) {
            float mx = -1e30f;
            #pragma unroll
            for (int nt = 0; nt < 8; ++nt)
                mx = fmaxf(mx, fmaxf(s[nt][2*rr], s[nt][2*rr+1]));
            mx = fmaxf(mx, __shfl_xor_sync(0xffffffffu, mx, 1));
            mx = fmaxf(mx, __shfl_xor_sync(0xffffffffu, mx, 2));
            float mnew = fmaxf(mrow[rr], mx);
            float alpha = fexp(mrow[rr] - mnew);
            mrow[rr] = mnew;
            float sum = 0.f;
            #pragma unroll
            for (int nt = 0; nt < 8; ++nt) {
                float p0 = fexp(s[nt][2*rr]   - mnew);
                float p1 = fexp(s[nt][2*rr+1] - mnew);
                s[nt][2*rr] = p0; s[nt][2*rr+1] = p1;
                sum += p0 + p1;
            }
            sum += __shfl_xor_sync(0xffffffffu, sum, 1);
            sum += __shfl_xor_sync(0xffffffffu, sum, 2);
            lrow[rr] = lrow[rr] * alpha + sum;
            #pragma unroll
            for (int nt = 0; nt < 8; ++nt) {
                acc_o[nt][2*rr]   *= alpha;
                acc_o[nt][2*rr+1] *= alpha;
            }
        }

        #pragma unroll
        for (int kk = 0; kk < 4; ++kk) {
            uint32_t ph[4], pl[4];
            #pragma unroll
            for (int rg = 0; rg < 4; ++rg) {
                int nt = 2 * kk + (rg >> 1);
                float p0 = s[nt][(rg & 1) * 2];
                float p1 = s[nt][(rg & 1) * 2 + 1];
                __nv_bfloat162 hb = __floats2bfloat162_rn(p0, p1);
                float l0 = p0 - __bfloat162float(hb.x);
                float l1 = p1 - __bfloat162float(hb.y);
                __nv_bfloat162 lb = __floats2bfloat162_rn(l0, l1);
                ph[rg] = *(uint32_t*)&hb;
                pl[rg] = *(uint32_t*)&lb;
            }
            uint32_t vh[4][4], vl[4][4];
            #pragma unroll
            for (int p = 0; p < 4; ++p) {
                uint32_t vo = Vs + (uint32_t)(kk * 16 + (lane & 15)) * FPITCH
                            + p * 32 + (lane >> 4) * 16;
                LDSM4T(vh[p][0], vh[p][1], vh[p][2], vh[p][3], vo);
                LDSM4T(vl[p][0], vl[p][1], vl[p][2], vl[p][3], vo + KVROWB);
            }
            #pragma unroll
            for (int p = 0; p < 4; ++p) {
                MMA16816(acc_o[2*p],   ph, vh[p][0], vh[p][1]);
                MMA16816(acc_o[2*p+1], ph, vh[p][2], vh[p][3]);
                MMA16816(acc_o[2*p],   ph, vl[p][0], vl[p][1]);
                MMA16816(acc_o[2*p+1], ph, vl[p][2], vl[p][3]);
                MMA16816(acc_o[2*p],   pl, vh[p][0], vh[p][1]);
                MMA16816(acc_o[2*p+1], pl, vh[p][2], vh[p][3]);
            }
        }
    }

    {
        const int r = lane >> 2, q2 = quad * 2;
        #pragma unroll
        for (int rr = 0; rr < 2; ++rr) {
            int m = m0 + wid * 16 + r + rr * 8;
            if (m < S_) {
                float inv = 1.f / lrow[rr];
                size_t off = ((size_t)b * S_ + m) * D_ + h * HD_ + q2;
                #pragma unroll
                for (int nt = 0; nt < 8; ++nt) {
                    float ox = acc_o[nt][2*rr]   * inv;
                    float oy = acc_o[nt][2*rr+1] * inv;
                    float2 o = make_float2(ox, oy);
                    *(float2*)(Xo + off + nt * 8) = o;
                    __nv_bfloat162 hb = __floats2bfloat162_rn(ox, oy);
                    __nv_bfloat162 lb = __floats2bfloat162_rn(
                        ox - __bfloat162float(hb.x), oy - __bfloat162float(hb.y));
                    *(__nv_bfloat162*)(Xhi + off + nt * 8) = hb;
                    *(__nv_bfloat162*)(Xlo + off + nt * 8) = lb;
                }
            }
        }
    }
}

// ============================================================================
// attn_tail: query row s = 256; also writes xhi/xlo
// ============================================================================
#define TAIL_SMEM ((257 * 65 + 64 + 257 + 256 + 4 * 64) * 4)
__global__ __launch_bounds__(256) void attn_tail(
    const __nv_bfloat16* __restrict__ qhi, const __nv_bfloat16* __restrict__ qlo,
    const __nv_bfloat16* __restrict__ khi, const __nv_bfloat16* __restrict__ klo,
    const __nv_bfloat16* __restrict__ vhi, const __nv_bfloat16* __restrict__ vlo,
    float* __restrict__ Xo,
    __nv_bfloat16* __restrict__ Xhi, __nv_bfloat16* __restrict__ Xlo, int bh0)
{
    extern __shared__ float fs[];
    float* ks  = fs;
    float* q   = ks + 257 * 65;
    float* p   = q + 64;
    float* red = p + 257;
    float* vp  = red + 256;
    const int t = threadIdx.x;
    const int bh = bh0 + blockIdx.x, b = bh >> 4, h = bh & 15;
    const size_t base = (size_t)b * S_ * D_ + h * HD_;

    if (t < 64) {
        size_t o = base + (size_t)256 * D_ + t;
        q[t] = __bfloat162float(qhi[o]) + __bfloat162float(qlo[o]);
    }
    for (int i = t; i < 257 * 64; i += 256) {
        int row = i >> 6, d = i & 63;
        size_t o = base + (size_t)row * D_ + d;
        ks[row * 65 + d] = __bfloat162float(khi[o]) + __bfloat162float(klo[o]);
    }
    __syncthreads();

    float v0 = 0.f, v1 = -1e30f;
    {
        const float* kr = ks + t * 65;
        #pragma unroll 8
        for (int d = 0; d < 64; ++d) v0 = fmaf(q[d], kr[d], v0);
    }
    if (t == 0) {
        v1 = 0.f;
        const float* kr = ks + 256 * 65;
        #pragma unroll 8
        for (int d = 0; d < 64; ++d) v1 = fmaf(q[d], kr[d], v1);
    }

    red[t] = fmaxf(v0, v1);
    __syncthreads();
    #pragma unroll
    for (int o = 128; o; o >>= 1) {
        if (t < o) red[t] = fmaxf(red[t], red[t + o]);
        __syncthreads();
    }
    float rmax = red[0];
    __syncthreads();
    float e0 = fexp(v0 - rmax);
    float e1 = (t == 0) ? fexp(v1 - rmax) : 0.f;
    red[t] = e0 + e1;
    __syncthreads();
    #pragma unroll
    for (int o = 128; o; o >>= 1) {
        if (t < o) red[t] += red[t + o];
        __syncthreads();
    }
    float inv = 1.f / red[0];
    p[t] = e0 * inv;
    if (t == 0) p[256] = e1 * inv;
    __syncthreads();

    {
        int d = t & 63, grp = t >> 6;
        float acc = 0.f;
        for (int tt = grp; tt < S_; tt += 4) {
            size_t off = base + (size_t)tt * D_ + d;
            acc = fmaf(p[tt], __bfloat162float(vhi[off]) + __bfloat162float(vlo[off]), acc);
        }
        vp[grp * 64 + d] = acc;
    }
    __syncthreads();
    if (t < 64) {
        float o = vp[t] + vp[64 + t] + vp[128 + t] + vp[192 + t];
        size_t off = ((size_t)b * S_ + 256) * D_ + h * HD_ + t;
        Xo[off] = o;
        __nv_bfloat16 hb = __float2bfloat16(o);
        Xhi[off] = hb;
        Xlo[off] = __float2bfloat16(o - __bfloat162float(hb));
    }
}

// ============================================================================
// xa: grid (BH, KE, 16*nproj); batch offset b0
// ============================================================================
__global__ __launch_bounds__(256) void xa_kernel(
    const float* __restrict__ X,
    const float* __restrict__ A0, const float* __restrict__ A1,
    const float* __restrict__ A2,
    const int* __restrict__ idx, float* __restrict__ xa, int b0)
{
    int b = b0 + blockIdx.x, slot = blockIdx.y;
    int proj = blockIdx.z >> 4, zz = blockIdx.z & 15;
    int rh = zz >> 3, sc = zz & 7;
    const float* A = (proj == 0) ? A0 : (proj == 1) ? A1 : A2;
    float* xad = xa + (size_t)proj * B_ * KE_ * S_ * R_;
    int sbase = sc * 33;
    int smax = min(S_, sbase + 33);
    int e = idx[b * KE_ + slot];
    __shared__ float As[8][D_];
    const float* Ap = A + ((size_t)e * R_ + rh * 8) * D_;
    for (int i = threadIdx.x; i < 8 * D_ / 4; i += 256)
        ((float4*)As)[i] = ((const float4*)Ap)[i];
    __syncthreads();

    int w = threadIdx.x >> 5, lane = threadIdx.x & 31;
    for (int s4 = sbase + w * 4; s4 < smax; s4 += 32) {
        float sum[8][4];
        #pragma unroll
        for (int r = 0; r < 8; r++)
            #pragma unroll
            for (int si = 0; si < 4; si++) sum[r][si] = 0.f;

        #pragma unroll 1
        for (int c = 0; c < 8; c++) {
            float4 xv[4];
            #pragma unroll
            for (int si = 0; si < 4; si++) {
                int s = s4 + si;
                xv[si] = (s < S_)
                    ? *(const float4*)(X + ((size_t)b * S_ + s) * D_ + c * 128 + lane * 4)
                    : make_float4(0.f, 0.f, 0.f, 0.f);
            }
            #pragma unroll
            for (int r = 0; r < 8; r++) {
                float4 av = *(const float4*)&As[r][c * 128 + lane * 4];
                #pragma unroll
                for (int si = 0; si < 4; si++)
                    sum[r][si] = fmaf(xv[si].x, av.x,
                                 fmaf(xv[si].y, av.y,
                                 fmaf(xv[si].z, av.z,
                                 fmaf(xv[si].w, av.w, sum[r][si]))));
            }
        }
        #pragma unroll
        for (int r = 0; r < 8; r++)
            #pragma unroll
            for (int si = 0; si < 4; si++) {
                float v = sum[r][si];
                #pragma unroll
                for (int o = 16; o; o >>= 1) v += __shfl_xor_sync(0xffffffffu, v, o);
                int s = s4 + si;
                if (lane == 0 && s < S_)
                    xad[(((size_t)b * KE_ + slot) * S_ + s) * R_ + rh * 8 + r] = v;
            }
    }
}

// ============================================================================
// lora_add / lora_split3
// ============================================================================
__global__ __launch_bounds__(256) void lora_add(
    const float* __restrict__ Bm, const int* __restrict__ idx,
    const float* __restrict__ gates, const float* __restrict__ xa,
    float* __restrict__ Y, float scale, int b0)
{
    int b = b0 + blockIdx.x;
    int cn = blockIdx.y << 6;
    int t = threadIdx.x;
    __shared__ float Bs[2][64][17];
    __shared__ float xs[2][64][17];
    int e0 = idx[b * KE_], e1 = idx[b * KE_ + 1];
    float g0 = gates[b * KE_] * scale, g1 = gates[b * KE_ + 1] * scale;

    for (int i = t; i < 2048; i += 256) {
        int slot = i >> 10, rem = i & 1023, c = rem >> 4, r = rem & 15;
        Bs[slot][c][r] = Bm[((size_t)(slot ? e1 : e0) * D_ + cn + c) * R_ + r];
    }

    int c = t & 63, sq = t >> 6;
    for (int s0 = 0; s0 < S_; s0 += 64) {
        __syncthreads();
        for (int i = t; i < 2048; i += 256) {
            int slot = i >> 10, rem = i & 1023, si = rem >> 4, r = rem & 15;
            int s = s0 + si;
            float v = (s < S_) ? xa[(((size_t)b * KE_ + slot) * S_ + s) * R_ + r] : 0.f;
            xs[slot][si][r] = v * (slot ? g1 : g0);
        }
        __syncthreads();
        for (int si = sq; si < 64; si += 4) {
            int s = s0 + si;
            if (s >= S_) break;
            float sum = 0.f;
            #pragma unroll
            for (int r = 0; r < 16; r++) {
                sum = fmaf(xs[0][si][r], Bs[0][c][r], sum);
                sum = fmaf(xs[1][si][r], Bs[1][c][r], sum);
            }
            Y[((size_t)b * S_ + s) * D_ + cn + c] += sum;
        }
    }
}

__global__ __launch_bounds__(256) void lora_split3(
    const float* __restrict__ Bq, const float* __restrict__ Bk,
    const float* __restrict__ Bv,
    const int* __restrict__ idx, const float* __restrict__ gates,
    const float* __restrict__ xa, const float* __restrict__ Yin,
    __nv_bfloat16* __restrict__ qhi, __nv_bfloat16* __restrict__ qlo,
    __nv_bfloat16* __restrict__ khi, __nv_bfloat16* __restrict__ klo,
    __nv_bfloat16* __restrict__ vhi, __nv_bfloat16* __restrict__ vlo, int b0)
{
    const int z = blockIdx.z;
    const float* Bm = (z == 0) ? Bq : (z == 1) ? Bk : Bv;
    const float* Yz = Yin + (size_t)z * MTOT * D_;
    const float* xaz = xa + (size_t)z * B_ * KE_ * S_ * R_;
    __nv_bfloat16* Yhi = (z == 0) ? qhi : (z == 1) ? khi : vhi;
    __nv_bfloat16* Ylo = (z == 0) ? qlo : (z == 1) ? klo : vlo;
    const float scale = (z == 0) ? SCALE_Q : 1.f;

    int b = b0 + blockIdx.x;
    int cn = blockIdx.y << 6;
    int t = threadIdx.x;
    __shared__ float Bs[2][64][17];
    __shared__ float xs[2][64][17];
    int e0 = idx[b * KE_], e1 = idx[b * KE_ + 1];
    float g0 = gates[b * KE_] * scale, g1 = gates[b * KE_ + 1] * scale;

    for (int i = t; i < 2048; i += 256) {
        int slot = i >> 10, rem = i & 1023, c = rem >> 4, r = rem & 15;
        Bs[slot][c][r] = Bm[((size_t)(slot ? e1 : e0) * D_ + cn + c) * R_ + r];
    }

    int c = t & 63, sq = t >> 6;
    for (int s0 = 0; s0 < S_; s0 += 64) {
        __syncthreads();
        for (int i = t; i < 2048; i += 256) {
            int slot = i >> 10, rem = i & 1023, si = rem >> 4, r = rem & 15;
            int s = s0 + si;
            float v = (s < S_) ? xaz[(((size_t)b * KE_ + slot) * S_ + s) * R_ + r] : 0.f;
            xs[slot][si][r] = v * (slot ? g1 : g0);
        }
        __syncthreads();
        for (int si = sq; si < 64; si += 4) {
            int s = s0 + si;
            if (s >= S_) break;
            float sum = 0.f;
            #pragma unroll
            for (int r = 0; r < 16; r++) {
                sum = fmaf(xs[0][si][r], Bs[0][c][r], sum);
                sum = fmaf(xs[1][si][r], Bs[1][c][r], sum);
            }
            size_t off = ((size_t)b * S_ + s) * D_ + cn + c;
            float v = Yz[off] + sum;
            __nv_bfloat16 hb = __float2bfloat16(v);
            Yhi[off] = hb;
            Ylo[off] = __float2bfloat16(v - __bfloat162float(hb));
        }
    }
}

// ---------------- host launcher --------------------------------------------
extern "C" void kernel_launch(void* const* d_in, const int* in_sizes, int n_in,
                              void* d_out, int out_size)
{
    const float* hs    = (const float*)d_in[0];
    const int*   idx   = (const int*)  d_in[1];
    const float* gates = (const float*)d_in[2];
    const float* wq = (const float*)d_in[3];  const float* Aq = (const float*)d_in[4];
    const float* Bq = (const float*)d_in[5];  const float* bq = (const float*)d_in[6];
    const float* wk = (const float*)d_in[7];  const float* Ak = (const float*)d_in[8];
    const float* Bk = (const float*)d_in[9];  const float* bk = (const float*)d_in[10];
    const float* wv = (const float*)d_in[11]; const float* Av = (const float*)d_in[12];
    const float* Bv = (const float*)d_in[13]; const float* bv = (const float*)d_in[14];
    const float* wo = (const float*)d_in[15]; const float* Ao = (const float*)d_in[16];
    const float* Bo = (const float*)d_in[17]; const float* bo = (const float*)d_in[18];
    float* out = (float*)d_out;

    float *tmp, *x2, *xa;
    __nv_bfloat16 *xhi, *xlo, *whi, *wlo, *qhi, *qlo, *khi, *klo, *vhi, *vlo;
    cudaGetSymbolAddress((void**)&tmp, g_tmp);
    cudaGetSymbolAddress((void**)&x2,  g_x2);
    cudaGetSymbolAddress((void**)&xa,  g_xa);
    cudaGetSymbolAddress((void**)&xhi, g_xhi);
    cudaGetSymbolAddress((void**)&xlo, g_xlo);
    cudaGetSymbolAddress((void**)&whi, g_whi);
    cudaGetSymbolAddress((void**)&wlo, g_wlo);
    cudaGetSymbolAddress((void**)&qhi, g_qhi);
    cudaGetSymbolAddress((void**)&qlo, g_qlo);
    cudaGetSymbolAddress((void**)&khi, g_khi);
    cudaGetSymbolAddress((void**)&klo, g_klo);
    cudaGetSymbolAddress((void**)&vhi, g_vhi);
    cudaGetSymbolAddress((void**)&vlo, g_vlo);

    cudaFuncSetAttribute(mma_gemm_qkv, cudaFuncAttributeMaxDynamicSharedMemorySize, GEMM_SMEM);
    cudaFuncSetAttribute(mma_gemm, cudaFuncAttributeMaxDynamicSharedMemorySize, GEMM_SMEM);
    cudaFuncSetAttribute(flash_attn, cudaFuncAttributeMaxDynamicSharedMemorySize, FA_SMEM);
    cudaFuncSetAttribute(attn_tail, cudaFuncAttributeMaxDynamicSharedMemorySize, TAIL_SMEM);

    static cudaStream_t s1 = nullptr, s2 = nullptr, s3 = nullptr;
    static cudaEvent_t evR, evW, evXA[2], evL[2], evT[2], evF[2], evXO[2], evEnd;
    if (!s1) {
        cudaStreamCreateWithFlags(&s1, cudaStreamNonBlocking);
        cudaStreamCreateWithFlags(&s2, cudaStreamNonBlocking);
        cudaStreamCreateWithFlags(&s3, cudaStreamNonBlocking);
        cudaEventCreateWithFlags(&evR, cudaEventDisableTiming);
        cudaEventCreateWithFlags(&evW, cudaEventDisableTiming);
        for (int i = 0; i < 2; ++i) {
            cudaEventCreateWithFlags(&evXA[i], cudaEventDisableTiming);
            cudaEventCreateWithFlags(&evL[i], cudaEventDisableTiming);
            cudaEventCreateWithFlags(&evT[i], cudaEventDisableTiming);
            cudaEventCreateWithFlags(&evF[i], cudaEventDisableTiming);
            cudaEventCreateWithFlags(&evXO[i], cudaEventDisableTiming);
        }
        cudaEventCreateWithFlags(&evEnd, cudaEventDisableTiming);
    }

    const int nw4 = D_ * D_ / 4;
    const int nh4 = MH_ * D_ / 4;
    cudaStream_t ws[2] = {s2, s3};

    // ---- initial forks: W split (s2), xa(qkv) per half on its worker ----
    cudaEventRecord(evR, 0);
    cudaStreamWaitEvent(s1, evR, 0);
    cudaStreamWaitEvent(s2, evR, 0);
    cudaStreamWaitEvent(s3, evR, 0);
    split_w4<<<dim3((nw4 + 255) / 256, 4), 256, 0, s2>>>(
        (const float4*)wq, (const float4*)wk, (const float4*)wv, (const float4*)wo,
        (uint2*)whi, (uint2*)wlo);
    cudaEventRecord(evW, s2);
    xa_kernel<<<dim3(BH_, KE_, 48), 256, 0, s2>>>(hs, Aq, Ak, Av, idx, xa, 0);
    cudaEventRecord(evXA[0], s2);
    xa_kernel<<<dim3(BH_, KE_, 48), 256, 0, s3>>>(hs, Aq, Ak, Av, idx, xa, BH_);
    cudaEventRecord(evXA[1], s3);

    // ---- per-half pipelines on stream 0 (half 0) and s1 (half 1) ----
    for (int h = 0; h < 2; ++h) {
        cudaStream_t st = h ? s1 : 0;
        cudaStream_t wk2 = ws[h];
        const int b0 = h * BH_;
        const int m0 = h * MH_;
        const int mmax = m0 + MH_;
        const int bh0 = b0 * H_;

        split_bf16<<<(nh4 + 255) / 256, 256, 0, st>>>(
            (const float4*)(hs + (size_t)m0 * D_),
            (uint2*)(xhi + (size_t)m0 * D_), (uint2*)(xlo + (size_t)m0 * D_), nh4);

        cudaStreamWaitEvent(st, evW, 0);
        mma_gemm_qkv<<<dim3(4, 33, 3), 256, GEMM_SMEM, st>>>(
            xhi, xlo, whi, wlo, bq, bk, bv, tmp, m0, mmax);

        cudaStreamWaitEvent(st, evXA[h], 0);
        lora_split3<<<dim3(BH_, 16, 3), 256, 0, st>>>(
            Bq, Bk, Bv, idx, gates, xa, tmp, qhi, qlo, khi, klo, vhi, vlo, b0);

        // fork: tail on worker concurrent with flash
        cudaEventRecord(evL[h], st);
        cudaStreamWaitEvent(wk2, evL[h], 0);
        attn_tail<<<BH_ * H_, 256, TAIL_SMEM, wk2>>>(
            qhi, qlo, khi, klo, vhi, vlo, x2, xhi, xlo, bh0);
        cudaEventRecord(evT[h], wk2);

        flash_attn<<<dim3(BH_ * H_, 4), 128, FA_SMEM, st>>>(
            qhi, qlo, khi, klo, vhi, vlo, x2, xhi, xlo, bh0);
        cudaStreamWaitEvent(st, evT[h], 0);

        // fork: xa(O) on worker concurrent with O GEMM
        cudaEventRecord(evF[h], st);
        cudaStreamWaitEvent(wk2, evF[h], 0);
        xa_kernel<<<dim3(BH_, KE_, 16), 256, 0, wk2>>>(x2, Ao, Ao, Ao, idx, xa, b0);
        cudaEventRecord(evXO[h], wk2);

        mma_gemm<<<dim3(4, 33), 256, GEMM_SMEM, st>>>(
            xhi, xlo, whi + (size_t)3 * D_ * D_, wlo + (size_t)3 * D_ * D_,
            bo, out, 1.f, m0, mmax);

        cudaStreamWaitEvent(st, evXO[h], 0);
        lora_add<<<dim3(BH_, 16), 256, 0, st>>>(Bo, idx, gates, xa, out, 1.f, b0);
    }

    cudaEventRecord(evEnd, s1);
    cudaStreamWaitEvent(0, evEnd, 0);
}

// round 14
// speedup vs baseline: 1.0531x; 1.0531x over previous
#include <cuda_runtime.h>
#include <cuda_bf16.h>
#include <cstdint>

#define B_ 32
#define S_ 257
#define D_ 1024
#define H_ 16
#define HD_ 64
#define E_ 8
#define R_ 16
#define KE_ 2
#define MTOT (B_*S_)
#define BH_ 16
#define MH_ (BH_*S_)
#define SCALE_Q 0.125f

// ---------------- scratch (device globals: allocation-free) ----------------
__device__ float g_tmp[(size_t)3 * MTOT * D_];
__device__ float g_x2 [(size_t)MTOT * D_];
__device__ float g_xa [(size_t)3 * B_ * KE_ * S_ * R_];
__device__ __nv_bfloat16 g_xhi[(size_t)MTOT * D_];
__device__ __nv_bfloat16 g_xlo[(size_t)MTOT * D_];
__device__ __nv_bfloat16 g_whi[(size_t)4 * D_ * D_];
__device__ __nv_bfloat16 g_wlo[(size_t)4 * D_ * D_];
__device__ __nv_bfloat16 g_qhi[(size_t)MTOT * D_];
__device__ __nv_bfloat16 g_qlo[(size_t)MTOT * D_];
__device__ __nv_bfloat16 g_khi[(size_t)MTOT * D_];
__device__ __nv_bfloat16 g_klo[(size_t)MTOT * D_];
__device__ __nv_bfloat16 g_vhi[(size_t)MTOT * D_];
__device__ __nv_bfloat16 g_vlo[(size_t)MTOT * D_];

// ========================= helpers ==========================================
__device__ __forceinline__ uint32_t smem_u32(const void* p) {
    uint32_t a;
    asm("{ .reg .u64 t; cvta.to.shared.u64 t, %1; cvt.u32.u64 %0, t; }"
        : "=r"(a) : "l"(p));
    return a;
}

#define LDSM4(r0, r1, r2, r3, addr) \
    asm volatile("ldmatrix.sync.aligned.m8n8.x4.shared.b16 {%0,%1,%2,%3}, [%4];" \
        : "=r"(r0), "=r"(r1), "=r"(r2), "=r"(r3) : "r"(addr))

#define LDSM4T(r0, r1, r2, r3, addr) \
    asm volatile("ldmatrix.sync.aligned.m8n8.x4.trans.shared.b16 {%0,%1,%2,%3}, [%4];" \
        : "=r"(r0), "=r"(r1), "=r"(r2), "=r"(r3) : "r"(addr))

#define MMA16816(d, a, b0, b1) \
    asm("mma.sync.aligned.m16n8k16.row.col.f32.bf16.bf16.f32 " \
        "{%0,%1,%2,%3}, {%4,%5,%6,%7}, {%8,%9}, {%0,%1,%2,%3};" \
        : "+f"((d)[0]), "+f"((d)[1]), "+f"((d)[2]), "+f"((d)[3]) \
        : "r"((a)[0]), "r"((a)[1]), "r"((a)[2]), "r"((a)[3]), "r"(b0), "r"(b1))

#define CP_ASYNC16(dst, src, sz) \
    asm volatile("cp.async.cg.shared.global [%0], [%1], 16, %2;" \
        :: "r"(dst), "l"(src), "r"(sz))
#define CP_COMMIT()  asm volatile("cp.async.commit_group;" ::: "memory")
#define CP_WAIT0()   asm volatile("cp.async.wait_group 0;" ::: "memory")

__device__ __forceinline__ float fexp(float x) {
    x = fmaxf(x, -80.f);
    float t = x * 1.4426950408889634f;
    float z = t + 12582912.f;
    int   k = __float_as_int(z) - 0x4B400000;
    float f = t - (z - 12582912.f);
    float p = 1.3333558146428443e-3f;
    p = fmaf(p, f, 9.6181291076284772e-3f);
    p = fmaf(p, f, 5.5504108664821580e-2f);
    p = fmaf(p, f, 2.4022650695910071e-1f);
    p = fmaf(p, f, 6.9314718055994531e-1f);
    p = fmaf(p, f, 1.0f);
    return __int_as_float(__float_as_int(p) + (k << 23));
}

// ============================================================================
// split fp32 -> (bf16 hi, bf16 lo)
// ============================================================================
__device__ __forceinline__ void split_one(
    const float4* __restrict__ x, uint2* __restrict__ hi, uint2* __restrict__ lo, int i)
{
    float4 v = x[i];
    __nv_bfloat162 h01 = __floats2bfloat162_rn(v.x, v.y);
    __nv_bfloat162 h23 = __floats2bfloat162_rn(v.z, v.w);
    float lx = v.x - __bfloat162float(h01.x);
    float ly = v.y - __bfloat162float(h01.y);
    float lz = v.z - __bfloat162float(h23.x);
    float lw = v.w - __bfloat162float(h23.y);
    __nv_bfloat162 l01 = __floats2bfloat162_rn(lx, ly);
    __nv_bfloat162 l23 = __floats2bfloat162_rn(lz, lw);
    uint2 hv, lv;
    hv.x = *(uint32_t*)&h01; hv.y = *(uint32_t*)&h23;
    lv.x = *(uint32_t*)&l01; lv.y = *(uint32_t*)&l23;
    hi[i] = hv; lo[i] = lv;
}

__global__ __launch_bounds__(256) void split_bf16(
    const float4* __restrict__ x, uint2* __restrict__ hi, uint2* __restrict__ lo, int n4)
{
    int i = blockIdx.x * 256 + threadIdx.x;
    if (i < n4) split_one(x, hi, lo, i);
}

__global__ __launch_bounds__(256) void split_w4(
    const float4* __restrict__ w0, const float4* __restrict__ w1,
    const float4* __restrict__ w2, const float4* __restrict__ w3,
    uint2* __restrict__ hi, uint2* __restrict__ lo)
{
    const int n4 = D_ * D_ / 4;
    int i = blockIdx.x * 256 + threadIdx.x;
    if (i >= n4) return;
    int z = blockIdx.y;
    const float4* src = (z == 0) ? w0 : (z == 1) ? w1 : (z == 2) ? w2 : w3;
    split_one(src, hi + (size_t)z * n4, lo + (size_t)z * n4, i);
}

// ============================================================================
// HMMA GEMM via bf16x3 split — 128x128 block tile, 4 warps (64x64 each), occ 2
// ============================================================================
#define APITCH 80
#define TILEB (128 * APITCH)
#define STAGEB (4 * TILEB)            // 40960
#define GEMM_SMEM (2 * STAGEB)        // 81920

__device__ __forceinline__ void stage_load(
    uint32_t sb, int buf, int c, int tm, int tn, int tid, int mmax,
    const __nv_bfloat16* __restrict__ Xhi, const __nv_bfloat16* __restrict__ Xlo,
    const __nv_bfloat16* __restrict__ Whi, const __nv_bfloat16* __restrict__ Wlo)
{
    uint32_t st = sb + buf * STAGEB;
    #pragma unroll
    for (int j = 0; j < 16; ++j) {
        int g = tid + j * 128;
        int tile = g >> 9, i = g & 511, row = i >> 2, seg = i & 3;
        const __nv_bfloat16* base = (tile == 0) ? Xhi : (tile == 1) ? Xlo
                                   : (tile == 2) ? Whi : Wlo;
        int grow = ((tile < 2) ? tm : tn) + row;
        const void* src = base + (size_t)grow * D_ + c * 32 + seg * 8;
        uint32_t dst = st + tile * TILEB + row * APITCH + seg * 16;
        int sz = (tile >= 2 || grow < mmax) ? 16 : 0;
        CP_ASYNC16(dst, src, sz);
    }
}

__device__ __forceinline__ void gemm_body(
    const __nv_bfloat16* __restrict__ Xhi, const __nv_bfloat16* __restrict__ Xlo,
    const __nv_bfloat16* __restrict__ Whi, const __nv_bfloat16* __restrict__ Wlo,
    const float* __restrict__ bias, float* __restrict__ Y, float scale,
    int m0g, int mmax)
{
    extern __shared__ char smem[];
    const uint32_t sb = smem_u32(smem);
    const int tid = threadIdx.x;
    const int wid = tid >> 5, lane = tid & 31;
    const int tm = m0g + (blockIdx.y << 7), tn = blockIdx.x << 7;
    const int wm = (wid & 1) * 64, wn = (wid >> 1) * 64;

    const int lrow = lane & 15;
    const int lk   = lane >> 4;
    const int brow = ((lane >> 4) << 3) + (lane & 7);
    const int bk   = (lane >> 3) & 1;

    float acc[4][8][4] = {};

    stage_load(sb, 0, 0, tm, tn, tid, mmax, Xhi, Xlo, Whi, Wlo);
    CP_COMMIT();

    for (int c = 0; c < 32; ++c) {
        const int buf = c & 1;
        CP_WAIT0();
        __syncthreads();
        if (c + 1 < 32) {
            stage_load(sb, buf ^ 1, c + 1, tm, tn, tid, mmax, Xhi, Xlo, Whi, Wlo);
            CP_COMMIT();
        }

        const uint32_t Ah = sb + buf * STAGEB;
        const uint32_t Al = Ah + TILEB;
        const uint32_t Bh = Ah + 2 * TILEB;
        const uint32_t Bl = Ah + 3 * TILEB;

        #pragma unroll
        for (int kk2 = 0; kk2 < 2; ++kk2) {
            const int kkb = kk2 * 32;
            uint32_t fa[4][4], fb[4][4], fc[4][4];
            const uint32_t aoff = (uint32_t)(wm + lrow) * APITCH + kkb + lk * 16;
            const uint32_t boff = (uint32_t)(wn + brow) * APITCH + kkb + bk * 16;
            #pragma unroll
            for (int mt = 0; mt < 4; ++mt)
                LDSM4(fa[mt][0], fa[mt][1], fa[mt][2], fa[mt][3],
                      Ah + aoff + mt * (16 * APITCH));
            #pragma unroll
            for (int p = 0; p < 4; ++p)
                LDSM4(fb[p][0], fb[p][1], fb[p][2], fb[p][3],
                      Bh + boff + p * (16 * APITCH));
            // phase 1: hi*hi
            #pragma unroll
            for (int mt = 0; mt < 4; ++mt)
                #pragma unroll
                for (int nt = 0; nt < 8; ++nt) {
                    const int p = nt >> 1, h = (nt & 1) * 2;
                    MMA16816(acc[mt][nt], fa[mt], fb[p][h], fb[p][h + 1]);
                }
            // load B-lo; phase 2: hi*lo
            #pragma unroll
            for (int p = 0; p < 4; ++p)
                LDSM4(fc[p][0], fc[p][1], fc[p][2], fc[p][3],
                      Bl + boff + p * (16 * APITCH));
            #pragma unroll
            for (int mt = 0; mt < 4; ++mt)
                #pragma unroll
                for (int nt = 0; nt < 8; ++nt) {
                    const int p = nt >> 1, h = (nt & 1) * 2;
                    MMA16816(acc[mt][nt], fa[mt], fc[p][h], fc[p][h + 1]);
                }
            // reload A with lo; phase 3: lo*hi
            #pragma unroll
            for (int mt = 0; mt < 4; ++mt)
                LDSM4(fa[mt][0], fa[mt][1], fa[mt][2], fa[mt][3],
                      Al + aoff + mt * (16 * APITCH));
            #pragma unroll
            for (int mt = 0; mt < 4; ++mt)
                #pragma unroll
                for (int nt = 0; nt < 8; ++nt) {
                    const int p = nt >> 1, h = (nt & 1) * 2;
                    MMA16816(acc[mt][nt], fa[mt], fb[p][h], fb[p][h + 1]);
                }
        }
        __syncthreads();
    }

    const int erow = lane >> 2, ecol = (lane & 3) * 2;
    #pragma unroll
    for (int mt = 0; mt < 4; ++mt) {
        #pragma unroll
        for (int nt = 0; nt < 8; ++nt) {
            int m0 = tm + wm + mt * 16 + erow;
            int n0 = tn + wn + nt * 8 + ecol;
            float bx = bias[n0], by = bias[n0 + 1];
            if (m0 < mmax) {
                float2 o;
                o.x = (acc[mt][nt][0] + bx) * scale;
                o.y = (acc[mt][nt][1] + by) * scale;
                *(float2*)(Y + (size_t)m0 * D_ + n0) = o;
            }
            if (m0 + 8 < mmax) {
                float2 o;
                o.x = (acc[mt][nt][2] + bx) * scale;
                o.y = (acc[mt][nt][3] + by) * scale;
                *(float2*)(Y + (size_t)(m0 + 8) * D_ + n0) = o;
            }
        }
    }
}

__global__ __launch_bounds__(128, 2) void mma_gemm_qkv(
    const __nv_bfloat16* __restrict__ Xhi, const __nv_bfloat16* __restrict__ Xlo,
    const __nv_bfloat16* __restrict__ Whi, const __nv_bfloat16* __restrict__ Wlo,
    const float* __restrict__ bq, const float* __restrict__ bk,
    const float* __restrict__ bv, float* __restrict__ Y, int m0g, int mmax)
{
    const int z = blockIdx.z;
    const size_t wo = (size_t)z * D_ * D_;
    const float* bias = (z == 0) ? bq : (z == 1) ? bk : bv;
    gemm_body(Xhi, Xlo, Whi + wo, Wlo + wo, bias,
              Y + (size_t)z * MTOT * D_, (z == 0) ? SCALE_Q : 1.f, m0g, mmax);
}

__global__ __launch_bounds__(128, 2) void mma_gemm(
    const __nv_bfloat16* __restrict__ Xhi, const __nv_bfloat16* __restrict__ Xlo,
    const __nv_bfloat16* __restrict__ Whi, const __nv_bfloat16* __restrict__ Wlo,
    const float* __restrict__ bias, float* __restrict__ Y, float scale,
    int m0g, int mmax)
{
    gemm_body(Xhi, Xlo, Whi, Wlo, bias, Y, scale, m0g, mmax);
}

// ============================================================================
// Fused flash attention: 64-row Q tiles, 128 threads.
// ============================================================================
#define FPITCH 144
#define KVROWB (64 * FPITCH)
#define KVSTG  (4 * KVROWB)
#define FA_SMEM (2 * KVSTG)

__device__ __forceinline__ void load_kv(
    uint32_t st, int t0, size_t kvbase, int tid,
    const __nv_bfloat16* __restrict__ khi, const __nv_bfloat16* __restrict__ klo,
    const __nv_bfloat16* __restrict__ vhi, const __nv_bfloat16* __restrict__ vlo)
{
    #pragma unroll
    for (int j = 0; j < 16; ++j) {
        int g = tid + j * 128;
        int tens = g >> 9, i = g & 511, row = i >> 3, seg = i & 7;
        const __nv_bfloat16* bp = (tens == 0) ? khi : (tens == 1) ? klo
                                 : (tens == 2) ? vhi : vlo;
        const void* src = bp + kvbase + (size_t)(t0 + row) * D_ + seg * 8;
        uint32_t dst = st + tens * KVROWB + row * FPITCH + seg * 16;
        CP_ASYNC16(dst, src, (t0 + row) < S_ ? 16 : 0);
    }
}

__global__ __launch_bounds__(128) void flash_attn(
    const __nv_bfloat16* __restrict__ qhi, const __nv_bfloat16* __restrict__ qlo,
    const __nv_bfloat16* __restrict__ khi, const __nv_bfloat16* __restrict__ klo,
    const __nv_bfloat16* __restrict__ vhi, const __nv_bfloat16* __restrict__ vlo,
    float* __restrict__ Xo,
    __nv_bfloat16* __restrict__ Xhi, __nv_bfloat16* __restrict__ Xlo, int bh0)
{
    extern __shared__ char smem[];
    const uint32_t sb = smem_u32(smem);
    const int tid = threadIdx.x, wid = tid >> 5, lane = tid & 31;
    const int bh = bh0 + blockIdx.x, b = bh >> 4, h = bh & 15;
    const int m0 = blockIdx.y * 64;
    const size_t kvbase = (size_t)b * S_ * D_ + h * HD_;

    #pragma unroll
    for (int j = 0; j < 8; ++j) {
        int g = tid + j * 128;
        int half = g >> 9, i = g & 511, row = i >> 3, seg = i & 7;
        const __nv_bfloat16* src = (half ? qlo : qhi) + kvbase
                                 + (size_t)(m0 + row) * D_ + seg * 8;
        uint32_t dst = sb + half * KVSTG + row * FPITCH + seg * 16;
        CP_ASYNC16(dst, src, (m0 + row) < S_ ? 16 : 0);
    }
    CP_COMMIT(); CP_WAIT0();
    __syncthreads();

    uint32_t qh[4][4], ql[4][4];
    {
        const uint32_t base = sb + (uint32_t)(wid * 16 + (lane & 15)) * FPITCH
                            + (lane >> 4) * 16;
        #pragma unroll
        for (int kk = 0; kk < 4; ++kk) {
            LDSM4(qh[kk][0], qh[kk][1], qh[kk][2], qh[kk][3], base + kk * 32);
            LDSM4(ql[kk][0], ql[kk][1], ql[kk][2], ql[kk][3], base + KVSTG + kk * 32);
        }
    }
    __syncthreads();

    float acc_o[8][4] = {};
    float mrow[2] = {-1e30f, -1e30f}, lrow[2] = {0.f, 0.f};
    const int brow = ((lane >> 4) << 3) + (lane & 7);
    const int bk   = (lane >> 3) & 1;
    const int quad = lane & 3;

    load_kv(sb, 0, kvbase, tid, khi, klo, vhi, vlo);
    CP_COMMIT();

    #pragma unroll 1
    for (int kv = 0; kv < 5; ++kv) {
        CP_WAIT0();
        __syncthreads();
        const uint32_t Ks = sb + (kv & 1) * KVSTG;
        const uint32_t Vs = Ks + 2 * KVROWB;
        if (kv < 4) {
            load_kv(sb + ((kv + 1) & 1) * KVSTG, (kv + 1) * 64, kvbase, tid,
                    khi, klo, vhi, vlo);
            CP_COMMIT();
        }

        float s[8][4] = {};
        #pragma unroll
        for (int kk = 0; kk < 4; ++kk) {
            uint32_t kh[4][4], kl[4][4];
            #pragma unroll
            for (int p = 0; p < 4; ++p) {
                uint32_t ko = Ks + (uint32_t)(p * 16 + brow) * FPITCH + kk * 32 + bk * 16;
                LDSM4(kh[p][0], kh[p][1], kh[p][2], kh[p][3], ko);
                LDSM4(kl[p][0], kl[p][1], kl[p][2], kl[p][3], ko + KVROWB);
            }
            #pragma unroll
            for (int p = 0; p < 4; ++p) {
                MMA16816(s[2*p],   qh[kk], kh[p][0], kh[p][1]);
                MMA16816(s[2*p+1], qh[kk], kh[p][2], kh[p][3]);
                MMA16816(s[2*p],   qh[kk], kl[p][0], kl[p][1]);
                MMA16816(s[2*p+1], qh[kk], kl[p][2], kl[p][3]);
                MMA16816(s[2*p],   ql[kk], kh[p][0], kh[p][1]);
                MMA16816(s[2*p+1], ql[kk], kh[p][2], kh[p][3]);
            }
        }

        if (kv == 4) {
            #pragma unroll
            for (int nt = 0; nt < 8; ++nt)
                #pragma unroll
                for (int rg = 0; rg < 4; ++rg) {
                    int col = 256 + nt * 8 + quad * 2 + (rg & 1);
                    if (col >= S_) s[nt][rg] = -1e30f;
                }
        }

        #pragma unroll
        for (int rr = 0; rr < 2; ++rr) {
            float mx = -1e30f;
            #pragma unroll
            for (int nt = 0; nt < 8; ++nt)
                mx = fmaxf(mx, fmaxf(s[nt][2*rr], s[nt][2*rr+1]));
            mx = fmaxf(mx, __shfl_xor_sync(0xffffffffu, mx, 1));
            mx = fmaxf(mx, __shfl_xor_sync(0xffffffffu, mx, 2));
            float mnew = fmaxf(mrow[rr], mx);
            float alpha = fexp(mrow[rr] - mnew);
            mrow[rr] = mnew;
            float sum = 0.f;
            #pragma unroll
            for (int nt = 0; nt < 8; ++nt) {
                float p0 = fexp(s[nt][2*rr]   - mnew);
                float p1 = fexp(s[nt][2*rr+1] - mnew);
                s[nt][2*rr] = p0; s[nt][2*rr+1] = p1;
                sum += p0 + p1;
            }
            sum += __shfl_xor_sync(0xffffffffu, sum, 1);
            sum += __shfl_xor_sync(0xffffffffu, sum, 2);
            lrow[rr] = lrow[rr] * alpha + sum;
            #pragma unroll
            for (int nt = 0; nt < 8; ++nt) {
                acc_o[nt][2*rr]   *= alpha;
                acc_o[nt][2*rr+1] *= alpha;
            }
        }

        #pragma unroll
        for (int kk = 0; kk < 4; ++kk) {
            uint32_t ph[4], pl[4];
            #pragma unroll
            for (int rg = 0; rg < 4; ++rg) {
                int nt = 2 * kk + (rg >> 1);
                float p0 = s[nt][(rg & 1) * 2];
                float p1 = s[nt][(rg & 1) * 2 + 1];
                __nv_bfloat162 hb = __floats2bfloat162_rn(p0, p1);
                float l0 = p0 - __bfloat162float(hb.x);
                float l1 = p1 - __bfloat162float(hb.y);
                __nv_bfloat162 lb = __floats2bfloat162_rn(l0, l1);
                ph[rg] = *(uint32_t*)&hb;
                pl[rg] = *(uint32_t*)&lb;
            }
            uint32_t vh[4][4], vl[4][4];
            #pragma unroll
            for (int p = 0; p < 4; ++p) {
                uint32_t vo = Vs + (uint32_t)(kk * 16 + (lane & 15)) * FPITCH
                            + p * 32 + (lane >> 4) * 16;
                LDSM4T(vh[p][0], vh[p][1], vh[p][2], vh[p][3], vo);
                LDSM4T(vl[p][0], vl[p][1], vl[p][2], vl[p][3], vo + KVROWB);
            }
            #pragma unroll
            for (int p = 0; p < 4; ++p) {
                MMA16816(acc_o[2*p],   ph, vh[p][0], vh[p][1]);
                MMA16816(acc_o[2*p+1], ph, vh[p][2], vh[p][3]);
                MMA16816(acc_o[2*p],   ph, vl[p][0], vl[p][1]);
                MMA16816(acc_o[2*p+1], ph, vl[p][2], vl[p][3]);
                MMA16816(acc_o[2*p],   pl, vh[p][0], vh[p][1]);
                MMA16816(acc_o[2*p+1], pl, vh[p][2], vh[p][3]);
            }
        }
    }

    {
        const int r = lane >> 2, q2 = quad * 2;
        #pragma unroll
        for (int rr = 0; rr < 2; ++rr) {
            int m = m0 + wid * 16 + r + rr * 8;
            if (m < S_) {
                float inv = 1.f / lrow[rr];
                size_t off = ((size_t)b * S_ + m) * D_ + h * HD_ + q2;
                #pragma unroll
                for (int nt = 0; nt < 8; ++nt) {
                    float ox = acc_o[nt][2*rr]   * inv;
                    float oy = acc_o[nt][2*rr+1] * inv;
                    float2 o = make_float2(ox, oy);
                    *(float2*)(Xo + off + nt * 8) = o;
                    __nv_bfloat162 hb = __floats2bfloat162_rn(ox, oy);
                    __nv_bfloat162 lb = __floats2bfloat162_rn(
                        ox - __bfloat162float(hb.x), oy - __bfloat162float(hb.y));
                    *(__nv_bfloat162*)(Xhi + off + nt * 8) = hb;
                    *(__nv_bfloat162*)(Xlo + off + nt * 8) = lb;
                }
            }
        }
    }
}

// ============================================================================
// attn_tail: query row s = 256; also writes xhi/xlo
// ============================================================================
#define TAIL_SMEM ((257 * 65 + 64 + 257 + 256 + 4 * 64) * 4)
__global__ __launch_bounds__(256) void attn_tail(
    const __nv_bfloat16* __restrict__ qhi, const __nv_bfloat16* __restrict__ qlo,
    const __nv_bfloat16* __restrict__ khi, const __nv_bfloat16* __restrict__ klo,
    const __nv_bfloat16* __restrict__ vhi, const __nv_bfloat16* __restrict__ vlo,
    float* __restrict__ Xo,
    __nv_bfloat16* __restrict__ Xhi, __nv_bfloat16* __restrict__ Xlo, int bh0)
{
    extern __shared__ float fs[];
    float* ks  = fs;
    float* q   = ks + 257 * 65;
    float* p   = q + 64;
    float* red = p + 257;
    float* vp  = red + 256;
    const int t = threadIdx.x;
    const int bh = bh0 + blockIdx.x, b = bh >> 4, h = bh & 15;
    const size_t base = (size_t)b * S_ * D_ + h * HD_;

    if (t < 64) {
        size_t o = base + (size_t)256 * D_ + t;
        q[t] = __bfloat162float(qhi[o]) + __bfloat162float(qlo[o]);
    }
    for (int i = t; i < 257 * 64; i += 256) {
        int row = i >> 6, d = i & 63;
        size_t o = base + (size_t)row * D_ + d;
        ks[row * 65 + d] = __bfloat162float(khi[o]) + __bfloat162float(klo[o]);
    }
    __syncthreads();

    float v0 = 0.f, v1 = -1e30f;
    {
        const float* kr = ks + t * 65;
        #pragma unroll 8
        for (int d = 0; d < 64; ++d) v0 = fmaf(q[d], kr[d], v0);
    }
    if (t == 0) {
        v1 = 0.f;
        const float* kr = ks + 256 * 65;
        #pragma unroll 8
        for (int d = 0; d < 64; ++d) v1 = fmaf(q[d], kr[d], v1);
    }

    red[t] = fmaxf(v0, v1);
    __syncthreads();
    #pragma unroll
    for (int o = 128; o; o >>= 1) {
        if (t < o) red[t] = fmaxf(red[t], red[t + o]);
        __syncthreads();
    }
    float rmax = red[0];
    __syncthreads();
    float e0 = fexp(v0 - rmax);
    float e1 = (t == 0) ? fexp(v1 - rmax) : 0.f;
    red[t] = e0 + e1;
    __syncthreads();
    #pragma unroll
    for (int o = 128; o; o >>= 1) {
        if (t < o) red[t] += red[t + o];
        __syncthreads();
    }
    float inv = 1.f / red[0];
    p[t] = e0 * inv;
    if (t == 0) p[256] = e1 * inv;
    __syncthreads();

    {
        int d = t & 63, grp = t >> 6;
        float acc = 0.f;
        for (int tt = grp; tt < S_; tt += 4) {
            size_t off = base + (size_t)tt * D_ + d;
            acc = fmaf(p[tt], __bfloat162float(vhi[off]) + __bfloat162float(vlo[off]), acc);
        }
        vp[grp * 64 + d] = acc;
    }
    __syncthreads();
    if (t < 64) {
        float o = vp[t] + vp[64 + t] + vp[128 + t] + vp[192 + t];
        size_t off = ((size_t)b * S_ + 256) * D_ + h * HD_ + t;
        Xo[off] = o;
        __nv_bfloat16 hb = __float2bfloat16(o);
        Xhi[off] = hb;
        Xlo[off] = __float2bfloat16(o - __bfloat162float(hb));
    }
}

// ============================================================================
// xa: grid (BH, KE, 16*nproj); batch offset b0
// ============================================================================
__global__ __launch_bounds__(256) void xa_kernel(
    const float* __restrict__ X,
    const float* __restrict__ A0, const float* __restrict__ A1,
    const float* __restrict__ A2,
    const int* __restrict__ idx, float* __restrict__ xa, int b0)
{
    int b = b0 + blockIdx.x, slot = blockIdx.y;
    int proj = blockIdx.z >> 4, zz = blockIdx.z & 15;
    int rh = zz >> 3, sc = zz & 7;
    const float* A = (proj == 0) ? A0 : (proj == 1) ? A1 : A2;
    float* xad = xa + (size_t)proj * B_ * KE_ * S_ * R_;
    int sbase = sc * 33;
    int smax = min(S_, sbase + 33);
    int e = idx[b * KE_ + slot];
    __shared__ float As[8][D_];
    const float* Ap = A + ((size_t)e * R_ + rh * 8) * D_;
    for (int i = threadIdx.x; i < 8 * D_ / 4; i += 256)
        ((float4*)As)[i] = ((const float4*)Ap)[i];
    __syncthreads();

    int w = threadIdx.x >> 5, lane = threadIdx.x & 31;
    for (int s4 = sbase + w * 4; s4 < smax; s4 += 32) {
        float sum[8][4];
        #pragma unroll
        for (int r = 0; r < 8; r++)
            #pragma unroll
            for (int si = 0; si < 4; si++) sum[r][si] = 0.f;

        #pragma unroll 1
        for (int c = 0; c < 8; c++) {
            float4 xv[4];
            #pragma unroll
            for (int si = 0; si < 4; si++) {
                int s = s4 + si;
                xv[si] = (s < S_)
                    ? *(const float4*)(X + ((size_t)b * S_ + s) * D_ + c * 128 + lane * 4)
                    : make_float4(0.f, 0.f, 0.f, 0.f);
            }
            #pragma unroll
            for (int r = 0; r < 8; r++) {
                float4 av = *(const float4*)&As[r][c * 128 + lane * 4];
                #pragma unroll
                for (int si = 0; si < 4; si++)
                    sum[r][si] = fmaf(xv[si].x, av.x,
                                 fmaf(xv[si].y, av.y,
                                 fmaf(xv[si].z, av.z,
                                 fmaf(xv[si].w, av.w, sum[r][si]))));
            }
        }
        #pragma unroll
        for (int r = 0; r < 8; r++)
            #pragma unroll
            for (int si = 0; si < 4; si++) {
                float v = sum[r][si];
                #pragma unroll
                for (int o = 16; o; o >>= 1) v += __shfl_xor_sync(0xffffffffu, v, o);
                int s = s4 + si;
                if (lane == 0 && s < S_)
                    xad[(((size_t)b * KE_ + slot) * S_ + s) * R_ + rh * 8 + r] = v;
            }
    }
}

// ============================================================================
// lora_add / lora_split3
// ============================================================================
__global__ __launch_bounds__(256) void lora_add(
    const float* __restrict__ Bm, const int* __restrict__ idx,
    const float* __restrict__ gates, const float* __restrict__ xa,
    float* __restrict__ Y, float scale, int b0)
{
    int b = b0 + blockIdx.x;
    int cn = blockIdx.y << 6;
    int t = threadIdx.x;
    __shared__ float Bs[2][64][17];
    __shared__ float xs[2][64][17];
    int e0 = idx[b * KE_], e1 = idx[b * KE_ + 1];
    float g0 = gates[b * KE_] * scale, g1 = gates[b * KE_ + 1] * scale;

    for (int i = t; i < 2048; i += 256) {
        int slot = i >> 10, rem = i & 1023, c = rem >> 4, r = rem & 15;
        Bs[slot][c][r] = Bm[((size_t)(slot ? e1 : e0) * D_ + cn + c) * R_ + r];
    }

    int c = t & 63, sq = t >> 6;
    for (int s0 = 0; s0 < S_; s0 += 64) {
        __syncthreads();
        for (int i = t; i < 2048; i += 256) {
            int slot = i >> 10, rem = i & 1023, si = rem >> 4, r = rem & 15;
            int s = s0 + si;
            float v = (s < S_) ? xa[(((size_t)b * KE_ + slot) * S_ + s) * R_ + r] : 0.f;
            xs[slot][si][r] = v * (slot ? g1 : g0);
        }
        __syncthreads();
        for (int si = sq; si < 64; si += 4) {
            int s = s0 + si;
            if (s >= S_) break;
            float sum = 0.f;
            #pragma unroll
            for (int r = 0; r < 16; r++) {
                sum = fmaf(xs[0][si][r], Bs[0][c][r], sum);
                sum = fmaf(xs[1][si][r], Bs[1][c][r], sum);
            }
            Y[((size_t)b * S_ + s) * D_ + cn + c] += sum;
        }
    }
}

__global__ __launch_bounds__(256) void lora_split3(
    const float* __restrict__ Bq, const float* __restrict__ Bk,
    const float* __restrict__ Bv,
    const int* __restrict__ idx, const float* __restrict__ gates,
    const float* __restrict__ xa, const float* __restrict__ Yin,
    __nv_bfloat16* __restrict__ qhi, __nv_bfloat16* __restrict__ qlo,
    __nv_bfloat16* __restrict__ khi, __nv_bfloat16* __restrict__ klo,
    __nv_bfloat16* __restrict__ vhi, __nv_bfloat16* __restrict__ vlo, int b0)
{
    const int z = blockIdx.z;
    const float* Bm = (z == 0) ? Bq : (z == 1) ? Bk : Bv;
    const float* Yz = Yin + (size_t)z * MTOT * D_;
    const float* xaz = xa + (size_t)z * B_ * KE_ * S_ * R_;
    __nv_bfloat16* Yhi = (z == 0) ? qhi : (z == 1) ? khi : vhi;
    __nv_bfloat16* Ylo = (z == 0) ? qlo : (z == 1) ? klo : vlo;
    const float scale = (z == 0) ? SCALE_Q : 1.f;

    int b = b0 + blockIdx.x;
    int cn = blockIdx.y << 6;
    int t = threadIdx.x;
    __shared__ float Bs[2][64][17];
    __shared__ float xs[2][64][17];
    int e0 = idx[b * KE_], e1 = idx[b * KE_ + 1];
    float g0 = gates[b * KE_] * scale, g1 = gates[b * KE_ + 1] * scale;

    for (int i = t; i < 2048; i += 256) {
        int slot = i >> 10, rem = i & 1023, c = rem >> 4, r = rem & 15;
        Bs[slot][c][r] = Bm[((size_t)(slot ? e1 : e0) * D_ + cn + c) * R_ + r];
    }

    int c = t & 63, sq = t >> 6;
    for (int s0 = 0; s0 < S_; s0 += 64) {
        __syncthreads();
        for (int i = t; i < 2048; i += 256) {
            int slot = i >> 10, rem = i & 1023, si = rem >> 4, r = rem & 15;
            int s = s0 + si;
            float v = (s < S_) ? xaz[(((size_t)b * KE_ + slot) * S_ + s) * R_ + r] : 0.f;
            xs[slot][si][r] = v * (slot ? g1 : g0);
        }
        __syncthreads();
        for (int si = sq; si < 64; si += 4) {
            int s = s0 + si;
            if (s >= S_) break;
            float sum = 0.f;
            #pragma unroll
            for (int r = 0; r < 16; r++) {
                sum = fmaf(xs[0][si][r], Bs[0][c][r], sum);
                sum = fmaf(xs[1][si][r], Bs[1][c][r], sum);
            }
            size_t off = ((size_t)b * S_ + s) * D_ + cn + c;
            float v = Yz[off] + sum;
            __nv_bfloat16 hb = __float2bfloat16(v);
            Yhi[off] = hb;
            Ylo[off] = __float2bfloat16(v - __bfloat162float(hb));
        }
    }
}

// ---------------- host launcher --------------------------------------------
extern "C" void kernel_launch(void* const* d_in, const int* in_sizes, int n_in,
                              void* d_out, int out_size)
{
    const float* hs    = (const float*)d_in[0];
    const int*   idx   = (const int*)  d_in[1];
    const float* gates = (const float*)d_in[2];
    const float* wq = (const float*)d_in[3];  const float* Aq = (const float*)d_in[4];
    const float* Bq = (const float*)d_in[5];  const float* bq = (const float*)d_in[6];
    const float* wk = (const float*)d_in[7];  const float* Ak = (const float*)d_in[8];
    const float* Bk = (const float*)d_in[9];  const float* bk = (const float*)d_in[10];
    const float* wv = (const float*)d_in[11]; const float* Av = (const float*)d_in[12];
    const float* Bv = (const float*)d_in[13]; const float* bv = (const float*)d_in[14];
    const float* wo = (const float*)d_in[15]; const float* Ao = (const float*)d_in[16];
    const float* Bo = (const float*)d_in[17]; const float* bo = (const float*)d_in[18];
    float* out = (float*)d_out;

    float *tmp, *x2, *xa;
    __nv_bfloat16 *xhi, *xlo, *whi, *wlo, *qhi, *qlo, *khi, *klo, *vhi, *vlo;
    cudaGetSymbolAddress((void**)&tmp, g_tmp);
    cudaGetSymbolAddress((void**)&x2,  g_x2);
    cudaGetSymbolAddress((void**)&xa,  g_xa);
    cudaGetSymbolAddress((void**)&xhi, g_xhi);
    cudaGetSymbolAddress((void**)&xlo, g_xlo);
    cudaGetSymbolAddress((void**)&whi, g_whi);
    cudaGetSymbolAddress((void**)&wlo, g_wlo);
    cudaGetSymbolAddress((void**)&qhi, g_qhi);
    cudaGetSymbolAddress((void**)&qlo, g_qlo);
    cudaGetSymbolAddress((void**)&khi, g_khi);
    cudaGetSymbolAddress((void**)&klo, g_klo);
    cudaGetSymbolAddress((void**)&vhi, g_vhi);
    cudaGetSymbolAddress((void**)&vlo, g_vlo);

    cudaFuncSetAttribute(mma_gemm_qkv, cudaFuncAttributeMaxDynamicSharedMemorySize, GEMM_SMEM);
    cudaFuncSetAttribute(mma_gemm, cudaFuncAttributeMaxDynamicSharedMemorySize, GEMM_SMEM);
    cudaFuncSetAttribute(flash_attn, cudaFuncAttributeMaxDynamicSharedMemorySize, FA_SMEM);
    cudaFuncSetAttribute(attn_tail, cudaFuncAttributeMaxDynamicSharedMemorySize, TAIL_SMEM);

    static cudaStream_t s1 = nullptr, s2 = nullptr;
    static cudaEvent_t evR, evW, evXA[2], evEnd;
    if (!s1) {
        cudaStreamCreateWithFlags(&s1, cudaStreamNonBlocking);
        cudaStreamCreateWithFlags(&s2, cudaStreamNonBlocking);
        cudaEventCreateWithFlags(&evR, cudaEventDisableTiming);
        cudaEventCreateWithFlags(&evW, cudaEventDisableTiming);
        cudaEventCreateWithFlags(&evXA[0], cudaEventDisableTiming);
        cudaEventCreateWithFlags(&evXA[1], cudaEventDisableTiming);
        cudaEventCreateWithFlags(&evEnd, cudaEventDisableTiming);
    }

    const int nw4 = D_ * D_ / 4;
    const int nh4 = MH_ * D_ / 4;

    // ---- fork side stream s2: W split + both halves' xa(qkv) ----
    cudaEventRecord(evR, 0);
    cudaStreamWaitEvent(s2, evR, 0);
    cudaStreamWaitEvent(s1, evR, 0);
    split_w4<<<dim3((nw4 + 255) / 256, 4), 256, 0, s2>>>(
        (const float4*)wq, (const float4*)wk, (const float4*)wv, (const float4*)wo,
        (uint2*)whi, (uint2*)wlo);
    cudaEventRecord(evW, s2);
    xa_kernel<<<dim3(BH_, KE_, 48), 256, 0, s2>>>(hs, Aq, Ak, Av, idx, xa, 0);
    cudaEventRecord(evXA[0], s2);
    xa_kernel<<<dim3(BH_, KE_, 48), 256, 0, s2>>>(hs, Aq, Ak, Av, idx, xa, BH_);
    cudaEventRecord(evXA[1], s2);

    // ---- per-half pipelines on stream 0 (half 0) and s1 (half 1) ----
    for (int h = 0; h < 2; ++h) {
        cudaStream_t st = h ? s1 : 0;
        const int b0 = h * BH_;
        const int m0 = h * MH_;
        const int mmax = m0 + MH_;
        const int bh0 = b0 * H_;

        split_bf16<<<(nh4 + 255) / 256, 256, 0, st>>>(
            (const float4*)(hs + (size_t)m0 * D_),
            (uint2*)(xhi + (size_t)m0 * D_), (uint2*)(xlo + (size_t)m0 * D_), nh4);

        cudaStreamWaitEvent(st, evW, 0);
        mma_gemm_qkv<<<dim3(8, 33, 3), 128, GEMM_SMEM, st>>>(
            xhi, xlo, whi, wlo, bq, bk, bv, tmp, m0, mmax);

        cudaStreamWaitEvent(st, evXA[h], 0);
        lora_split3<<<dim3(BH_, 16, 3), 256, 0, st>>>(
            Bq, Bk, Bv, idx, gates, xa, tmp, qhi, qlo, khi, klo, vhi, vlo, b0);

        attn_tail<<<BH_ * H_, 256, TAIL_SMEM, st>>>(
            qhi, qlo, khi, klo, vhi, vlo, x2, xhi, xlo, bh0);
        flash_attn<<<dim3(BH_ * H_, 4), 128, FA_SMEM, st>>>(
            qhi, qlo, khi, klo, vhi, vlo, x2, xhi, xlo, bh0);

        xa_kernel<<<dim3(BH_, KE_, 16), 256, 0, st>>>(x2, Ao, Ao, Ao, idx, xa, b0);

        mma_gemm<<<dim3(8, 33), 128, GEMM_SMEM, st>>>(
            xhi, xlo, whi + (size_t)3 * D_ * D_, wlo + (size_t)3 * D_ * D_,
            bo, out, 1.f, m0, mmax);

        lora_add<<<dim3(BH_, 16), 256, 0, st>>>(Bo, idx, gates, xa, out, 1.f, b0);
    }

    // join half 1 back into stream 0
    cudaEventRecord(evEnd, s1);
    cudaStreamWaitEvent(0, evEnd, 0);
}

// round 15
// speedup vs baseline: 1.1097x; 1.0537x over previous
#include <cuda_runtime.h>
#include <cuda_bf16.h>
#include <cstdint>

#define B_ 32
#define S_ 257
#define D_ 1024
#define H_ 16
#define HD_ 64
#define E_ 8
#define R_ 16
#define KE_ 2
#define MTOT (B_*S_)
#define BH_ 16
#define MH_ (BH_*S_)
#define SCALE_Q 0.125f

// ---------------- scratch (device globals: allocation-free) ----------------
__device__ float g_tmp[(size_t)3 * MTOT * D_];
__device__ float g_x2 [(size_t)MTOT * D_];
__device__ float g_xa [(size_t)3 * B_ * KE_ * S_ * R_];
__device__ __nv_bfloat16 g_xhi[(size_t)MTOT * D_];
__device__ __nv_bfloat16 g_xlo[(size_t)MTOT * D_];
__device__ __nv_bfloat16 g_whi[(size_t)4 * D_ * D_];
__device__ __nv_bfloat16 g_wlo[(size_t)4 * D_ * D_];
__device__ __nv_bfloat16 g_qhi[(size_t)MTOT * D_];
__device__ __nv_bfloat16 g_qlo[(size_t)MTOT * D_];
__device__ __nv_bfloat16 g_khi[(size_t)MTOT * D_];
__device__ __nv_bfloat16 g_klo[(size_t)MTOT * D_];
__device__ __nv_bfloat16 g_vhi[(size_t)MTOT * D_];
__device__ __nv_bfloat16 g_vlo[(size_t)MTOT * D_];

// ========================= helpers ==========================================
__device__ __forceinline__ uint32_t smem_u32(const void* p) {
    uint32_t a;
    asm("{ .reg .u64 t; cvta.to.shared.u64 t, %1; cvt.u32.u64 %0, t; }"
        : "=r"(a) : "l"(p));
    return a;
}

#define LDSM4(r0, r1, r2, r3, addr) \
    asm volatile("ldmatrix.sync.aligned.m8n8.x4.shared.b16 {%0,%1,%2,%3}, [%4];" \
        : "=r"(r0), "=r"(r1), "=r"(r2), "=r"(r3) : "r"(addr))

#define LDSM4T(r0, r1, r2, r3, addr) \
    asm volatile("ldmatrix.sync.aligned.m8n8.x4.trans.shared.b16 {%0,%1,%2,%3}, [%4];" \
        : "=r"(r0), "=r"(r1), "=r"(r2), "=r"(r3) : "r"(addr))

// non-volatile: lets ptxas interleave/pipeline MMAs with LDSMs
#define MMA16816(d, a, b0, b1) \
    asm("mma.sync.aligned.m16n8k16.row.col.f32.bf16.bf16.f32 " \
        "{%0,%1,%2,%3}, {%4,%5,%6,%7}, {%8,%9}, {%0,%1,%2,%3};" \
        : "+f"((d)[0]), "+f"((d)[1]), "+f"((d)[2]), "+f"((d)[3]) \
        : "r"((a)[0]), "r"((a)[1]), "r"((a)[2]), "r"((a)[3]), "r"(b0), "r"(b1))

#define CP_ASYNC16(dst, src, sz) \
    asm volatile("cp.async.cg.shared.global [%0], [%1], 16, %2;" \
        :: "r"(dst), "l"(src), "r"(sz))
#define CP_COMMIT()  asm volatile("cp.async.commit_group;" ::: "memory")
#define CP_WAIT0()   asm volatile("cp.async.wait_group 0;" ::: "memory")

__device__ __forceinline__ float fexp(float x) {
    x = fmaxf(x, -80.f);
    float t = x * 1.4426950408889634f;
    float z = t + 12582912.f;
    int   k = __float_as_int(z) - 0x4B400000;
    float f = t - (z - 12582912.f);
    float p = 1.3333558146428443e-3f;
    p = fmaf(p, f, 9.6181291076284772e-3f);
    p = fmaf(p, f, 5.5504108664821580e-2f);
    p = fmaf(p, f, 2.4022650695910071e-1f);
    p = fmaf(p, f, 6.9314718055994531e-1f);
    p = fmaf(p, f, 1.0f);
    return __int_as_float(__float_as_int(p) + (k << 23));
}

// ============================================================================
// split fp32 -> (bf16 hi, bf16 lo)
// ============================================================================
__device__ __forceinline__ void split_one(
    const float4* __restrict__ x, uint2* __restrict__ hi, uint2* __restrict__ lo, int i)
{
    float4 v = x[i];
    __nv_bfloat162 h01 = __floats2bfloat162_rn(v.x, v.y);
    __nv_bfloat162 h23 = __floats2bfloat162_rn(v.z, v.w);
    float lx = v.x - __bfloat162float(h01.x);
    float ly = v.y - __bfloat162float(h01.y);
    float lz = v.z - __bfloat162float(h23.x);
    float lw = v.w - __bfloat162float(h23.y);
    __nv_bfloat162 l01 = __floats2bfloat162_rn(lx, ly);
    __nv_bfloat162 l23 = __floats2bfloat162_rn(lz, lw);
    uint2 hv, lv;
    hv.x = *(uint32_t*)&h01; hv.y = *(uint32_t*)&h23;
    lv.x = *(uint32_t*)&l01; lv.y = *(uint32_t*)&l23;
    hi[i] = hv; lo[i] = lv;
}

__global__ __launch_bounds__(256) void split_bf16(
    const float4* __restrict__ x, uint2* __restrict__ hi, uint2* __restrict__ lo, int n4)
{
    int i = blockIdx.x * 256 + threadIdx.x;
    if (i < n4) split_one(x, hi, lo, i);
}

__global__ __launch_bounds__(256) void split_w4(
    const float4* __restrict__ w0, const float4* __restrict__ w1,
    const float4* __restrict__ w2, const float4* __restrict__ w3,
    uint2* __restrict__ hi, uint2* __restrict__ lo)
{
    const int n4 = D_ * D_ / 4;
    int i = blockIdx.x * 256 + threadIdx.x;
    if (i >= n4) return;
    int z = blockIdx.y;
    const float4* src = (z == 0) ? w0 : (z == 1) ? w1 : (z == 2) ? w2 : w3;
    split_one(src, hi + (size_t)z * n4, lo + (size_t)z * n4, i);
}

// ============================================================================
// HMMA GEMM via bf16x3 split — 128x128 block tile, 8 warps (64x32), occ 2
// (R12 configuration — measured best)
// ============================================================================
#define APITCH 80
#define TILEB (128 * APITCH)
#define STAGEB (4 * TILEB)            // 40960
#define GEMM_SMEM (2 * STAGEB)        // 81920

__device__ __forceinline__ void stage_load(
    uint32_t sb, int buf, int c, int tm, int tn, int tid, int mmax,
    const __nv_bfloat16* __restrict__ Xhi, const __nv_bfloat16* __restrict__ Xlo,
    const __nv_bfloat16* __restrict__ Whi, const __nv_bfloat16* __restrict__ Wlo)
{
    uint32_t st = sb + buf * STAGEB;
    #pragma unroll
    for (int j = 0; j < 8; ++j) {
        int g = tid + j * 256;
        int tile = g >> 9, i = g & 511, row = i >> 2, seg = i & 3;
        const __nv_bfloat16* base = (tile == 0) ? Xhi : (tile == 1) ? Xlo
                                   : (tile == 2) ? Whi : Wlo;
        int grow = ((tile < 2) ? tm : tn) + row;
        const void* src = base + (size_t)grow * D_ + c * 32 + seg * 8;
        uint32_t dst = st + tile * TILEB + row * APITCH + seg * 16;
        int sz = (tile >= 2 || grow < mmax) ? 16 : 0;
        CP_ASYNC16(dst, src, sz);
    }
}

__device__ __forceinline__ void gemm_body(
    const __nv_bfloat16* __restrict__ Xhi, const __nv_bfloat16* __restrict__ Xlo,
    const __nv_bfloat16* __restrict__ Whi, const __nv_bfloat16* __restrict__ Wlo,
    const float* __restrict__ bias, float* __restrict__ Y, float scale,
    int m0g, int mmax)
{
    extern __shared__ char smem[];
    const uint32_t sb = smem_u32(smem);
    const int tid = threadIdx.x;
    const int wid = tid >> 5, lane = tid & 31;
    const int tm = m0g + (blockIdx.y << 7), tn = blockIdx.x << 7;
    const int wm = (wid & 1) * 64, wn = (wid >> 1) * 32;

    const int lrow = lane & 15;
    const int lk   = lane >> 4;
    const int brow = ((lane >> 4) << 3) + (lane & 7);
    const int bk   = (lane >> 3) & 1;

    float acc[4][4][4] = {};

    stage_load(sb, 0, 0, tm, tn, tid, mmax, Xhi, Xlo, Whi, Wlo);
    CP_COMMIT();

    for (int c = 0; c < 32; ++c) {
        const int buf = c & 1;
        CP_WAIT0();
        __syncthreads();
        if (c + 1 < 32) {
            stage_load(sb, buf ^ 1, c + 1, tm, tn, tid, mmax, Xhi, Xlo, Whi, Wlo);
            CP_COMMIT();
        }

        const uint32_t Ah = sb + buf * STAGEB;
        const uint32_t Al = Ah + TILEB;
        const uint32_t Bh = Ah + 2 * TILEB;
        const uint32_t Bl = Ah + 3 * TILEB;

        #pragma unroll
        for (int kk2 = 0; kk2 < 2; ++kk2) {
            const int kkb = kk2 * 32;
            uint32_t fa[4][4], fb[2][4], fc[2][4];
            const uint32_t aoff = (uint32_t)(wm + lrow) * APITCH + kkb + lk * 16;
            const uint32_t boff = (uint32_t)(wn + brow) * APITCH + kkb + bk * 16;
            #pragma unroll
            for (int mt = 0; mt < 4; ++mt)
                LDSM4(fa[mt][0], fa[mt][1], fa[mt][2], fa[mt][3],
                      Ah + aoff + mt * (16 * APITCH));
            #pragma unroll
            for (int p = 0; p < 2; ++p) {
                LDSM4(fb[p][0], fb[p][1], fb[p][2], fb[p][3],
                      Bh + boff + p * (16 * APITCH));
                LDSM4(fc[p][0], fc[p][1], fc[p][2], fc[p][3],
                      Bl + boff + p * (16 * APITCH));
            }
            // phase 1: hi*hi
            #pragma unroll
            for (int mt = 0; mt < 4; ++mt)
                #pragma unroll
                for (int nt = 0; nt < 4; ++nt) {
                    const int p = nt >> 1, h = (nt & 1) * 2;
                    MMA16816(acc[mt][nt], fa[mt], fb[p][h], fb[p][h + 1]);
                }
            // phase 2: hi*lo
            #pragma unroll
            for (int mt = 0; mt < 4; ++mt)
                #pragma unroll
                for (int nt = 0; nt < 4; ++nt) {
                    const int p = nt >> 1, h = (nt & 1) * 2;
                    MMA16816(acc[mt][nt], fa[mt], fc[p][h], fc[p][h + 1]);
                }
            // reload A with lo; phase 3: lo*hi
            #pragma unroll
            for (int mt = 0; mt < 4; ++mt)
                LDSM4(fa[mt][0], fa[mt][1], fa[mt][2], fa[mt][3],
                      Al + aoff + mt * (16 * APITCH));
            #pragma unroll
            for (int mt = 0; mt < 4; ++mt)
                #pragma unroll
                for (int nt = 0; nt < 4; ++nt) {
                    const int p = nt >> 1, h = (nt & 1) * 2;
                    MMA16816(acc[mt][nt], fa[mt], fb[p][h], fb[p][h + 1]);
                }
        }
        __syncthreads();
    }

    const int erow = lane >> 2, ecol = (lane & 3) * 2;
    #pragma unroll
    for (int mt = 0; mt < 4; ++mt) {
        #pragma unroll
        for (int nt = 0; nt < 4; ++nt) {
            int m0 = tm + wm + mt * 16 + erow;
            int n0 = tn + wn + nt * 8 + ecol;
            float bx = bias[n0], by = bias[n0 + 1];
            if (m0 < mmax) {
                float2 o;
                o.x = (acc[mt][nt][0] + bx) * scale;
                o.y = (acc[mt][nt][1] + by) * scale;
                *(float2*)(Y + (size_t)m0 * D_ + n0) = o;
            }
            if (m0 + 8 < mmax) {
                float2 o;
                o.x = (acc[mt][nt][2] + bx) * scale;
                o.y = (acc[mt][nt][3] + by) * scale;
                *(float2*)(Y + (size_t)(m0 + 8) * D_ + n0) = o;
            }
        }
    }
}

__global__ __launch_bounds__(256, 2) void mma_gemm_qkv(
    const __nv_bfloat16* __restrict__ Xhi, const __nv_bfloat16* __restrict__ Xlo,
    const __nv_bfloat16* __restrict__ Whi, const __nv_bfloat16* __restrict__ Wlo,
    const float* __restrict__ bq, const float* __restrict__ bk,
    const float* __restrict__ bv, float* __restrict__ Y, int m0g, int mmax)
{
    const int z = blockIdx.z;
    const size_t wo = (size_t)z * D_ * D_;
    const float* bias = (z == 0) ? bq : (z == 1) ? bk : bv;
    gemm_body(Xhi, Xlo, Whi + wo, Wlo + wo, bias,
              Y + (size_t)z * MTOT * D_, (z == 0) ? SCALE_Q : 1.f, m0g, mmax);
}

__global__ __launch_bounds__(256, 2) void mma_gemm(
    const __nv_bfloat16* __restrict__ Xhi, const __nv_bfloat16* __restrict__ Xlo,
    const __nv_bfloat16* __restrict__ Whi, const __nv_bfloat16* __restrict__ Wlo,
    const float* __restrict__ bias, float* __restrict__ Y, float scale,
    int m0g, int mmax)
{
    gemm_body(Xhi, Xlo, Whi, Wlo, bias, Y, scale, m0g, mmax);
}

// ============================================================================
// Fused flash attention: 64-row Q tiles, 128 threads.
// ============================================================================
#define FPITCH 144
#define KVROWB (64 * FPITCH)
#define KVSTG  (4 * KVROWB)
#define FA_SMEM (2 * KVSTG)

__device__ __forceinline__ void load_kv(
    uint32_t st, int t0, size_t kvbase, int tid,
    const __nv_bfloat16* __restrict__ khi, const __nv_bfloat16* __restrict__ klo,
    const __nv_bfloat16* __restrict__ vhi, const __nv_bfloat16* __restrict__ vlo)
{
    #pragma unroll
    for (int j = 0; j < 16; ++j) {
        int g = tid + j * 128;
        int tens = g >> 9, i = g & 511, row = i >> 3, seg = i & 7;
        const __nv_bfloat16* bp = (tens == 0) ? khi : (tens == 1) ? klo
                                 : (tens == 2) ? vhi : vlo;
        const void* src = bp + kvbase + (size_t)(t0 + row) * D_ + seg * 8;
        uint32_t dst = st + tens * KVROWB + row * FPITCH + seg * 16;
        CP_ASYNC16(dst, src, (t0 + row) < S_ ? 16 : 0);
    }
}

__global__ __launch_bounds__(128) void flash_attn(
    const __nv_bfloat16* __restrict__ qhi, const __nv_bfloat16* __restrict__ qlo,
    const __nv_bfloat16* __restrict__ khi, const __nv_bfloat16* __restrict__ klo,
    const __nv_bfloat16* __restrict__ vhi, const __nv_bfloat16* __restrict__ vlo,
    float* __restrict__ Xo,
    __nv_bfloat16* __restrict__ Xhi, __nv_bfloat16* __restrict__ Xlo, int bh0)
{
    extern __shared__ char smem[];
    const uint32_t sb = smem_u32(smem);
    const int tid = threadIdx.x, wid = tid >> 5, lane = tid & 31;
    const int bh = bh0 + blockIdx.x, b = bh >> 4, h = bh & 15;
    const int m0 = blockIdx.y * 64;
    const size_t kvbase = (size_t)b * S_ * D_ + h * HD_;

    #pragma unroll
    for (int j = 0; j < 8; ++j) {
        int g = tid + j * 128;
        int half = g >> 9, i = g & 511, row = i >> 3, seg = i & 7;
        const __nv_bfloat16* src = (half ? qlo : qhi) + kvbase
                                 + (size_t)(m0 + row) * D_ + seg * 8;
        uint32_t dst = sb + half * KVSTG + row * FPITCH + seg * 16;
        CP_ASYNC16(dst, src, (m0 + row) < S_ ? 16 : 0);
    }
    CP_COMMIT(); CP_WAIT0();
    __syncthreads();

    uint32_t qh[4][4], ql[4][4];
    {
        const uint32_t base = sb + (uint32_t)(wid * 16 + (lane & 15)) * FPITCH
                            + (lane >> 4) * 16;
        #pragma unroll
        for (int kk = 0; kk < 4; ++kk) {
            LDSM4(qh[kk][0], qh[kk][1], qh[kk][2], qh[kk][3], base + kk * 32);
            LDSM4(ql[kk][0], ql[kk][1], ql[kk][2], ql[kk][3], base + KVSTG + kk * 32);
        }
    }
    __syncthreads();

    float acc_o[8][4] = {};
    float mrow[2] = {-1e30f, -1e30f}, lrow[2] = {0.f, 0.f};
    const int brow = ((lane >> 4) << 3) + (lane & 7);
    const int bk   = (lane >> 3) & 1;
    const int quad = lane & 3;

    load_kv(sb, 0, kvbase, tid, khi, klo, vhi, vlo);
    CP_COMMIT();

    #pragma unroll 1
    for (int kv = 0; kv < 5; ++kv) {
        CP_WAIT0();
        __syncthreads();
        const uint32_t Ks = sb + (kv & 1) * KVSTG;
        const uint32_t Vs = Ks + 2 * KVROWB;
        if (kv < 4) {
            load_kv(sb + ((kv + 1) & 1) * KVSTG, (kv + 1) * 64, kvbase, tid,
                    khi, klo, vhi, vlo);
            CP_COMMIT();
        }

        float s[8][4] = {};
        #pragma unroll
        for (int kk = 0; kk < 4; ++kk) {
            uint32_t kh[4][4], kl[4][4];
            #pragma unroll
            for (int p = 0; p < 4; ++p) {
                uint32_t ko = Ks + (uint32_t)(p * 16 + brow) * FPITCH + kk * 32 + bk * 16;
                LDSM4(kh[p][0], kh[p][1], kh[p][2], kh[p][3], ko);
                LDSM4(kl[p][0], kl[p][1], kl[p][2], kl[p][3], ko + KVROWB);
            }
            #pragma unroll
            for (int p = 0; p < 4; ++p) {
                MMA16816(s[2*p],   qh[kk], kh[p][0], kh[p][1]);
                MMA16816(s[2*p+1], qh[kk], kh[p][2], kh[p][3]);
                MMA16816(s[2*p],   qh[kk], kl[p][0], kl[p][1]);
                MMA16816(s[2*p+1], qh[kk], kl[p][2], kl[p][3]);
                MMA16816(s[2*p],   ql[kk], kh[p][0], kh[p][1]);
                MMA16816(s[2*p+1], ql[kk], kh[p][2], kh[p][3]);
            }
        }

        if (kv == 4) {
            #pragma unroll
            for (int nt = 0; nt < 8; ++nt)
                #pragma unroll
                for (int rg = 0; rg < 4; ++rg) {
                    int col = 256 + nt * 8 + quad * 2 + (rg & 1);
                    if (col >= S_) s[nt][rg] = -1e30f;
                }
        }

        #pragma unroll
        for (int rr = 0; rr < 2; ++rr) {
            float mx = -1e30f;
            #pragma unroll
            for (int nt = 0; nt < 8; ++nt)
                mx = fmaxf(mx, fmaxf(s[nt][2*rr], s[nt][2*rr+1]));
            mx = fmaxf(mx, __shfl_xor_sync(0xffffffffu, mx, 1));
            mx = fmaxf(mx, __shfl_xor_sync(0xffffffffu, mx, 2));
            float mnew = fmaxf(mrow[rr], mx);
            float alpha = fexp(mrow[rr] - mnew);
            mrow[rr] = mnew;
            float sum = 0.f;
            #pragma unroll
            for (int nt = 0; nt < 8; ++nt) {
                float p0 = fexp(s[nt][2*rr]   - mnew);
                float p1 = fexp(s[nt][2*rr+1] - mnew);
                s[nt][2*rr] = p0; s[nt][2*rr+1] = p1;
                sum += p0 + p1;
            }
            sum += __shfl_xor_sync(0xffffffffu, sum, 1);
            sum += __shfl_xor_sync(0xffffffffu, sum, 2);
            lrow[rr] = lrow[rr] * alpha + sum;
            #pragma unroll
            for (int nt = 0; nt < 8; ++nt) {
                acc_o[nt][2*rr]   *= alpha;
                acc_o[nt][2*rr+1] *= alpha;
            }
        }

        #pragma unroll
        for (int kk = 0; kk < 4; ++kk) {
            uint32_t ph[4], pl[4];
            #pragma unroll
            for (int rg = 0; rg < 4; ++rg) {
                int nt = 2 * kk + (rg >> 1);
                float p0 = s[nt][(rg & 1) * 2];
                float p1 = s[nt][(rg & 1) * 2 + 1];
                __nv_bfloat162 hb = __floats2bfloat162_rn(p0, p1);
                float l0 = p0 - __bfloat162float(hb.x);
                float l1 = p1 - __bfloat162float(hb.y);
                __nv_bfloat162 lb = __floats2bfloat162_rn(l0, l1);
                ph[rg] = *(uint32_t*)&hb;
                pl[rg] = *(uint32_t*)&lb;
            }
            uint32_t vh[4][4], vl[4][4];
            #pragma unroll
            for (int p = 0; p < 4; ++p) {
                uint32_t vo = Vs + (uint32_t)(kk * 16 + (lane & 15)) * FPITCH
                            + p * 32 + (lane >> 4) * 16;
                LDSM4T(vh[p][0], vh[p][1], vh[p][2], vh[p][3], vo);
                LDSM4T(vl[p][0], vl[p][1], vl[p][2], vl[p][3], vo + KVROWB);
            }
            #pragma unroll
            for (int p = 0; p < 4; ++p) {
                MMA16816(acc_o[2*p],   ph, vh[p][0], vh[p][1]);
                MMA16816(acc_o[2*p+1], ph, vh[p][2], vh[p][3]);
                MMA16816(acc_o[2*p],   ph, vl[p][0], vl[p][1]);
                MMA16816(acc_o[2*p+1], ph, vl[p][2], vl[p][3]);
                MMA16816(acc_o[2*p],   pl, vh[p][0], vh[p][1]);
                MMA16816(acc_o[2*p+1], pl, vh[p][2], vh[p][3]);
            }
        }
    }

    {
        const int r = lane >> 2, q2 = quad * 2;
        #pragma unroll
        for (int rr = 0; rr < 2; ++rr) {
            int m = m0 + wid * 16 + r + rr * 8;
            if (m < S_) {
                float inv = 1.f / lrow[rr];
                size_t off = ((size_t)b * S_ + m) * D_ + h * HD_ + q2;
                #pragma unroll
                for (int nt = 0; nt < 8; ++nt) {
                    float ox = acc_o[nt][2*rr]   * inv;
                    float oy = acc_o[nt][2*rr+1] * inv;
                    float2 o = make_float2(ox, oy);
                    *(float2*)(Xo + off + nt * 8) = o;
                    __nv_bfloat162 hb = __floats2bfloat162_rn(ox, oy);
                    __nv_bfloat162 lb = __floats2bfloat162_rn(
                        ox - __bfloat162float(hb.x), oy - __bfloat162float(hb.y));
                    *(__nv_bfloat162*)(Xhi + off + nt * 8) = hb;
                    *(__nv_bfloat162*)(Xlo + off + nt * 8) = lb;
                }
            }
        }
    }
}

// ============================================================================
// attn_tail: query row s = 256; also writes xhi/xlo
// ============================================================================
#define TAIL_SMEM ((257 * 65 + 64 + 257 + 256 + 4 * 64) * 4)
__global__ __launch_bounds__(256) void attn_tail(
    const __nv_bfloat16* __restrict__ qhi, const __nv_bfloat16* __restrict__ qlo,
    const __nv_bfloat16* __restrict__ khi, const __nv_bfloat16* __restrict__ klo,
    const __nv_bfloat16* __restrict__ vhi, const __nv_bfloat16* __restrict__ vlo,
    float* __restrict__ Xo,
    __nv_bfloat16* __restrict__ Xhi, __nv_bfloat16* __restrict__ Xlo, int bh0)
{
    extern __shared__ float fs[];
    float* ks  = fs;
    float* q   = ks + 257 * 65;
    float* p   = q + 64;
    float* red = p + 257;
    float* vp  = red + 256;
    const int t = threadIdx.x;
    const int bh = bh0 + blockIdx.x, b = bh >> 4, h = bh & 15;
    const size_t base = (size_t)b * S_ * D_ + h * HD_;

    if (t < 64) {
        size_t o = base + (size_t)256 * D_ + t;
        q[t] = __bfloat162float(qhi[o]) + __bfloat162float(qlo[o]);
    }
    for (int i = t; i < 257 * 64; i += 256) {
        int row = i >> 6, d = i & 63;
        size_t o = base + (size_t)row * D_ + d;
        ks[row * 65 + d] = __bfloat162float(khi[o]) + __bfloat162float(klo[o]);
    }
    __syncthreads();

    float v0 = 0.f, v1 = -1e30f;
    {
        const float* kr = ks + t * 65;
        #pragma unroll 8
        for (int d = 0; d < 64; ++d) v0 = fmaf(q[d], kr[d], v0);
    }
    if (t == 0) {
        v1 = 0.f;
        const float* kr = ks + 256 * 65;
        #pragma unroll 8
        for (int d = 0; d < 64; ++d) v1 = fmaf(q[d], kr[d], v1);
    }

    red[t] = fmaxf(v0, v1);
    __syncthreads();
    #pragma unroll
    for (int o = 128; o; o >>= 1) {
        if (t < o) red[t] = fmaxf(red[t], red[t + o]);
        __syncthreads();
    }
    float rmax = red[0];
    __syncthreads();
    float e0 = fexp(v0 - rmax);
    float e1 = (t == 0) ? fexp(v1 - rmax) : 0.f;
    red[t] = e0 + e1;
    __syncthreads();
    #pragma unroll
    for (int o = 128; o; o >>= 1) {
        if (t < o) red[t] += red[t + o];
        __syncthreads();
    }
    float inv = 1.f / red[0];
    p[t] = e0 * inv;
    if (t == 0) p[256] = e1 * inv;
    __syncthreads();

    {
        int d = t & 63, grp = t >> 6;
        float acc = 0.f;
        for (int tt = grp; tt < S_; tt += 4) {
            size_t off = base + (size_t)tt * D_ + d;
            acc = fmaf(p[tt], __bfloat162float(vhi[off]) + __bfloat162float(vlo[off]), acc);
        }
        vp[grp * 64 + d] = acc;
    }
    __syncthreads();
    if (t < 64) {
        float o = vp[t] + vp[64 + t] + vp[128 + t] + vp[192 + t];
        size_t off = ((size_t)b * S_ + 256) * D_ + h * HD_ + t;
        Xo[off] = o;
        __nv_bfloat16 hb = __float2bfloat16(o);
        Xhi[off] = hb;
        Xlo[off] = __float2bfloat16(o - __bfloat162float(hb));
    }
}

// ============================================================================
// xa: grid (BH, KE, 16*nproj); batch offset b0
// ============================================================================
__global__ __launch_bounds__(256) void xa_kernel(
    const float* __restrict__ X,
    const float* __restrict__ A0, const float* __restrict__ A1,
    const float* __restrict__ A2,
    const int* __restrict__ idx, float* __restrict__ xa, int b0)
{
    int b = b0 + blockIdx.x, slot = blockIdx.y;
    int proj = blockIdx.z >> 4, zz = blockIdx.z & 15;
    int rh = zz >> 3, sc = zz & 7;
    const float* A = (proj == 0) ? A0 : (proj == 1) ? A1 : A2;
    float* xad = xa + (size_t)proj * B_ * KE_ * S_ * R_;
    int sbase = sc * 33;
    int smax = min(S_, sbase + 33);
    int e = idx[b * KE_ + slot];
    __shared__ float As[8][D_];
    const float* Ap = A + ((size_t)e * R_ + rh * 8) * D_;
    for (int i = threadIdx.x; i < 8 * D_ / 4; i += 256)
        ((float4*)As)[i] = ((const float4*)Ap)[i];
    __syncthreads();

    int w = threadIdx.x >> 5, lane = threadIdx.x & 31;
    for (int s4 = sbase + w * 4; s4 < smax; s4 += 32) {
        float sum[8][4];
        #pragma unroll
        for (int r = 0; r < 8; r++)
            #pragma unroll
            for (int si = 0; si < 4; si++) sum[r][si] = 0.f;

        #pragma unroll 1
        for (int c = 0; c < 8; c++) {
            float4 xv[4];
            #pragma unroll
            for (int si = 0; si < 4; si++) {
                int s = s4 + si;
                xv[si] = (s < S_)
                    ? *(const float4*)(X + ((size_t)b * S_ + s) * D_ + c * 128 + lane * 4)
                    : make_float4(0.f, 0.f, 0.f, 0.f);
            }
            #pragma unroll
            for (int r = 0; r < 8; r++) {
                float4 av = *(const float4*)&As[r][c * 128 + lane * 4];
                #pragma unroll
                for (int si = 0; si < 4; si++)
                    sum[r][si] = fmaf(xv[si].x, av.x,
                                 fmaf(xv[si].y, av.y,
                                 fmaf(xv[si].z, av.z,
                                 fmaf(xv[si].w, av.w, sum[r][si]))));
            }
        }
        #pragma unroll
        for (int r = 0; r < 8; r++)
            #pragma unroll
            for (int si = 0; si < 4; si++) {
                float v = sum[r][si];
                #pragma unroll
                for (int o = 16; o; o >>= 1) v += __shfl_xor_sync(0xffffffffu, v, o);
                int s = s4 + si;
                if (lane == 0 && s < S_)
                    xad[(((size_t)b * KE_ + slot) * S_ + s) * R_ + rh * 8 + r] = v;
            }
    }
}

// ============================================================================
// lora_add / lora_split3
// ============================================================================
__global__ __launch_bounds__(256) void lora_add(
    const float* __restrict__ Bm, const int* __restrict__ idx,
    const float* __restrict__ gates, const float* __restrict__ xa,
    float* __restrict__ Y, float scale, int b0)
{
    int b = b0 + blockIdx.x;
    int cn = blockIdx.y << 6;
    int t = threadIdx.x;
    __shared__ float Bs[2][64][17];
    __shared__ float xs[2][64][17];
    int e0 = idx[b * KE_], e1 = idx[b * KE_ + 1];
    float g0 = gates[b * KE_] * scale, g1 = gates[b * KE_ + 1] * scale;

    for (int i = t; i < 2048; i += 256) {
        int slot = i >> 10, rem = i & 1023, c = rem >> 4, r = rem & 15;
        Bs[slot][c][r] = Bm[((size_t)(slot ? e1 : e0) * D_ + cn + c) * R_ + r];
    }

    int c = t & 63, sq = t >> 6;
    for (int s0 = 0; s0 < S_; s0 += 64) {
        __syncthreads();
        for (int i = t; i < 2048; i += 256) {
            int slot = i >> 10, rem = i & 1023, si = rem >> 4, r = rem & 15;
            int s = s0 + si;
            float v = (s < S_) ? xa[(((size_t)b * KE_ + slot) * S_ + s) * R_ + r] : 0.f;
            xs[slot][si][r] = v * (slot ? g1 : g0);
        }
        __syncthreads();
        for (int si = sq; si < 64; si += 4) {
            int s = s0 + si;
            if (s >= S_) break;
            float sum = 0.f;
            #pragma unroll
            for (int r = 0; r < 16; r++) {
                sum = fmaf(xs[0][si][r], Bs[0][c][r], sum);
                sum = fmaf(xs[1][si][r], Bs[1][c][r], sum);
            }
            Y[((size_t)b * S_ + s) * D_ + cn + c] += sum;
        }
    }
}

__global__ __launch_bounds__(256) void lora_split3(
    const float* __restrict__ Bq, const float* __restrict__ Bk,
    const float* __restrict__ Bv,
    const int* __restrict__ idx, const float* __restrict__ gates,
    const float* __restrict__ xa, const float* __restrict__ Yin,
    __nv_bfloat16* __restrict__ qhi, __nv_bfloat16* __restrict__ qlo,
    __nv_bfloat16* __restrict__ khi, __nv_bfloat16* __restrict__ klo,
    __nv_bfloat16* __restrict__ vhi, __nv_bfloat16* __restrict__ vlo, int b0)
{
    const int z = blockIdx.z;
    const float* Bm = (z == 0) ? Bq : (z == 1) ? Bk : Bv;
    const float* Yz = Yin + (size_t)z * MTOT * D_;
    const float* xaz = xa + (size_t)z * B_ * KE_ * S_ * R_;
    __nv_bfloat16* Yhi = (z == 0) ? qhi : (z == 1) ? khi : vhi;
    __nv_bfloat16* Ylo = (z == 0) ? qlo : (z == 1) ? klo : vlo;
    const float scale = (z == 0) ? SCALE_Q : 1.f;

    int b = b0 + blockIdx.x;
    int cn = blockIdx.y << 6;
    int t = threadIdx.x;
    __shared__ float Bs[2][64][17];
    __shared__ float xs[2][64][17];
    int e0 = idx[b * KE_], e1 = idx[b * KE_ + 1];
    float g0 = gates[b * KE_] * scale, g1 = gates[b * KE_ + 1] * scale;

    for (int i = t; i < 2048; i += 256) {
        int slot = i >> 10, rem = i & 1023, c = rem >> 4, r = rem & 15;
        Bs[slot][c][r] = Bm[((size_t)(slot ? e1 : e0) * D_ + cn + c) * R_ + r];
    }

    int c = t & 63, sq = t >> 6;
    for (int s0 = 0; s0 < S_; s0 += 64) {
        __syncthreads();
        for (int i = t; i < 2048; i += 256) {
            int slot = i >> 10, rem = i & 1023, si = rem >> 4, r = rem & 15;
            int s = s0 + si;
            float v = (s < S_) ? xaz[(((size_t)b * KE_ + slot) * S_ + s) * R_ + r] : 0.f;
            xs[slot][si][r] = v * (slot ? g1 : g0);
        }
        __syncthreads();
        for (int si = sq; si < 64; si += 4) {
            int s = s0 + si;
            if (s >= S_) break;
            float sum = 0.f;
            #pragma unroll
            for (int r = 0; r < 16; r++) {
                sum = fmaf(xs[0][si][r], Bs[0][c][r], sum);
                sum = fmaf(xs[1][si][r], Bs[1][c][r], sum);
            }
            size_t off = ((size_t)b * S_ + s) * D_ + cn + c;
            float v = Yz[off] + sum;
            __nv_bfloat16 hb = __float2bfloat16(v);
            Yhi[off] = hb;
            Ylo[off] = __float2bfloat16(v - __bfloat162float(hb));
        }
    }
}

// ---------------- host launcher --------------------------------------------
extern "C" void kernel_launch(void* const* d_in, const int* in_sizes, int n_in,
                              void* d_out, int out_size)
{
    const float* hs    = (const float*)d_in[0];
    const int*   idx   = (const int*)  d_in[1];
    const float* gates = (const float*)d_in[2];
    const float* wq = (const float*)d_in[3];  const float* Aq = (const float*)d_in[4];
    const float* Bq = (const float*)d_in[5];  const float* bq = (const float*)d_in[6];
    const float* wk = (const float*)d_in[7];  const float* Ak = (const float*)d_in[8];
    const float* Bk = (const float*)d_in[9];  const float* bk = (const float*)d_in[10];
    const float* wv = (const float*)d_in[11]; const float* Av = (const float*)d_in[12];
    const float* Bv = (const float*)d_in[13]; const float* bv = (const float*)d_in[14];
    const float* wo = (const float*)d_in[15]; const float* Ao = (const float*)d_in[16];
    const float* Bo = (const float*)d_in[17]; const float* bo = (const float*)d_in[18];
    float* out = (float*)d_out;

    float *tmp, *x2, *xa;
    __nv_bfloat16 *xhi, *xlo, *whi, *wlo, *qhi, *qlo, *khi, *klo, *vhi, *vlo;
    cudaGetSymbolAddress((void**)&tmp, g_tmp);
    cudaGetSymbolAddress((void**)&x2,  g_x2);
    cudaGetSymbolAddress((void**)&xa,  g_xa);
    cudaGetSymbolAddress((void**)&xhi, g_xhi);
    cudaGetSymbolAddress((void**)&xlo, g_xlo);
    cudaGetSymbolAddress((void**)&whi, g_whi);
    cudaGetSymbolAddress((void**)&wlo, g_wlo);
    cudaGetSymbolAddress((void**)&qhi, g_qhi);
    cudaGetSymbolAddress((void**)&qlo, g_qlo);
    cudaGetSymbolAddress((void**)&khi, g_khi);
    cudaGetSymbolAddress((void**)&klo, g_klo);
    cudaGetSymbolAddress((void**)&vhi, g_vhi);
    cudaGetSymbolAddress((void**)&vlo, g_vlo);

    cudaFuncSetAttribute(mma_gemm_qkv, cudaFuncAttributeMaxDynamicSharedMemorySize, GEMM_SMEM);
    cudaFuncSetAttribute(mma_gemm, cudaFuncAttributeMaxDynamicSharedMemorySize, GEMM_SMEM);
    cudaFuncSetAttribute(flash_attn, cudaFuncAttributeMaxDynamicSharedMemorySize, FA_SMEM);
    cudaFuncSetAttribute(attn_tail, cudaFuncAttributeMaxDynamicSharedMemorySize, TAIL_SMEM);

    static cudaStream_t s1 = nullptr, s2 = nullptr, s3 = nullptr;
    static cudaEvent_t evR, evW, evXA[2], evL[2], evT[2], evF[2], evXO[2], evEnd;
    if (!s1) {
        cudaStreamCreateWithFlags(&s1, cudaStreamNonBlocking);
        cudaStreamCreateWithFlags(&s2, cudaStreamNonBlocking);
        cudaStreamCreateWithFlags(&s3, cudaStreamNonBlocking);
        cudaEventCreateWithFlags(&evR, cudaEventDisableTiming);
        cudaEventCreateWithFlags(&evW, cudaEventDisableTiming);
        for (int i = 0; i < 2; ++i) {
            cudaEventCreateWithFlags(&evXA[i], cudaEventDisableTiming);
            cudaEventCreateWithFlags(&evL[i], cudaEventDisableTiming);
            cudaEventCreateWithFlags(&evT[i], cudaEventDisableTiming);
            cudaEventCreateWithFlags(&evF[i], cudaEventDisableTiming);
            cudaEventCreateWithFlags(&evXO[i], cudaEventDisableTiming);
        }
        cudaEventCreateWithFlags(&evEnd, cudaEventDisableTiming);
    }

    const int nw4 = D_ * D_ / 4;
    const int nh4 = MH_ * D_ / 4;
    cudaStream_t ws[2] = {s2, s3};

    // ---- initial forks: W split on s2; per-half xa(qkv) on own worker ----
    cudaEventRecord(evR, 0);
    cudaStreamWaitEvent(s1, evR, 0);
    cudaStreamWaitEvent(s2, evR, 0);
    cudaStreamWaitEvent(s3, evR, 0);
    split_w4<<<dim3((nw4 + 255) / 256, 4), 256, 0, s2>>>(
        (const float4*)wq, (const float4*)wk, (const float4*)wv, (const float4*)wo,
        (uint2*)whi, (uint2*)wlo);
    cudaEventRecord(evW, s2);
    xa_kernel<<<dim3(BH_, KE_, 48), 256, 0, s2>>>(hs, Aq, Ak, Av, idx, xa, 0);
    cudaEventRecord(evXA[0], s2);
    xa_kernel<<<dim3(BH_, KE_, 48), 256, 0, s3>>>(hs, Aq, Ak, Av, idx, xa, BH_);
    cudaEventRecord(evXA[1], s3);

    // ---- per-half pipelines on stream 0 (half 0) and s1 (half 1) ----
    for (int h = 0; h < 2; ++h) {
        cudaStream_t st = h ? s1 : 0;
        cudaStream_t wk2 = ws[h];
        const int b0 = h * BH_;
        const int m0 = h * MH_;
        const int mmax = m0 + MH_;
        const int bh0 = b0 * H_;

        split_bf16<<<(nh4 + 255) / 256, 256, 0, st>>>(
            (const float4*)(hs + (size_t)m0 * D_),
            (uint2*)(xhi + (size_t)m0 * D_), (uint2*)(xlo + (size_t)m0 * D_), nh4);

        cudaStreamWaitEvent(st, evW, 0);
        mma_gemm_qkv<<<dim3(8, 33, 3), 256, GEMM_SMEM, st>>>(
            xhi, xlo, whi, wlo, bq, bk, bv, tmp, m0, mmax);

        cudaStreamWaitEvent(st, evXA[h], 0);
        lora_split3<<<dim3(BH_, 16, 3), 256, 0, st>>>(
            Bq, Bk, Bv, idx, gates, xa, tmp, qhi, qlo, khi, klo, vhi, vlo, b0);

        // fork: attn_tail on worker concurrent with flash_attn
        cudaEventRecord(evL[h], st);
        cudaStreamWaitEvent(wk2, evL[h], 0);
        attn_tail<<<BH_ * H_, 256, TAIL_SMEM, wk2>>>(
            qhi, qlo, khi, klo, vhi, vlo, x2, xhi, xlo, bh0);
        cudaEventRecord(evT[h], wk2);

        flash_attn<<<dim3(BH_ * H_, 4), 128, FA_SMEM, st>>>(
            qhi, qlo, khi, klo, vhi, vlo, x2, xhi, xlo, bh0);
        cudaStreamWaitEvent(st, evT[h], 0);

        // fork: xa(O) on worker concurrent with O GEMM
        cudaEventRecord(evF[h], st);
        cudaStreamWaitEvent(wk2, evF[h], 0);
        xa_kernel<<<dim3(BH_, KE_, 16), 256, 0, wk2>>>(x2, Ao, Ao, Ao, idx, xa, b0);
        cudaEventRecord(evXO[h], wk2);

        mma_gemm<<<dim3(8, 33), 256, GEMM_SMEM, st>>>(
            xhi, xlo, whi + (size_t)3 * D_ * D_, wlo + (size_t)3 * D_ * D_,
            bo, out, 1.f, m0, mmax);

        cudaStreamWaitEvent(st, evXO[h], 0);
        lora_add<<<dim3(BH_, 16), 256, 0, st>>>(Bo, idx, gates, xa, out, 1.f, b0);
    }

    cudaEventRecord(evEnd, s1);
    cudaStreamWaitEvent(0, evEnd, 0);
}

// round 16
// speedup vs baseline: 1.1259x; 1.0146x over previous
#include <cuda_runtime.h>
#include <cuda_bf16.h>
#include <cstdint>

#define B_ 32
#define S_ 257
#define D_ 1024
#define H_ 16
#define HD_ 64
#define E_ 8
#define R_ 16
#define KE_ 2
#define MTOT (B_*S_)
#define BH_ 16
#define MH_ (BH_*S_)
#define SCALE_Q 0.125f

// ---------------- scratch (device globals: allocation-free) ----------------
__device__ float g_tmp[(size_t)3 * MTOT * D_];
__device__ float g_x2 [(size_t)MTOT * D_];
__device__ float g_xa [(size_t)3 * B_ * KE_ * S_ * R_];
__device__ __nv_bfloat16 g_xhi[(size_t)MTOT * D_];
__device__ __nv_bfloat16 g_xlo[(size_t)MTOT * D_];
__device__ __nv_bfloat16 g_whi[(size_t)4 * D_ * D_];
__device__ __nv_bfloat16 g_wlo[(size_t)4 * D_ * D_];
__device__ __nv_bfloat16 g_qhi[(size_t)MTOT * D_];
__device__ __nv_bfloat16 g_qlo[(size_t)MTOT * D_];
__device__ __nv_bfloat16 g_khi[(size_t)MTOT * D_];
__device__ __nv_bfloat16 g_klo[(size_t)MTOT * D_];
__device__ __nv_bfloat16 g_vhi[(size_t)MTOT * D_];
__device__ __nv_bfloat16 g_vlo[(size_t)MTOT * D_];

// ========================= helpers ==========================================
__device__ __forceinline__ uint32_t smem_u32(const void* p) {
    uint32_t a;
    asm("{ .reg .u64 t; cvta.to.shared.u64 t, %1; cvt.u32.u64 %0, t; }"
        : "=r"(a) : "l"(p));
    return a;
}

#define LDSM4(r0, r1, r2, r3, addr) \
    asm volatile("ldmatrix.sync.aligned.m8n8.x4.shared.b16 {%0,%1,%2,%3}, [%4];" \
        : "=r"(r0), "=r"(r1), "=r"(r2), "=r"(r3) : "r"(addr))

#define LDSM4T(r0, r1, r2, r3, addr) \
    asm volatile("ldmatrix.sync.aligned.m8n8.x4.trans.shared.b16 {%0,%1,%2,%3}, [%4];" \
        : "=r"(r0), "=r"(r1), "=r"(r2), "=r"(r3) : "r"(addr))

// non-volatile: lets ptxas interleave/pipeline MMAs with LDSMs
#define MMA16816(d, a, b0, b1) \
    asm("mma.sync.aligned.m16n8k16.row.col.f32.bf16.bf16.f32 " \
        "{%0,%1,%2,%3}, {%4,%5,%6,%7}, {%8,%9}, {%0,%1,%2,%3};" \
        : "+f"((d)[0]), "+f"((d)[1]), "+f"((d)[2]), "+f"((d)[3]) \
        : "r"((a)[0]), "r"((a)[1]), "r"((a)[2]), "r"((a)[3]), "r"(b0), "r"(b1))

#define CP_ASYNC16(dst, src, sz) \
    asm volatile("cp.async.cg.shared.global [%0], [%1], 16, %2;" \
        :: "r"(dst), "l"(src), "r"(sz))
#define CP_COMMIT()  asm volatile("cp.async.commit_group;" ::: "memory")
#define CP_WAIT0()   asm volatile("cp.async.wait_group 0;" ::: "memory")

__device__ __forceinline__ float fexp(float x) {
    x = fmaxf(x, -80.f);
    float t = x * 1.4426950408889634f;
    float z = t + 12582912.f;
    int   k = __float_as_int(z) - 0x4B400000;
    float f = t - (z - 12582912.f);
    float p = 1.3333558146428443e-3f;
    p = fmaf(p, f, 9.6181291076284772e-3f);
    p = fmaf(p, f, 5.5504108664821580e-2f);
    p = fmaf(p, f, 2.4022650695910071e-1f);
    p = fmaf(p, f, 6.9314718055994531e-1f);
    p = fmaf(p, f, 1.0f);
    return __int_as_float(__float_as_int(p) + (k << 23));
}

// ============================================================================
// split fp32 -> (bf16 hi, bf16 lo)
// ============================================================================
__device__ __forceinline__ void split_one(
    const float4* __restrict__ x, uint2* __restrict__ hi, uint2* __restrict__ lo, int i)
{
    float4 v = x[i];
    __nv_bfloat162 h01 = __floats2bfloat162_rn(v.x, v.y);
    __nv_bfloat162 h23 = __floats2bfloat162_rn(v.z, v.w);
    float lx = v.x - __bfloat162float(h01.x);
    float ly = v.y - __bfloat162float(h01.y);
    float lz = v.z - __bfloat162float(h23.x);
    float lw = v.w - __bfloat162float(h23.y);
    __nv_bfloat162 l01 = __floats2bfloat162_rn(lx, ly);
    __nv_bfloat162 l23 = __floats2bfloat162_rn(lz, lw);
    uint2 hv, lv;
    hv.x = *(uint32_t*)&h01; hv.y = *(uint32_t*)&h23;
    lv.x = *(uint32_t*)&l01; lv.y = *(uint32_t*)&l23;
    hi[i] = hv; lo[i] = lv;
}

__global__ __launch_bounds__(256) void split_bf16(
    const float4* __restrict__ x, uint2* __restrict__ hi, uint2* __restrict__ lo, int n4)
{
    int i = blockIdx.x * 256 + threadIdx.x;
    if (i < n4) split_one(x, hi, lo, i);
}

__global__ __launch_bounds__(256) void split_w3(
    const float4* __restrict__ w0, const float4* __restrict__ w1,
    const float4* __restrict__ w2,
    uint2* __restrict__ hi, uint2* __restrict__ lo)
{
    const int n4 = D_ * D_ / 4;
    int i = blockIdx.x * 256 + threadIdx.x;
    if (i >= n4) return;
    int z = blockIdx.y;
    const float4* src = (z == 0) ? w0 : (z == 1) ? w1 : w2;
    split_one(src, hi + (size_t)z * n4, lo + (size_t)z * n4, i);
}

// ============================================================================
// HMMA GEMM via bf16x3 split — 128x128 block tile, 8 warps (64x32), occ 2
// ============================================================================
#define APITCH 80
#define TILEB (128 * APITCH)
#define STAGEB (4 * TILEB)
#define GEMM_SMEM (2 * STAGEB)

__device__ __forceinline__ void stage_load(
    uint32_t sb, int buf, int c, int tm, int tn, int tid, int mmax,
    const __nv_bfloat16* __restrict__ Xhi, const __nv_bfloat16* __restrict__ Xlo,
    const __nv_bfloat16* __restrict__ Whi, const __nv_bfloat16* __restrict__ Wlo)
{
    uint32_t st = sb + buf * STAGEB;
    #pragma unroll
    for (int j = 0; j < 8; ++j) {
        int g = tid + j * 256;
        int tile = g >> 9, i = g & 511, row = i >> 2, seg = i & 3;
        const __nv_bfloat16* base = (tile == 0) ? Xhi : (tile == 1) ? Xlo
                                   : (tile == 2) ? Whi : Wlo;
        int grow = ((tile < 2) ? tm : tn) + row;
        const void* src = base + (size_t)grow * D_ + c * 32 + seg * 8;
        uint32_t dst = st + tile * TILEB + row * APITCH + seg * 16;
        int sz = (tile >= 2 || grow < mmax) ? 16 : 0;
        CP_ASYNC16(dst, src, sz);
    }
}

__device__ __forceinline__ void gemm_body(
    const __nv_bfloat16* __restrict__ Xhi, const __nv_bfloat16* __restrict__ Xlo,
    const __nv_bfloat16* __restrict__ Whi, const __nv_bfloat16* __restrict__ Wlo,
    const float* __restrict__ bias, float* __restrict__ Y, float scale,
    int m0g, int mmax)
{
    extern __shared__ char smem[];
    const uint32_t sb = smem_u32(smem);
    const int tid = threadIdx.x;
    const int wid = tid >> 5, lane = tid & 31;
    const int tm = m0g + (blockIdx.y << 7), tn = blockIdx.x << 7;
    const int wm = (wid & 1) * 64, wn = (wid >> 1) * 32;

    const int lrow = lane & 15;
    const int lk   = lane >> 4;
    const int brow = ((lane >> 4) << 3) + (lane & 7);
    const int bk   = (lane >> 3) & 1;

    float acc[4][4][4] = {};

    stage_load(sb, 0, 0, tm, tn, tid, mmax, Xhi, Xlo, Whi, Wlo);
    CP_COMMIT();

    for (int c = 0; c < 32; ++c) {
        const int buf = c & 1;
        CP_WAIT0();
        __syncthreads();
        if (c + 1 < 32) {
            stage_load(sb, buf ^ 1, c + 1, tm, tn, tid, mmax, Xhi, Xlo, Whi, Wlo);
            CP_COMMIT();
        }

        const uint32_t Ah = sb + buf * STAGEB;
        const uint32_t Al = Ah + TILEB;
        const uint32_t Bh = Ah + 2 * TILEB;
        const uint32_t Bl = Ah + 3 * TILEB;

        #pragma unroll
        for (int kk2 = 0; kk2 < 2; ++kk2) {
            const int kkb = kk2 * 32;
            uint32_t fa[4][4], fb[2][4], fc[2][4];
            const uint32_t aoff = (uint32_t)(wm + lrow) * APITCH + kkb + lk * 16;
            const uint32_t boff = (uint32_t)(wn + brow) * APITCH + kkb + bk * 16;
            #pragma unroll
            for (int mt = 0; mt < 4; ++mt)
                LDSM4(fa[mt][0], fa[mt][1], fa[mt][2], fa[mt][3],
                      Ah + aoff + mt * (16 * APITCH));
            #pragma unroll
            for (int p = 0; p < 2; ++p) {
                LDSM4(fb[p][0], fb[p][1], fb[p][2], fb[p][3],
                      Bh + boff + p * (16 * APITCH));
                LDSM4(fc[p][0], fc[p][1], fc[p][2], fc[p][3],
                      Bl + boff + p * (16 * APITCH));
            }
            #pragma unroll
            for (int mt = 0; mt < 4; ++mt)
                #pragma unroll
                for (int nt = 0; nt < 4; ++nt) {
                    const int p = nt >> 1, h = (nt & 1) * 2;
                    MMA16816(acc[mt][nt], fa[mt], fb[p][h], fb[p][h + 1]);
                }
            #pragma unroll
            for (int mt = 0; mt < 4; ++mt)
                #pragma unroll
                for (int nt = 0; nt < 4; ++nt) {
                    const int p = nt >> 1, h = (nt & 1) * 2;
                    MMA16816(acc[mt][nt], fa[mt], fc[p][h], fc[p][h + 1]);
                }
            #pragma unroll
            for (int mt = 0; mt < 4; ++mt)
                LDSM4(fa[mt][0], fa[mt][1], fa[mt][2], fa[mt][3],
                      Al + aoff + mt * (16 * APITCH));
            #pragma unroll
            for (int mt = 0; mt < 4; ++mt)
                #pragma unroll
                for (int nt = 0; nt < 4; ++nt) {
                    const int p = nt >> 1, h = (nt & 1) * 2;
                    MMA16816(acc[mt][nt], fa[mt], fb[p][h], fb[p][h + 1]);
                }
        }
        __syncthreads();
    }

    const int erow = lane >> 2, ecol = (lane & 3) * 2;
    #pragma unroll
    for (int mt = 0; mt < 4; ++mt) {
        #pragma unroll
        for (int nt = 0; nt < 4; ++nt) {
            int m0 = tm + wm + mt * 16 + erow;
            int n0 = tn + wn + nt * 8 + ecol;
            float bx = bias[n0], by = bias[n0 + 1];
            if (m0 < mmax) {
                float2 o;
                o.x = (acc[mt][nt][0] + bx) * scale;
                o.y = (acc[mt][nt][1] + by) * scale;
                *(float2*)(Y + (size_t)m0 * D_ + n0) = o;
            }
            if (m0 + 8 < mmax) {
                float2 o;
                o.x = (acc[mt][nt][2] + bx) * scale;
                o.y = (acc[mt][nt][3] + by) * scale;
                *(float2*)(Y + (size_t)(m0 + 8) * D_ + n0) = o;
            }
        }
    }
}

__global__ __launch_bounds__(256, 2) void mma_gemm_qkv(
    const __nv_bfloat16* __restrict__ Xhi, const __nv_bfloat16* __restrict__ Xlo,
    const __nv_bfloat16* __restrict__ Whi, const __nv_bfloat16* __restrict__ Wlo,
    const float* __restrict__ bq, const float* __restrict__ bk,
    const float* __restrict__ bv, float* __restrict__ Y, int m0g, int mmax)
{
    const int z = blockIdx.z;
    const size_t wo = (size_t)z * D_ * D_;
    const float* bias = (z == 0) ? bq : (z == 1) ? bk : bv;
    gemm_body(Xhi, Xlo, Whi + wo, Wlo + wo, bias,
              Y + (size_t)z * MTOT * D_, (z == 0) ? SCALE_Q : 1.f, m0g, mmax);
}

__global__ __launch_bounds__(256, 2) void mma_gemm(
    const __nv_bfloat16* __restrict__ Xhi, const __nv_bfloat16* __restrict__ Xlo,
    const __nv_bfloat16* __restrict__ Whi, const __nv_bfloat16* __restrict__ Wlo,
    const float* __restrict__ bias, float* __restrict__ Y, float scale,
    int m0g, int mmax)
{
    gemm_body(Xhi, Xlo, Whi, Wlo, bias, Y, scale, m0g, mmax);
}

// ============================================================================
// Fused flash attention: 64-row Q tiles, 128 threads.
// kv tiles 0..3 cover t<256; t=256 column folded analytically in fp32.
// ============================================================================
#define FPITCH 144
#define KVROWB (64 * FPITCH)
#define KVSTG  (4 * KVROWB)
#define FA_SMEM (2 * KVSTG + 512)

__device__ __forceinline__ void load_kv(
    uint32_t st, int t0, size_t kvbase, int tid,
    const __nv_bfloat16* __restrict__ khi, const __nv_bfloat16* __restrict__ klo,
    const __nv_bfloat16* __restrict__ vhi, const __nv_bfloat16* __restrict__ vlo)
{
    #pragma unroll
    for (int j = 0; j < 16; ++j) {
        int g = tid + j * 128;
        int tens = g >> 9, i = g & 511, row = i >> 3, seg = i & 7;
        const __nv_bfloat16* bp = (tens == 0) ? khi : (tens == 1) ? klo
                                 : (tens == 2) ? vhi : vlo;
        const void* src = bp + kvbase + (size_t)(t0 + row) * D_ + seg * 8;
        uint32_t dst = st + tens * KVROWB + row * FPITCH + seg * 16;
        CP_ASYNC16(dst, src, 16);
    }
}

__global__ __launch_bounds__(128) void flash_attn(
    const __nv_bfloat16* __restrict__ qhi, const __nv_bfloat16* __restrict__ qlo,
    const __nv_bfloat16* __restrict__ khi, const __nv_bfloat16* __restrict__ klo,
    const __nv_bfloat16* __restrict__ vhi, const __nv_bfloat16* __restrict__ vlo,
    float* __restrict__ Xo,
    __nv_bfloat16* __restrict__ Xhi, __nv_bfloat16* __restrict__ Xlo, int bh0)
{
    extern __shared__ char smem[];
    const uint32_t sb = smem_u32(smem);
    float* k256f = (float*)(smem + 2 * KVSTG);
    float* v256f = k256f + 64;
    const int tid = threadIdx.x, wid = tid >> 5, lane = tid & 31;
    const int bh = bh0 + blockIdx.x, b = bh >> 4, h = bh & 15;
    const int m0 = blockIdx.y * 64;
    const size_t kvbase = (size_t)b * S_ * D_ + h * HD_;

    #pragma unroll
    for (int j = 0; j < 8; ++j) {
        int g = tid + j * 128;
        int half = g >> 9, i = g & 511, row = i >> 3, seg = i & 7;
        const __nv_bfloat16* src = (half ? qlo : qhi) + kvbase
                                 + (size_t)(m0 + row) * D_ + seg * 8;
        uint32_t dst = sb + half * KVSTG + row * FPITCH + seg * 16;
        CP_ASYNC16(dst, src, (m0 + row) < S_ ? 16 : 0);
    }
    // stage k256/v256 as fp32
    if (tid < 64) {
        size_t o = kvbase + (size_t)256 * D_ + tid;
        k256f[tid] = __bfloat162float(khi[o]) + __bfloat162float(klo[o]);
        v256f[tid] = __bfloat162float(vhi[o]) + __bfloat162float(vlo[o]);
    }
    CP_COMMIT(); CP_WAIT0();
    __syncthreads();

    uint32_t qh[4][4], ql[4][4];
    {
        const uint32_t base = sb + (uint32_t)(wid * 16 + (lane & 15)) * FPITCH
                            + (lane >> 4) * 16;
        #pragma unroll
        for (int kk = 0; kk < 4; ++kk) {
            LDSM4(qh[kk][0], qh[kk][1], qh[kk][2], qh[kk][3], base + kk * 32);
            LDSM4(ql[kk][0], ql[kk][1], ql[kk][2], ql[kk][3], base + KVSTG + kk * 32);
        }
    }
    __syncthreads();

    const int quad = lane & 3;

    // s256[rr] = q_row . k256 (fp32) using resident fragments
    float s256[2];
    #pragma unroll
    for (int rr = 0; rr < 2; ++rr) {
        float a = 0.f;
        #pragma unroll
        for (int kk = 0; kk < 4; ++kk) {
            int c0 = kk * 16 + quad * 2;
            __nv_bfloat162 hb = *(__nv_bfloat162*)&qh[kk][rr];
            __nv_bfloat162 lb = *(__nv_bfloat162*)&ql[kk][rr];
            a = fmaf(__bfloat162float(hb.x) + __bfloat162float(lb.x), k256f[c0], a);
            a = fmaf(__bfloat162float(hb.y) + __bfloat162float(lb.y), k256f[c0 + 1], a);
            hb = *(__nv_bfloat162*)&qh[kk][rr + 2];
            lb = *(__nv_bfloat162*)&ql[kk][rr + 2];
            a = fmaf(__bfloat162float(hb.x) + __bfloat162float(lb.x), k256f[c0 + 8], a);
            a = fmaf(__bfloat162float(hb.y) + __bfloat162float(lb.y), k256f[c0 + 9], a);
        }
        a += __shfl_xor_sync(0xffffffffu, a, 1);
        a += __shfl_xor_sync(0xffffffffu, a, 2);
        s256[rr] = a;
    }

    float acc_o[8][4] = {};
    float mrow[2] = {-1e30f, -1e30f}, lrow[2] = {0.f, 0.f};
    float p256[2] = {0.f, 0.f};
    const int brow = ((lane >> 4) << 3) + (lane & 7);
    const int bk   = (lane >> 3) & 1;

    load_kv(sb, 0, kvbase, tid, khi, klo, vhi, vlo);
    CP_COMMIT();

    #pragma unroll 1
    for (int kv = 0; kv < 4; ++kv) {
        CP_WAIT0();
        __syncthreads();
        const uint32_t Ks = sb + (kv & 1) * KVSTG;
        const uint32_t Vs = Ks + 2 * KVROWB;
        if (kv < 3) {
            load_kv(sb + ((kv + 1) & 1) * KVSTG, (kv + 1) * 64, kvbase, tid,
                    khi, klo, vhi, vlo);
            CP_COMMIT();
        }

        float s[8][4] = {};
        #pragma unroll
        for (int kk = 0; kk < 4; ++kk) {
            uint32_t kh[4][4], kl[4][4];
            #pragma unroll
            for (int p = 0; p < 4; ++p) {
                uint32_t ko = Ks + (uint32_t)(p * 16 + brow) * FPITCH + kk * 32 + bk * 16;
                LDSM4(kh[p][0], kh[p][1], kh[p][2], kh[p][3], ko);
                LDSM4(kl[p][0], kl[p][1], kl[p][2], kl[p][3], ko + KVROWB);
            }
            #pragma unroll
            for (int p = 0; p < 4; ++p) {
                MMA16816(s[2*p],   qh[kk], kh[p][0], kh[p][1]);
                MMA16816(s[2*p+1], qh[kk], kh[p][2], kh[p][3]);
                MMA16816(s[2*p],   qh[kk], kl[p][0], kl[p][1]);
                MMA16816(s[2*p+1], qh[kk], kl[p][2], kl[p][3]);
                MMA16816(s[2*p],   ql[kk], kh[p][0], kh[p][1]);
                MMA16816(s[2*p+1], ql[kk], kh[p][2], kh[p][3]);
            }
        }

        const bool last = (kv == 3);

        #pragma unroll
        for (int rr = 0; rr < 2; ++rr) {
            float mx = -1e30f;
            #pragma unroll
            for (int nt = 0; nt < 8; ++nt)
                mx = fmaxf(mx, fmaxf(s[nt][2*rr], s[nt][2*rr+1]));
            mx = fmaxf(mx, __shfl_xor_sync(0xffffffffu, mx, 1));
            mx = fmaxf(mx, __shfl_xor_sync(0xffffffffu, mx, 2));
            if (last) mx = fmaxf(mx, s256[rr]);
            float mnew = fmaxf(mrow[rr], mx);
            float alpha = fexp(mrow[rr] - mnew);
            mrow[rr] = mnew;
            float sum = 0.f;
            #pragma unroll
            for (int nt = 0; nt < 8; ++nt) {
                float p0 = fexp(s[nt][2*rr]   - mnew);
                float p1 = fexp(s[nt][2*rr+1] - mnew);
                s[nt][2*rr] = p0; s[nt][2*rr+1] = p1;
                sum += p0 + p1;
            }
            sum += __shfl_xor_sync(0xffffffffu, sum, 1);
            sum += __shfl_xor_sync(0xffffffffu, sum, 2);
            if (last) {
                p256[rr] = fexp(s256[rr] - mnew);
                sum += p256[rr];
            }
            lrow[rr] = lrow[rr] * alpha + sum;
            #pragma unroll
            for (int nt = 0; nt < 8; ++nt) {
                acc_o[nt][2*rr]   *= alpha;
                acc_o[nt][2*rr+1] *= alpha;
            }
        }

        #pragma unroll
        for (int kk = 0; kk < 4; ++kk) {
            uint32_t ph[4], pl[4];
            #pragma unroll
            for (int rg = 0; rg < 4; ++rg) {
                int nt = 2 * kk + (rg >> 1);
                float p0 = s[nt][(rg & 1) * 2];
                float p1 = s[nt][(rg & 1) * 2 + 1];
                __nv_bfloat162 hb = __floats2bfloat162_rn(p0, p1);
                float l0 = p0 - __bfloat162float(hb.x);
                float l1 = p1 - __bfloat162float(hb.y);
                __nv_bfloat162 lb = __floats2bfloat162_rn(l0, l1);
                ph[rg] = *(uint32_t*)&hb;
                pl[rg] = *(uint32_t*)&lb;
            }
            uint32_t vh[4][4], vl[4][4];
            #pragma unroll
            for (int p = 0; p < 4; ++p) {
                uint32_t vo = Vs + (uint32_t)(kk * 16 + (lane & 15)) * FPITCH
                            + p * 32 + (lane >> 4) * 16;
                LDSM4T(vh[p][0], vh[p][1], vh[p][2], vh[p][3], vo);
                LDSM4T(vl[p][0], vl[p][1], vl[p][2], vl[p][3], vo + KVROWB);
            }
            #pragma unroll
            for (int p = 0; p < 4; ++p) {
                MMA16816(acc_o[2*p],   ph, vh[p][0], vh[p][1]);
                MMA16816(acc_o[2*p+1], ph, vh[p][2], vh[p][3]);
                MMA16816(acc_o[2*p],   ph, vl[p][0], vl[p][1]);
                MMA16816(acc_o[2*p+1], ph, vl[p][2], vl[p][3]);
                MMA16816(acc_o[2*p],   pl, vh[p][0], vh[p][1]);
                MMA16816(acc_o[2*p+1], pl, vh[p][2], vh[p][3]);
            }
        }

        if (last) {
            #pragma unroll
            for (int rr = 0; rr < 2; ++rr)
                #pragma unroll
                for (int nt = 0; nt < 8; ++nt) {
                    int col = nt * 8 + quad * 2;
                    acc_o[nt][2*rr]   = fmaf(p256[rr], v256f[col],     acc_o[nt][2*rr]);
                    acc_o[nt][2*rr+1] = fmaf(p256[rr], v256f[col + 1], acc_o[nt][2*rr+1]);
                }
        }
    }

    {
        const int r = lane >> 2, q2 = quad * 2;
        #pragma unroll
        for (int rr = 0; rr < 2; ++rr) {
            int m = m0 + wid * 16 + r + rr * 8;
            if (m < S_) {
                float inv = 1.f / lrow[rr];
                size_t off = ((size_t)b * S_ + m) * D_ + h * HD_ + q2;
                #pragma unroll
                for (int nt = 0; nt < 8; ++nt) {
                    float ox = acc_o[nt][2*rr]   * inv;
                    float oy = acc_o[nt][2*rr+1] * inv;
                    float2 o = make_float2(ox, oy);
                    *(float2*)(Xo + off + nt * 8) = o;
                    __nv_bfloat162 hb = __floats2bfloat162_rn(ox, oy);
                    __nv_bfloat162 lb = __floats2bfloat162_rn(
                        ox - __bfloat162float(hb.x), oy - __bfloat162float(hb.y));
                    *(__nv_bfloat162*)(Xhi + off + nt * 8) = hb;
                    *(__nv_bfloat162*)(Xlo + off + nt * 8) = lb;
                }
            }
        }
    }
}

// ============================================================================
// attn_tail: query row s = 256; also writes xhi/xlo
// ============================================================================
#define TAIL_SMEM ((257 * 65 + 64 + 257 + 256 + 4 * 64) * 4)
__global__ __launch_bounds__(256) void attn_tail(
    const __nv_bfloat16* __restrict__ qhi, const __nv_bfloat16* __restrict__ qlo,
    const __nv_bfloat16* __restrict__ khi, const __nv_bfloat16* __restrict__ klo,
    const __nv_bfloat16* __restrict__ vhi, const __nv_bfloat16* __restrict__ vlo,
    float* __restrict__ Xo,
    __nv_bfloat16* __restrict__ Xhi, __nv_bfloat16* __restrict__ Xlo, int bh0)
{
    extern __shared__ float fs[];
    float* ks  = fs;
    float* q   = ks + 257 * 65;
    float* p   = q + 64;
    float* red = p + 257;
    float* vp  = red + 256;
    const int t = threadIdx.x;
    const int bh = bh0 + blockIdx.x, b = bh >> 4, h = bh & 15;
    const size_t base = (size_t)b * S_ * D_ + h * HD_;

    if (t < 64) {
        size_t o = base + (size_t)256 * D_ + t;
        q[t] = __bfloat162float(qhi[o]) + __bfloat162float(qlo[o]);
    }
    for (int i = t; i < 257 * 64; i += 256) {
        int row = i >> 6, d = i & 63;
        size_t o = base + (size_t)row * D_ + d;
        ks[row * 65 + d] = __bfloat162float(khi[o]) + __bfloat162float(klo[o]);
    }
    __syncthreads();

    float v0 = 0.f, v1 = -1e30f;
    {
        const float* kr = ks + t * 65;
        #pragma unroll 8
        for (int d = 0; d < 64; ++d) v0 = fmaf(q[d], kr[d], v0);
    }
    if (t == 0) {
        v1 = 0.f;
        const float* kr = ks + 256 * 65;
        #pragma unroll 8
        for (int d = 0; d < 64; ++d) v1 = fmaf(q[d], kr[d], v1);
    }

    red[t] = fmaxf(v0, v1);
    __syncthreads();
    #pragma unroll
    for (int o = 128; o; o >>= 1) {
        if (t < o) red[t] = fmaxf(red[t], red[t + o]);
        __syncthreads();
    }
    float rmax = red[0];
    __syncthreads();
    float e0 = fexp(v0 - rmax);
    float e1 = (t == 0) ? fexp(v1 - rmax) : 0.f;
    red[t] = e0 + e1;
    __syncthreads();
    #pragma unroll
    for (int o = 128; o; o >>= 1) {
        if (t < o) red[t] += red[t + o];
        __syncthreads();
    }
    float inv = 1.f / red[0];
    p[t] = e0 * inv;
    if (t == 0) p[256] = e1 * inv;
    __syncthreads();

    {
        int d = t & 63, grp = t >> 6;
        float acc = 0.f;
        for (int tt = grp; tt < S_; tt += 4) {
            size_t off = base + (size_t)tt * D_ + d;
            acc = fmaf(p[tt], __bfloat162float(vhi[off]) + __bfloat162float(vlo[off]), acc);
        }
        vp[grp * 64 + d] = acc;
    }
    __syncthreads();
    if (t < 64) {
        float o = vp[t] + vp[64 + t] + vp[128 + t] + vp[192 + t];
        size_t off = ((size_t)b * S_ + 256) * D_ + h * HD_ + t;
        Xo[off] = o;
        __nv_bfloat16 hb = __float2bfloat16(o);
        Xhi[off] = hb;
        Xlo[off] = __float2bfloat16(o - __bfloat162float(hb));
    }
}

// ============================================================================
// xa: grid (BH, KE, 16*nproj); batch offset b0
// ============================================================================
__global__ __launch_bounds__(256) void xa_kernel(
    const float* __restrict__ X,
    const float* __restrict__ A0, const float* __restrict__ A1,
    const float* __restrict__ A2,
    const int* __restrict__ idx, float* __restrict__ xa, int b0)
{
    int b = b0 + blockIdx.x, slot = blockIdx.y;
    int proj = blockIdx.z >> 4, zz = blockIdx.z & 15;
    int rh = zz >> 3, sc = zz & 7;
    const float* A = (proj == 0) ? A0 : (proj == 1) ? A1 : A2;
    float* xad = xa + (size_t)proj * B_ * KE_ * S_ * R_;
    int sbase = sc * 33;
    int smax = min(S_, sbase + 33);
    int e = idx[b * KE_ + slot];
    __shared__ float As[8][D_];
    const float* Ap = A + ((size_t)e * R_ + rh * 8) * D_;
    for (int i = threadIdx.x; i < 8 * D_ / 4; i += 256)
        ((float4*)As)[i] = ((const float4*)Ap)[i];
    __syncthreads();

    int w = threadIdx.x >> 5, lane = threadIdx.x & 31;
    for (int s4 = sbase + w * 4; s4 < smax; s4 += 32) {
        float sum[8][4];
        #pragma unroll
        for (int r = 0; r < 8; r++)
            #pragma unroll
            for (int si = 0; si < 4; si++) sum[r][si] = 0.f;

        #pragma unroll 1
        for (int c = 0; c < 8; c++) {
            float4 xv[4];
            #pragma unroll
            for (int si = 0; si < 4; si++) {
                int s = s4 + si;
                xv[si] = (s < S_)
                    ? *(const float4*)(X + ((size_t)b * S_ + s) * D_ + c * 128 + lane * 4)
                    : make_float4(0.f, 0.f, 0.f, 0.f);
            }
            #pragma unroll
            for (int r = 0; r < 8; r++) {
                float4 av = *(const float4*)&As[r][c * 128 + lane * 4];
                #pragma unroll
                for (int si = 0; si < 4; si++)
                    sum[r][si] = fmaf(xv[si].x, av.x,
                                 fmaf(xv[si].y, av.y,
                                 fmaf(xv[si].z, av.z,
                                 fmaf(xv[si].w, av.w, sum[r][si]))));
            }
        }
        #pragma unroll
        for (int r = 0; r < 8; r++)
            #pragma unroll
            for (int si = 0; si < 4; si++) {
                float v = sum[r][si];
                #pragma unroll
                for (int o = 16; o; o >>= 1) v += __shfl_xor_sync(0xffffffffu, v, o);
                int s = s4 + si;
                if (lane == 0 && s < S_)
                    xad[(((size_t)b * KE_ + slot) * S_ + s) * R_ + rh * 8 + r] = v;
            }
    }
}

// ============================================================================
// lora_add / lora_split3
// ============================================================================
__global__ __launch_bounds__(256) void lora_add(
    const float* __restrict__ Bm, const int* __restrict__ idx,
    const float* __restrict__ gates, const float* __restrict__ xa,
    float* __restrict__ Y, float scale, int b0)
{
    int b = b0 + blockIdx.x;
    int cn = blockIdx.y << 6;
    int t = threadIdx.x;
    __shared__ float Bs[2][64][17];
    __shared__ float xs[2][64][17];
    int e0 = idx[b * KE_], e1 = idx[b * KE_ + 1];
    float g0 = gates[b * KE_] * scale, g1 = gates[b * KE_ + 1] * scale;

    for (int i = t; i < 2048; i += 256) {
        int slot = i >> 10, rem = i & 1023, c = rem >> 4, r = rem & 15;
        Bs[slot][c][r] = Bm[((size_t)(slot ? e1 : e0) * D_ + cn + c) * R_ + r];
    }

    int c = t & 63, sq = t >> 6;
    for (int s0 = 0; s0 < S_; s0 += 64) {
        __syncthreads();
        for (int i = t; i < 2048; i += 256) {
            int slot = i >> 10, rem = i & 1023, si = rem >> 4, r = rem & 15;
            int s = s0 + si;
            float v = (s < S_) ? xa[(((size_t)b * KE_ + slot) * S_ + s) * R_ + r] : 0.f;
            xs[slot][si][r] = v * (slot ? g1 : g0);
        }
        __syncthreads();
        for (int si = sq; si < 64; si += 4) {
            int s = s0 + si;
            if (s >= S_) break;
            float sum = 0.f;
            #pragma unroll
            for (int r = 0; r < 16; r++) {
                sum = fmaf(xs[0][si][r], Bs[0][c][r], sum);
                sum = fmaf(xs[1][si][r], Bs[1][c][r], sum);
            }
            Y[((size_t)b * S_ + s) * D_ + cn + c] += sum;
        }
    }
}

__global__ __launch_bounds__(256) void lora_split3(
    const float* __restrict__ Bq, const float* __restrict__ Bk,
    const float* __restrict__ Bv,
    const int* __restrict__ idx, const float* __restrict__ gates,
    const float* __restrict__ xa, const float* __restrict__ Yin,
    __nv_bfloat16* __restrict__ qhi, __nv_bfloat16* __restrict__ qlo,
    __nv_bfloat16* __restrict__ khi, __nv_bfloat16* __restrict__ klo,
    __nv_bfloat16* __restrict__ vhi, __nv_bfloat16* __restrict__ vlo, int b0)
{
    const int z = blockIdx.z;
    const float* Bm = (z == 0) ? Bq : (z == 1) ? Bk : Bv;
    const float* Yz = Yin + (size_t)z * MTOT * D_;
    const float* xaz = xa + (size_t)z * B_ * KE_ * S_ * R_;
    __nv_bfloat16* Yhi = (z == 0) ? qhi : (z == 1) ? khi : vhi;
    __nv_bfloat16* Ylo = (z == 0) ? qlo : (z == 1) ? klo : vlo;
    const float scale = (z == 0) ? SCALE_Q : 1.f;

    int b = b0 + blockIdx.x;
    int cn = blockIdx.y << 6;
    int t = threadIdx.x;
    __shared__ float Bs[2][64][17];
    __shared__ float xs[2][64][17];
    int e0 = idx[b * KE_], e1 = idx[b * KE_ + 1];
    float g0 = gates[b * KE_] * scale, g1 = gates[b * KE_ + 1] * scale;

    for (int i = t; i < 2048; i += 256) {
        int slot = i >> 10, rem = i & 1023, c = rem >> 4, r = rem & 15;
        Bs[slot][c][r] = Bm[((size_t)(slot ? e1 : e0) * D_ + cn + c) * R_ + r];
    }

    int c = t & 63, sq = t >> 6;
    for (int s0 = 0; s0 < S_; s0 += 64) {
        __syncthreads();
        for (int i = t; i < 2048; i += 256) {
            int slot = i >> 10, rem = i & 1023, si = rem >> 4, r = rem & 15;
            int s = s0 + si;
            float v = (s < S_) ? xaz[(((size_t)b * KE_ + slot) * S_ + s) * R_ + r] : 0.f;
            xs[slot][si][r] = v * (slot ? g1 : g0);
        }
        __syncthreads();
        for (int si = sq; si < 64; si += 4) {
            int s = s0 + si;
            if (s >= S_) break;
            float sum = 0.f;
            #pragma unroll
            for (int r = 0; r < 16; r++) {
                sum = fmaf(xs[0][si][r], Bs[0][c][r], sum);
                sum = fmaf(xs[1][si][r], Bs[1][c][r], sum);
            }
            size_t off = ((size_t)b * S_ + s) * D_ + cn + c;
            float v = Yz[off] + sum;
            __nv_bfloat16 hb = __float2bfloat16(v);
            Yhi[off] = hb;
            Ylo[off] = __float2bfloat16(v - __bfloat162float(hb));
        }
    }
}

// ---------------- host launcher --------------------------------------------
extern "C" void kernel_launch(void* const* d_in, const int* in_sizes, int n_in,
                              void* d_out, int out_size)
{
    const float* hs    = (const float*)d_in[0];
    const int*   idx   = (const int*)  d_in[1];
    const float* gates = (const float*)d_in[2];
    const float* wq = (const float*)d_in[3];  const float* Aq = (const float*)d_in[4];
    const float* Bq = (const float*)d_in[5];  const float* bq = (const float*)d_in[6];
    const float* wk = (const float*)d_in[7];  const float* Ak = (const float*)d_in[8];
    const float* Bk = (const float*)d_in[9];  const float* bk = (const float*)d_in[10];
    const float* wv = (const float*)d_in[11]; const float* Av = (const float*)d_in[12];
    const float* Bv = (const float*)d_in[13]; const float* bv = (const float*)d_in[14];
    const float* wo = (const float*)d_in[15]; const float* Ao = (const float*)d_in[16];
    const float* Bo = (const float*)d_in[17]; const float* bo = (const float*)d_in[18];
    float* out = (float*)d_out;

    float *tmp, *x2, *xa;
    __nv_bfloat16 *xhi, *xlo, *whi, *wlo, *qhi, *qlo, *khi, *klo, *vhi, *vlo;
    cudaGetSymbolAddress((void**)&tmp, g_tmp);
    cudaGetSymbolAddress((void**)&x2,  g_x2);
    cudaGetSymbolAddress((void**)&xa,  g_xa);
    cudaGetSymbolAddress((void**)&xhi, g_xhi);
    cudaGetSymbolAddress((void**)&xlo, g_xlo);
    cudaGetSymbolAddress((void**)&whi, g_whi);
    cudaGetSymbolAddress((void**)&wlo, g_wlo);
    cudaGetSymbolAddress((void**)&qhi, g_qhi);
    cudaGetSymbolAddress((void**)&qlo, g_qlo);
    cudaGetSymbolAddress((void**)&khi, g_khi);
    cudaGetSymbolAddress((void**)&klo, g_klo);
    cudaGetSymbolAddress((void**)&vhi, g_vhi);
    cudaGetSymbolAddress((void**)&vlo, g_vlo);

    cudaFuncSetAttribute(mma_gemm_qkv, cudaFuncAttributeMaxDynamicSharedMemorySize, GEMM_SMEM);
    cudaFuncSetAttribute(mma_gemm, cudaFuncAttributeMaxDynamicSharedMemorySize, GEMM_SMEM);
    cudaFuncSetAttribute(flash_attn, cudaFuncAttributeMaxDynamicSharedMemorySize, FA_SMEM);
    cudaFuncSetAttribute(attn_tail, cudaFuncAttributeMaxDynamicSharedMemorySize, TAIL_SMEM);

    static cudaStream_t s1 = nullptr, s2 = nullptr, s3 = nullptr;
    static cudaEvent_t evR, evW, evXA[2], evL[2], evT[2], evF[2], evXO[2], evEnd;
    if (!s1) {
        cudaStreamCreateWithFlags(&s1, cudaStreamNonBlocking);
        cudaStreamCreateWithFlags(&s2, cudaStreamNonBlocking);
        cudaStreamCreateWithFlags(&s3, cudaStreamNonBlocking);
        cudaEventCreateWithFlags(&evR, cudaEventDisableTiming);
        cudaEventCreateWithFlags(&evW, cudaEventDisableTiming);
        for (int i = 0; i < 2; ++i) {
            cudaEventCreateWithFlags(&evXA[i], cudaEventDisableTiming);
            cudaEventCreateWithFlags(&evL[i], cudaEventDisableTiming);
            cudaEventCreateWithFlags(&evT[i], cudaEventDisableTiming);
            cudaEventCreateWithFlags(&evF[i], cudaEventDisableTiming);
            cudaEventCreateWithFlags(&evXO[i], cudaEventDisableTiming);
        }
        cudaEventCreateWithFlags(&evEnd, cudaEventDisableTiming);
    }

    const int nw4 = D_ * D_ / 4;
    const int nh4 = MH_ * D_ / 4;
    cudaStream_t ws[2] = {s2, s3};

    // ---- initial forks: qkv W split on s2 (wo later); per-half xa on worker
    cudaEventRecord(evR, 0);
    cudaStreamWaitEvent(s1, evR, 0);
    cudaStreamWaitEvent(s2, evR, 0);
    cudaStreamWaitEvent(s3, evR, 0);
    split_w3<<<dim3((nw4 + 255) / 256, 3), 256, 0, s2>>>(
        (const float4*)wq, (const float4*)wk, (const float4*)wv,
        (uint2*)whi, (uint2*)wlo);
    cudaEventRecord(evW, s2);
    split_bf16<<<(nw4 + 255) / 256, 256, 0, s2>>>(
        (const float4*)wo, (uint2*)(whi + (size_t)3 * D_ * D_),
        (uint2*)(wlo + (size_t)3 * D_ * D_), nw4);
    xa_kernel<<<dim3(BH_, KE_, 48), 256, 0, s2>>>(hs, Aq, Ak, Av, idx, xa, 0);
    cudaEventRecord(evXA[0], s2);
    xa_kernel<<<dim3(BH_, KE_, 48), 256, 0, s3>>>(hs, Aq, Ak, Av, idx, xa, BH_);
    cudaEventRecord(evXA[1], s3);

    // ---- per-half pipelines on stream 0 (half 0) and s1 (half 1) ----
    for (int h = 0; h < 2; ++h) {
        cudaStream_t st = h ? s1 : 0;
        cudaStream_t wk2 = ws[h];
        const int b0 = h * BH_;
        const int m0 = h * MH_;
        const int mmax = m0 + MH_;
        const int bh0 = b0 * H_;

        split_bf16<<<(nh4 + 255) / 256, 256, 0, st>>>(
            (const float4*)(hs + (size_t)m0 * D_),
            (uint2*)(xhi + (size_t)m0 * D_), (uint2*)(xlo + (size_t)m0 * D_), nh4);

        cudaStreamWaitEvent(st, evW, 0);
        mma_gemm_qkv<<<dim3(8, 33, 3), 256, GEMM_SMEM, st>>>(
            xhi, xlo, whi, wlo, bq, bk, bv, tmp, m0, mmax);

        cudaStreamWaitEvent(st, evXA[h], 0);
        lora_split3<<<dim3(BH_, 16, 3), 256, 0, st>>>(
            Bq, Bk, Bv, idx, gates, xa, tmp, qhi, qlo, khi, klo, vhi, vlo, b0);

        // fork: attn_tail on worker concurrent with flash_attn
        cudaEventRecord(evL[h], st);
        cudaStreamWaitEvent(wk2, evL[h], 0);
        attn_tail<<<BH_ * H_, 256, TAIL_SMEM, wk2>>>(
            qhi, qlo, khi, klo, vhi, vlo, x2, xhi, xlo, bh0);
        cudaEventRecord(evT[h], wk2);

        flash_attn<<<dim3(BH_ * H_, 4), 128, FA_SMEM, st>>>(
            qhi, qlo, khi, klo, vhi, vlo, x2, xhi, xlo, bh0);
        cudaStreamWaitEvent(st, evT[h], 0);

        // fork: xa(O) on worker concurrent with O GEMM
        cudaEventRecord(evF[h], st);
        cudaStreamWaitEvent(wk2, evF[h], 0);
        xa_kernel<<<dim3(BH_, KE_, 16), 256, 0, wk2>>>(x2, Ao, Ao, Ao, idx, xa, b0);
        cudaEventRecord(evXO[h], wk2);

        mma_gemm<<<dim3(8, 33), 256, GEMM_SMEM, st>>>(
            xhi, xlo, whi + (size_t)3 * D_ * D_, wlo + (size_t)3 * D_ * D_,
            bo, out, 1.f, m0, mmax);

        cudaStreamWaitEvent(st, evXO[h], 0);
        lora_add<<<dim3(BH_, 16), 256, 0, st>>>(Bo, idx, gates, xa, out, 1.f, b0);
    }

    cudaEventRecord(evEnd, s1);
    cudaStreamWaitEvent(0, evEnd, 0);
}

// round 17
// speedup vs baseline: 1.1594x; 1.0298x over previous
#include <cuda_runtime.h>
#include <cuda_bf16.h>
#include <cstdint>

#define B_ 32
#define S_ 257
#define D_ 1024
#define H_ 16
#define HD_ 64
#define E_ 8
#define R_ 16
#define KE_ 2
#define MTOT (B_*S_)
#define BH_ 16
#define MH_ (BH_*S_)
#define SCALE_Q 0.125f

// ---------------- scratch (device globals: allocation-free) ----------------
__device__ float g_tmp[(size_t)3 * MTOT * D_];
__device__ float g_x2 [(size_t)MTOT * D_];
__device__ float g_xa [(size_t)3 * B_ * KE_ * S_ * R_];
__device__ __nv_bfloat16 g_xhi[(size_t)MTOT * D_];
__device__ __nv_bfloat16 g_xlo[(size_t)MTOT * D_];
__device__ __nv_bfloat16 g_whi[(size_t)4 * D_ * D_];
__device__ __nv_bfloat16 g_wlo[(size_t)4 * D_ * D_];
__device__ __nv_bfloat16 g_qhi[(size_t)MTOT * D_];
__device__ __nv_bfloat16 g_qlo[(size_t)MTOT * D_];
__device__ __nv_bfloat16 g_khi[(size_t)MTOT * D_];
__device__ __nv_bfloat16 g_klo[(size_t)MTOT * D_];
__device__ __nv_bfloat16 g_vhi[(size_t)MTOT * D_];
__device__ __nv_bfloat16 g_vlo[(size_t)MTOT * D_];

// ========================= helpers ==========================================
__device__ __forceinline__ uint32_t smem_u32(const void* p) {
    uint32_t a;
    asm("{ .reg .u64 t; cvta.to.shared.u64 t, %1; cvt.u32.u64 %0, t; }"
        : "=r"(a) : "l"(p));
    return a;
}

#define LDSM4(r0, r1, r2, r3, addr) \
    asm volatile("ldmatrix.sync.aligned.m8n8.x4.shared.b16 {%0,%1,%2,%3}, [%4];" \
        : "=r"(r0), "=r"(r1), "=r"(r2), "=r"(r3) : "r"(addr))

#define LDSM4T(r0, r1, r2, r3, addr) \
    asm volatile("ldmatrix.sync.aligned.m8n8.x4.trans.shared.b16 {%0,%1,%2,%3}, [%4];" \
        : "=r"(r0), "=r"(r1), "=r"(r2), "=r"(r3) : "r"(addr))

// non-volatile: lets ptxas interleave/pipeline MMAs with LDSMs
#define MMA16816(d, a, b0, b1) \
    asm("mma.sync.aligned.m16n8k16.row.col.f32.bf16.bf16.f32 " \
        "{%0,%1,%2,%3}, {%4,%5,%6,%7}, {%8,%9}, {%0,%1,%2,%3};" \
        : "+f"((d)[0]), "+f"((d)[1]), "+f"((d)[2]), "+f"((d)[3]) \
        : "r"((a)[0]), "r"((a)[1]), "r"((a)[2]), "r"((a)[3]), "r"(b0), "r"(b1))

#define CP_ASYNC16(dst, src, sz) \
    asm volatile("cp.async.cg.shared.global [%0], [%1], 16, %2;" \
        :: "r"(dst), "l"(src), "r"(sz))
#define CP_COMMIT()  asm volatile("cp.async.commit_group;" ::: "memory")
#define CP_WAIT0()   asm volatile("cp.async.wait_group 0;" ::: "memory")

__device__ __forceinline__ float fexp(float x) {
    x = fmaxf(x, -80.f);
    float t = x * 1.4426950408889634f;
    float z = t + 12582912.f;
    int   k = __float_as_int(z) - 0x4B400000;
    float f = t - (z - 12582912.f);
    float p = 1.3333558146428443e-3f;
    p = fmaf(p, f, 9.6181291076284772e-3f);
    p = fmaf(p, f, 5.5504108664821580e-2f);
    p = fmaf(p, f, 2.4022650695910071e-1f);
    p = fmaf(p, f, 6.9314718055994531e-1f);
    p = fmaf(p, f, 1.0f);
    return __int_as_float(__float_as_int(p) + (k << 23));
}

// ============================================================================
// split fp32 -> (bf16 hi, bf16 lo)
// ============================================================================
__device__ __forceinline__ void split_one(
    const float4* __restrict__ x, uint2* __restrict__ hi, uint2* __restrict__ lo, int i)
{
    float4 v = x[i];
    __nv_bfloat162 h01 = __floats2bfloat162_rn(v.x, v.y);
    __nv_bfloat162 h23 = __floats2bfloat162_rn(v.z, v.w);
    float lx = v.x - __bfloat162float(h01.x);
    float ly = v.y - __bfloat162float(h01.y);
    float lz = v.z - __bfloat162float(h23.x);
    float lw = v.w - __bfloat162float(h23.y);
    __nv_bfloat162 l01 = __floats2bfloat162_rn(lx, ly);
    __nv_bfloat162 l23 = __floats2bfloat162_rn(lz, lw);
    uint2 hv, lv;
    hv.x = *(uint32_t*)&h01; hv.y = *(uint32_t*)&h23;
    lv.x = *(uint32_t*)&l01; lv.y = *(uint32_t*)&l23;
    hi[i] = hv; lo[i] = lv;
}

__global__ __launch_bounds__(256) void split_bf16(
    const float4* __restrict__ x, uint2* __restrict__ hi, uint2* __restrict__ lo, int n4)
{
    int i = blockIdx.x * 256 + threadIdx.x;
    if (i < n4) split_one(x, hi, lo, i);
}

__global__ __launch_bounds__(256) void split_w3(
    const float4* __restrict__ w0, const float4* __restrict__ w1,
    const float4* __restrict__ w2,
    uint2* __restrict__ hi, uint2* __restrict__ lo)
{
    const int n4 = D_ * D_ / 4;
    int i = blockIdx.x * 256 + threadIdx.x;
    if (i >= n4) return;
    int z = blockIdx.y;
    const float4* src = (z == 0) ? w0 : (z == 1) ? w1 : w2;
    split_one(src, hi + (size_t)z * n4, lo + (size_t)z * n4, i);
}

// ============================================================================
// HMMA GEMM via bf16x3 split — 128x128 block tile, 8 warps (64x32), occ 2
// ============================================================================
#define APITCH 80
#define TILEB (128 * APITCH)
#define STAGEB (4 * TILEB)
#define GEMM_SMEM (2 * STAGEB)

__device__ __forceinline__ void stage_load(
    uint32_t sb, int buf, int c, int tm, int tn, int tid, int mmax,
    const __nv_bfloat16* __restrict__ Xhi, const __nv_bfloat16* __restrict__ Xlo,
    const __nv_bfloat16* __restrict__ Whi, const __nv_bfloat16* __restrict__ Wlo)
{
    uint32_t st = sb + buf * STAGEB;
    #pragma unroll
    for (int j = 0; j < 8; ++j) {
        int g = tid + j * 256;
        int tile = g >> 9, i = g & 511, row = i >> 2, seg = i & 3;
        const __nv_bfloat16* base = (tile == 0) ? Xhi : (tile == 1) ? Xlo
                                   : (tile == 2) ? Whi : Wlo;
        int grow = ((tile < 2) ? tm : tn) + row;
        const void* src = base + (size_t)grow * D_ + c * 32 + seg * 8;
        uint32_t dst = st + tile * TILEB + row * APITCH + seg * 16;
        int sz = (tile >= 2 || grow < mmax) ? 16 : 0;
        CP_ASYNC16(dst, src, sz);
    }
}

__device__ __forceinline__ void gemm_body(
    const __nv_bfloat16* __restrict__ Xhi, const __nv_bfloat16* __restrict__ Xlo,
    const __nv_bfloat16* __restrict__ Whi, const __nv_bfloat16* __restrict__ Wlo,
    const float* __restrict__ bias, float* __restrict__ Y, float scale,
    int m0g, int mmax)
{
    extern __shared__ char smem[];
    const uint32_t sb = smem_u32(smem);
    const int tid = threadIdx.x;
    const int wid = tid >> 5, lane = tid & 31;
    const int tm = m0g + (blockIdx.y << 7), tn = blockIdx.x << 7;
    const int wm = (wid & 1) * 64, wn = (wid >> 1) * 32;

    const int lrow = lane & 15;
    const int lk   = lane >> 4;
    const int brow = ((lane >> 4) << 3) + (lane & 7);
    const int bk   = (lane >> 3) & 1;

    float acc[4][4][4] = {};

    stage_load(sb, 0, 0, tm, tn, tid, mmax, Xhi, Xlo, Whi, Wlo);
    CP_COMMIT();

    for (int c = 0; c < 32; ++c) {
        const int buf = c & 1;
        CP_WAIT0();
        __syncthreads();
        if (c + 1 < 32) {
            stage_load(sb, buf ^ 1, c + 1, tm, tn, tid, mmax, Xhi, Xlo, Whi, Wlo);
            CP_COMMIT();
        }

        const uint32_t Ah = sb + buf * STAGEB;
        const uint32_t Al = Ah + TILEB;
        const uint32_t Bh = Ah + 2 * TILEB;
        const uint32_t Bl = Ah + 3 * TILEB;

        #pragma unroll
        for (int kk2 = 0; kk2 < 2; ++kk2) {
            const int kkb = kk2 * 32;
            uint32_t fa[4][4], fb[2][4], fc[2][4];
            const uint32_t aoff = (uint32_t)(wm + lrow) * APITCH + kkb + lk * 16;
            const uint32_t boff = (uint32_t)(wn + brow) * APITCH + kkb + bk * 16;
            #pragma unroll
            for (int mt = 0; mt < 4; ++mt)
                LDSM4(fa[mt][0], fa[mt][1], fa[mt][2], fa[mt][3],
                      Ah + aoff + mt * (16 * APITCH));
            #pragma unroll
            for (int p = 0; p < 2; ++p) {
                LDSM4(fb[p][0], fb[p][1], fb[p][2], fb[p][3],
                      Bh + boff + p * (16 * APITCH));
                LDSM4(fc[p][0], fc[p][1], fc[p][2], fc[p][3],
                      Bl + boff + p * (16 * APITCH));
            }
            #pragma unroll
            for (int mt = 0; mt < 4; ++mt)
                #pragma unroll
                for (int nt = 0; nt < 4; ++nt) {
                    const int p = nt >> 1, h = (nt & 1) * 2;
                    MMA16816(acc[mt][nt], fa[mt], fb[p][h], fb[p][h + 1]);
                }
            #pragma unroll
            for (int mt = 0; mt < 4; ++mt)
                #pragma unroll
                for (int nt = 0; nt < 4; ++nt) {
                    const int p = nt >> 1, h = (nt & 1) * 2;
                    MMA16816(acc[mt][nt], fa[mt], fc[p][h], fc[p][h + 1]);
                }
            #pragma unroll
            for (int mt = 0; mt < 4; ++mt)
                LDSM4(fa[mt][0], fa[mt][1], fa[mt][2], fa[mt][3],
                      Al + aoff + mt * (16 * APITCH));
            #pragma unroll
            for (int mt = 0; mt < 4; ++mt)
                #pragma unroll
                for (int nt = 0; nt < 4; ++nt) {
                    const int p = nt >> 1, h = (nt & 1) * 2;
                    MMA16816(acc[mt][nt], fa[mt], fb[p][h], fb[p][h + 1]);
                }
        }
        __syncthreads();
    }

    const int erow = lane >> 2, ecol = (lane & 3) * 2;
    #pragma unroll
    for (int mt = 0; mt < 4; ++mt) {
        #pragma unroll
        for (int nt = 0; nt < 4; ++nt) {
            int m0 = tm + wm + mt * 16 + erow;
            int n0 = tn + wn + nt * 8 + ecol;
            float bx = bias[n0], by = bias[n0 + 1];
            if (m0 < mmax) {
                float2 o;
                o.x = (acc[mt][nt][0] + bx) * scale;
                o.y = (acc[mt][nt][1] + by) * scale;
                *(float2*)(Y + (size_t)m0 * D_ + n0) = o;
            }
            if (m0 + 8 < mmax) {
                float2 o;
                o.x = (acc[mt][nt][2] + bx) * scale;
                o.y = (acc[mt][nt][3] + by) * scale;
                *(float2*)(Y + (size_t)(m0 + 8) * D_ + n0) = o;
            }
        }
    }
}

// grid.z in [0, nz); projection index = z0 + blockIdx.z
__global__ __launch_bounds__(256, 2) void mma_gemm_qkv(
    const __nv_bfloat16* __restrict__ Xhi, const __nv_bfloat16* __restrict__ Xlo,
    const __nv_bfloat16* __restrict__ Whi, const __nv_bfloat16* __restrict__ Wlo,
    const float* __restrict__ bq, const float* __restrict__ bk,
    const float* __restrict__ bv, float* __restrict__ Y, int m0g, int mmax, int z0)
{
    const int z = z0 + blockIdx.z;
    const size_t wo = (size_t)z * D_ * D_;
    const float* bias = (z == 0) ? bq : (z == 1) ? bk : bv;
    gemm_body(Xhi, Xlo, Whi + wo, Wlo + wo, bias,
              Y + (size_t)z * MTOT * D_, (z == 0) ? SCALE_Q : 1.f, m0g, mmax);
}

__global__ __launch_bounds__(256, 2) void mma_gemm(
    const __nv_bfloat16* __restrict__ Xhi, const __nv_bfloat16* __restrict__ Xlo,
    const __nv_bfloat16* __restrict__ Whi, const __nv_bfloat16* __restrict__ Wlo,
    const float* __restrict__ bias, float* __restrict__ Y, float scale,
    int m0g, int mmax)
{
    gemm_body(Xhi, Xlo, Whi, Wlo, bias, Y, scale, m0g, mmax);
}

// ============================================================================
// Fused flash attention: 64-row Q tiles, 128 threads.
// kv tiles 0..3 cover t<256; t=256 column folded analytically in fp32.
// ============================================================================
#define FPITCH 144
#define KVROWB (64 * FPITCH)
#define KVSTG  (4 * KVROWB)
#define FA_SMEM (2 * KVSTG + 512)

__device__ __forceinline__ void load_kv(
    uint32_t st, int t0, size_t kvbase, int tid,
    const __nv_bfloat16* __restrict__ khi, const __nv_bfloat16* __restrict__ klo,
    const __nv_bfloat16* __restrict__ vhi, const __nv_bfloat16* __restrict__ vlo)
{
    #pragma unroll
    for (int j = 0; j < 16; ++j) {
        int g = tid + j * 128;
        int tens = g >> 9, i = g & 511, row = i >> 3, seg = i & 7;
        const __nv_bfloat16* bp = (tens == 0) ? khi : (tens == 1) ? klo
                                 : (tens == 2) ? vhi : vlo;
        const void* src = bp + kvbase + (size_t)(t0 + row) * D_ + seg * 8;
        uint32_t dst = st + tens * KVROWB + row * FPITCH + seg * 16;
        CP_ASYNC16(dst, src, 16);
    }
}

__global__ __launch_bounds__(128) void flash_attn(
    const __nv_bfloat16* __restrict__ qhi, const __nv_bfloat16* __restrict__ qlo,
    const __nv_bfloat16* __restrict__ khi, const __nv_bfloat16* __restrict__ klo,
    const __nv_bfloat16* __restrict__ vhi, const __nv_bfloat16* __restrict__ vlo,
    float* __restrict__ Xo,
    __nv_bfloat16* __restrict__ Xhi, __nv_bfloat16* __restrict__ Xlo, int bh0)
{
    extern __shared__ char smem[];
    const uint32_t sb = smem_u32(smem);
    float* k256f = (float*)(smem + 2 * KVSTG);
    float* v256f = k256f + 64;
    const int tid = threadIdx.x, wid = tid >> 5, lane = tid & 31;
    const int bh = bh0 + blockIdx.x, b = bh >> 4, h = bh & 15;
    const int m0 = blockIdx.y * 64;
    const size_t kvbase = (size_t)b * S_ * D_ + h * HD_;

    #pragma unroll
    for (int j = 0; j < 8; ++j) {
        int g = tid + j * 128;
        int half = g >> 9, i = g & 511, row = i >> 3, seg = i & 7;
        const __nv_bfloat16* src = (half ? qlo : qhi) + kvbase
                                 + (size_t)(m0 + row) * D_ + seg * 8;
        uint32_t dst = sb + half * KVSTG + row * FPITCH + seg * 16;
        CP_ASYNC16(dst, src, (m0 + row) < S_ ? 16 : 0);
    }
    if (tid < 64) {
        size_t o = kvbase + (size_t)256 * D_ + tid;
        k256f[tid] = __bfloat162float(khi[o]) + __bfloat162float(klo[o]);
        v256f[tid] = __bfloat162float(vhi[o]) + __bfloat162float(vlo[o]);
    }
    CP_COMMIT(); CP_WAIT0();
    __syncthreads();

    uint32_t qh[4][4], ql[4][4];
    {
        const uint32_t base = sb + (uint32_t)(wid * 16 + (lane & 15)) * FPITCH
                            + (lane >> 4) * 16;
        #pragma unroll
        for (int kk = 0; kk < 4; ++kk) {
            LDSM4(qh[kk][0], qh[kk][1], qh[kk][2], qh[kk][3], base + kk * 32);
            LDSM4(ql[kk][0], ql[kk][1], ql[kk][2], ql[kk][3], base + KVSTG + kk * 32);
        }
    }
    __syncthreads();

    const int quad = lane & 3;

    float s256[2];
    #pragma unroll
    for (int rr = 0; rr < 2; ++rr) {
        float a = 0.f;
        #pragma unroll
        for (int kk = 0; kk < 4; ++kk) {
            int c0 = kk * 16 + quad * 2;
            __nv_bfloat162 hb = *(__nv_bfloat162*)&qh[kk][rr];
            __nv_bfloat162 lb = *(__nv_bfloat162*)&ql[kk][rr];
            a = fmaf(__bfloat162float(hb.x) + __bfloat162float(lb.x), k256f[c0], a);
            a = fmaf(__bfloat162float(hb.y) + __bfloat162float(lb.y), k256f[c0 + 1], a);
            hb = *(__nv_bfloat162*)&qh[kk][rr + 2];
            lb = *(__nv_bfloat162*)&ql[kk][rr + 2];
            a = fmaf(__bfloat162float(hb.x) + __bfloat162float(lb.x), k256f[c0 + 8], a);
            a = fmaf(__bfloat162float(hb.y) + __bfloat162float(lb.y), k256f[c0 + 9], a);
        }
        a += __shfl_xor_sync(0xffffffffu, a, 1);
        a += __shfl_xor_sync(0xffffffffu, a, 2);
        s256[rr] = a;
    }

    float acc_o[8][4] = {};
    float mrow[2] = {-1e30f, -1e30f}, lrow[2] = {0.f, 0.f};
    float p256[2] = {0.f, 0.f};
    const int brow = ((lane >> 4) << 3) + (lane & 7);
    const int bk   = (lane >> 3) & 1;

    load_kv(sb, 0, kvbase, tid, khi, klo, vhi, vlo);
    CP_COMMIT();

    #pragma unroll 1
    for (int kv = 0; kv < 4; ++kv) {
        CP_WAIT0();
        __syncthreads();
        const uint32_t Ks = sb + (kv & 1) * KVSTG;
        const uint32_t Vs = Ks + 2 * KVROWB;
        if (kv < 3) {
            load_kv(sb + ((kv + 1) & 1) * KVSTG, (kv + 1) * 64, kvbase, tid,
                    khi, klo, vhi, vlo);
            CP_COMMIT();
        }

        float s[8][4] = {};
        #pragma unroll
        for (int kk = 0; kk < 4; ++kk) {
            uint32_t kh[4][4], kl[4][4];
            #pragma unroll
            for (int p = 0; p < 4; ++p) {
                uint32_t ko = Ks + (uint32_t)(p * 16 + brow) * FPITCH + kk * 32 + bk * 16;
                LDSM4(kh[p][0], kh[p][1], kh[p][2], kh[p][3], ko);
                LDSM4(kl[p][0], kl[p][1], kl[p][2], kl[p][3], ko + KVROWB);
            }
            #pragma unroll
            for (int p = 0; p < 4; ++p) {
                MMA16816(s[2*p],   qh[kk], kh[p][0], kh[p][1]);
                MMA16816(s[2*p+1], qh[kk], kh[p][2], kh[p][3]);
                MMA16816(s[2*p],   qh[kk], kl[p][0], kl[p][1]);
                MMA16816(s[2*p+1], qh[kk], kl[p][2], kl[p][3]);
                MMA16816(s[2*p],   ql[kk], kh[p][0], kh[p][1]);
                MMA16816(s[2*p+1], ql[kk], kh[p][2], kh[p][3]);
            }
        }

        const bool last = (kv == 3);

        #pragma unroll
        for (int rr = 0; rr < 2; ++rr) {
            float mx = -1e30f;
            #pragma unroll
            for (int nt = 0; nt < 8; ++nt)
                mx = fmaxf(mx, fmaxf(s[nt][2*rr], s[nt][2*rr+1]));
            mx = fmaxf(mx, __shfl_xor_sync(0xffffffffu, mx, 1));
            mx = fmaxf(mx, __shfl_xor_sync(0xffffffffu, mx, 2));
            if (last) mx = fmaxf(mx, s256[rr]);
            float mnew = fmaxf(mrow[rr], mx);
            float alpha = fexp(mrow[rr] - mnew);
            mrow[rr] = mnew;
            float sum = 0.f;
            #pragma unroll
            for (int nt = 0; nt < 8; ++nt) {
                float p0 = fexp(s[nt][2*rr]   - mnew);
                float p1 = fexp(s[nt][2*rr+1] - mnew);
                s[nt][2*rr] = p0; s[nt][2*rr+1] = p1;
                sum += p0 + p1;
            }
            sum += __shfl_xor_sync(0xffffffffu, sum, 1);
            sum += __shfl_xor_sync(0xffffffffu, sum, 2);
            if (last) {
                p256[rr] = fexp(s256[rr] - mnew);
                sum += p256[rr];
            }
            lrow[rr] = lrow[rr] * alpha + sum;
            #pragma unroll
            for (int nt = 0; nt < 8; ++nt) {
                acc_o[nt][2*rr]   *= alpha;
                acc_o[nt][2*rr+1] *= alpha;
            }
        }

        #pragma unroll
        for (int kk = 0; kk < 4; ++kk) {
            uint32_t ph[4], pl[4];
            #pragma unroll
            for (int rg = 0; rg < 4; ++rg) {
                int nt = 2 * kk + (rg >> 1);
                float p0 = s[nt][(rg & 1) * 2];
                float p1 = s[nt][(rg & 1) * 2 + 1];
                __nv_bfloat162 hb = __floats2bfloat162_rn(p0, p1);
                float l0 = p0 - __bfloat162float(hb.x);
                float l1 = p1 - __bfloat162float(hb.y);
                __nv_bfloat162 lb = __floats2bfloat162_rn(l0, l1);
                ph[rg] = *(uint32_t*)&hb;
                pl[rg] = *(uint32_t*)&lb;
            }
            uint32_t vh[4][4], vl[4][4];
            #pragma unroll
            for (int p = 0; p < 4; ++p) {
                uint32_t vo = Vs + (uint32_t)(kk * 16 + (lane & 15)) * FPITCH
                            + p * 32 + (lane >> 4) * 16;
                LDSM4T(vh[p][0], vh[p][1], vh[p][2], vh[p][3], vo);
                LDSM4T(vl[p][0], vl[p][1], vl[p][2], vl[p][3], vo + KVROWB);
            }
            #pragma unroll
            for (int p = 0; p < 4; ++p) {
                MMA16816(acc_o[2*p],   ph, vh[p][0], vh[p][1]);
                MMA16816(acc_o[2*p+1], ph, vh[p][2], vh[p][3]);
                MMA16816(acc_o[2*p],   ph, vl[p][0], vl[p][1]);
                MMA16816(acc_o[2*p+1], ph, vl[p][2], vl[p][3]);
                MMA16816(acc_o[2*p],   pl, vh[p][0], vh[p][1]);
                MMA16816(acc_o[2*p+1], pl, vh[p][2], vh[p][3]);
            }
        }

        if (last) {
            #pragma unroll
            for (int rr = 0; rr < 2; ++rr)
                #pragma unroll
                for (int nt = 0; nt < 8; ++nt) {
                    int col = nt * 8 + quad * 2;
                    acc_o[nt][2*rr]   = fmaf(p256[rr], v256f[col],     acc_o[nt][2*rr]);
                    acc_o[nt][2*rr+1] = fmaf(p256[rr], v256f[col + 1], acc_o[nt][2*rr+1]);
                }
        }
    }

    {
        const int r = lane >> 2, q2 = quad * 2;
        #pragma unroll
        for (int rr = 0; rr < 2; ++rr) {
            int m = m0 + wid * 16 + r + rr * 8;
            if (m < S_) {
                float inv = 1.f / lrow[rr];
                size_t off = ((size_t)b * S_ + m) * D_ + h * HD_ + q2;
                #pragma unroll
                for (int nt = 0; nt < 8; ++nt) {
                    float ox = acc_o[nt][2*rr]   * inv;
                    float oy = acc_o[nt][2*rr+1] * inv;
                    float2 o = make_float2(ox, oy);
                    *(float2*)(Xo + off + nt * 8) = o;
                    __nv_bfloat162 hb = __floats2bfloat162_rn(ox, oy);
                    __nv_bfloat162 lb = __floats2bfloat162_rn(
                        ox - __bfloat162float(hb.x), oy - __bfloat162float(hb.y));
                    *(__nv_bfloat162*)(Xhi + off + nt * 8) = hb;
                    *(__nv_bfloat162*)(Xlo + off + nt * 8) = lb;
                }
            }
        }
    }
}

// ============================================================================
// attn_tail: query row s = 256; also writes xhi/xlo
// ============================================================================
#define TAIL_SMEM ((257 * 65 + 64 + 257 + 256 + 4 * 64) * 4)
__global__ __launch_bounds__(256) void attn_tail(
    const __nv_bfloat16* __restrict__ qhi, const __nv_bfloat16* __restrict__ qlo,
    const __nv_bfloat16* __restrict__ khi, const __nv_bfloat16* __restrict__ klo,
    const __nv_bfloat16* __restrict__ vhi, const __nv_bfloat16* __restrict__ vlo,
    float* __restrict__ Xo,
    __nv_bfloat16* __restrict__ Xhi, __nv_bfloat16* __restrict__ Xlo, int bh0)
{
    extern __shared__ float fs[];
    float* ks  = fs;
    float* q   = ks + 257 * 65;
    float* p   = q + 64;
    float* red = p + 257;
    float* vp  = red + 256;
    const int t = threadIdx.x;
    const int bh = bh0 + blockIdx.x, b = bh >> 4, h = bh & 15;
    const size_t base = (size_t)b * S_ * D_ + h * HD_;

    if (t < 64) {
        size_t o = base + (size_t)256 * D_ + t;
        q[t] = __bfloat162float(qhi[o]) + __bfloat162float(qlo[o]);
    }
    for (int i = t; i < 257 * 64; i += 256) {
        int row = i >> 6, d = i & 63;
        size_t o = base + (size_t)row * D_ + d;
        ks[row * 65 + d] = __bfloat162float(khi[o]) + __bfloat162float(klo[o]);
    }
    __syncthreads();

    float v0 = 0.f, v1 = -1e30f;
    {
        const float* kr = ks + t * 65;
        #pragma unroll 8
        for (int d = 0; d < 64; ++d) v0 = fmaf(q[d], kr[d], v0);
    }
    if (t == 0) {
        v1 = 0.f;
        const float* kr = ks + 256 * 65;
        #pragma unroll 8
        for (int d = 0; d < 64; ++d) v1 = fmaf(q[d], kr[d], v1);
    }

    red[t] = fmaxf(v0, v1);
    __syncthreads();
    #pragma unroll
    for (int o = 128; o; o >>= 1) {
        if (t < o) red[t] = fmaxf(red[t], red[t + o]);
        __syncthreads();
    }
    float rmax = red[0];
    __syncthreads();
    float e0 = fexp(v0 - rmax);
    float e1 = (t == 0) ? fexp(v1 - rmax) : 0.f;
    red[t] = e0 + e1;
    __syncthreads();
    #pragma unroll
    for (int o = 128; o; o >>= 1) {
        if (t < o) red[t] += red[t + o];
        __syncthreads();
    }
    float inv = 1.f / red[0];
    p[t] = e0 * inv;
    if (t == 0) p[256] = e1 * inv;
    __syncthreads();

    {
        int d = t & 63, grp = t >> 6;
        float acc = 0.f;
        for (int tt = grp; tt < S_; tt += 4) {
            size_t off = base + (size_t)tt * D_ + d;
            acc = fmaf(p[tt], __bfloat162float(vhi[off]) + __bfloat162float(vlo[off]), acc);
        }
        vp[grp * 64 + d] = acc;
    }
    __syncthreads();
    if (t < 64) {
        float o = vp[t] + vp[64 + t] + vp[128 + t] + vp[192 + t];
        size_t off = ((size_t)b * S_ + 256) * D_ + h * HD_ + t;
        Xo[off] = o;
        __nv_bfloat16 hb = __float2bfloat16(o);
        Xhi[off] = hb;
        Xlo[off] = __float2bfloat16(o - __bfloat162float(hb));
    }
}

// ============================================================================
// xa: grid (BH, KE, 8*nproj); s-chunks of 65 (halved A reload traffic)
// ============================================================================
__global__ __launch_bounds__(256) void xa_kernel(
    const float* __restrict__ X,
    const float* __restrict__ A0, const float* __restrict__ A1,
    const float* __restrict__ A2,
    const int* __restrict__ idx, float* __restrict__ xa, int b0)
{
    int b = b0 + blockIdx.x, slot = blockIdx.y;
    int proj = blockIdx.z >> 3, zz = blockIdx.z & 7;
    int rh = zz >> 2, sc = zz & 3;
    const float* A = (proj == 0) ? A0 : (proj == 1) ? A1 : A2;
    float* xad = xa + (size_t)proj * B_ * KE_ * S_ * R_;
    int sbase = sc * 65;
    int smax = min(S_, sbase + 65);
    int e = idx[b * KE_ + slot];
    __shared__ float As[8][D_];
    const float* Ap = A + ((size_t)e * R_ + rh * 8) * D_;
    for (int i = threadIdx.x; i < 8 * D_ / 4; i += 256)
        ((float4*)As)[i] = ((const float4*)Ap)[i];
    __syncthreads();

    int w = threadIdx.x >> 5, lane = threadIdx.x & 31;
    for (int s4 = sbase + w * 4; s4 < smax; s4 += 32) {
        float sum[8][4];
        #pragma unroll
        for (int r = 0; r < 8; r++)
            #pragma unroll
            for (int si = 0; si < 4; si++) sum[r][si] = 0.f;

        #pragma unroll 1
        for (int c = 0; c < 8; c++) {
            float4 xv[4];
            #pragma unroll
            for (int si = 0; si < 4; si++) {
                int s = s4 + si;
                xv[si] = (s < S_)
                    ? *(const float4*)(X + ((size_t)b * S_ + s) * D_ + c * 128 + lane * 4)
                    : make_float4(0.f, 0.f, 0.f, 0.f);
            }
            #pragma unroll
            for (int r = 0; r < 8; r++) {
                float4 av = *(const float4*)&As[r][c * 128 + lane * 4];
                #pragma unroll
                for (int si = 0; si < 4; si++)
                    sum[r][si] = fmaf(xv[si].x, av.x,
                                 fmaf(xv[si].y, av.y,
                                 fmaf(xv[si].z, av.z,
                                 fmaf(xv[si].w, av.w, sum[r][si]))));
            }
        }
        #pragma unroll
        for (int r = 0; r < 8; r++)
            #pragma unroll
            for (int si = 0; si < 4; si++) {
                float v = sum[r][si];
                #pragma unroll
                for (int o = 16; o; o >>= 1) v += __shfl_xor_sync(0xffffffffu, v, o);
                int s = s4 + si;
                if (lane == 0 && s < S_)
                    xad[(((size_t)b * KE_ + slot) * S_ + s) * R_ + rh * 8 + r] = v;
            }
    }
}

// ============================================================================
// lora_add / lora_split (z0 offset selects projection range)
// ============================================================================
__global__ __launch_bounds__(256) void lora_add(
    const float* __restrict__ Bm, const int* __restrict__ idx,
    const float* __restrict__ gates, const float* __restrict__ xa,
    float* __restrict__ Y, float scale, int b0)
{
    int b = b0 + blockIdx.x;
    int cn = blockIdx.y << 6;
    int t = threadIdx.x;
    __shared__ float Bs[2][64][17];
    __shared__ float xs[2][64][17];
    int e0 = idx[b * KE_], e1 = idx[b * KE_ + 1];
    float g0 = gates[b * KE_] * scale, g1 = gates[b * KE_ + 1] * scale;

    for (int i = t; i < 2048; i += 256) {
        int slot = i >> 10, rem = i & 1023, c = rem >> 4, r = rem & 15;
        Bs[slot][c][r] = Bm[((size_t)(slot ? e1 : e0) * D_ + cn + c) * R_ + r];
    }

    int c = t & 63, sq = t >> 6;
    for (int s0 = 0; s0 < S_; s0 += 64) {
        __syncthreads();
        for (int i = t; i < 2048; i += 256) {
            int slot = i >> 10, rem = i & 1023, si = rem >> 4, r = rem & 15;
            int s = s0 + si;
            float v = (s < S_) ? xa[(((size_t)b * KE_ + slot) * S_ + s) * R_ + r] : 0.f;
            xs[slot][si][r] = v * (slot ? g1 : g0);
        }
        __syncthreads();
        for (int si = sq; si < 64; si += 4) {
            int s = s0 + si;
            if (s >= S_) break;
            float sum = 0.f;
            #pragma unroll
            for (int r = 0; r < 16; r++) {
                sum = fmaf(xs[0][si][r], Bs[0][c][r], sum);
                sum = fmaf(xs[1][si][r], Bs[1][c][r], sum);
            }
            Y[((size_t)b * S_ + s) * D_ + cn + c] += sum;
        }
    }
}

__global__ __launch_bounds__(256) void lora_split3(
    const float* __restrict__ Bq, const float* __restrict__ Bk,
    const float* __restrict__ Bv,
    const int* __restrict__ idx, const float* __restrict__ gates,
    const float* __restrict__ xa, const float* __restrict__ Yin,
    __nv_bfloat16* __restrict__ qhi, __nv_bfloat16* __restrict__ qlo,
    __nv_bfloat16* __restrict__ khi, __nv_bfloat16* __restrict__ klo,
    __nv_bfloat16* __restrict__ vhi, __nv_bfloat16* __restrict__ vlo,
    int b0, int z0)
{
    const int z = z0 + blockIdx.z;
    const float* Bm = (z == 0) ? Bq : (z == 1) ? Bk : Bv;
    const float* Yz = Yin + (size_t)z * MTOT * D_;
    const float* xaz = xa + (size_t)z * B_ * KE_ * S_ * R_;
    __nv_bfloat16* Yhi = (z == 0) ? qhi : (z == 1) ? khi : vhi;
    __nv_bfloat16* Ylo = (z == 0) ? qlo : (z == 1) ? klo : vlo;
    const float scale = (z == 0) ? SCALE_Q : 1.f;

    int b = b0 + blockIdx.x;
    int cn = blockIdx.y << 6;
    int t = threadIdx.x;
    __shared__ float Bs[2][64][17];
    __shared__ float xs[2][64][17];
    int e0 = idx[b * KE_], e1 = idx[b * KE_ + 1];
    float g0 = gates[b * KE_] * scale, g1 = gates[b * KE_ + 1] * scale;

    for (int i = t; i < 2048; i += 256) {
        int slot = i >> 10, rem = i & 1023, c = rem >> 4, r = rem & 15;
        Bs[slot][c][r] = Bm[((size_t)(slot ? e1 : e0) * D_ + cn + c) * R_ + r];
    }

    int c = t & 63, sq = t >> 6;
    for (int s0 = 0; s0 < S_; s0 += 64) {
        __syncthreads();
        for (int i = t; i < 2048; i += 256) {
            int slot = i >> 10, rem = i & 1023, si = rem >> 4, r = rem & 15;
            int s = s0 + si;
            float v = (s < S_) ? xaz[(((size_t)b * KE_ + slot) * S_ + s) * R_ + r] : 0.f;
            xs[slot][si][r] = v * (slot ? g1 : g0);
        }
        __syncthreads();
        for (int si = sq; si < 64; si += 4) {
            int s = s0 + si;
            if (s >= S_) break;
            float sum = 0.f;
            #pragma unroll
            for (int r = 0; r < 16; r++) {
                sum = fmaf(xs[0][si][r], Bs[0][c][r], sum);
                sum = fmaf(xs[1][si][r], Bs[1][c][r], sum);
            }
            size_t off = ((size_t)b * S_ + s) * D_ + cn + c;
            float v = Yz[off] + sum;
            __nv_bfloat16 hb = __float2bfloat16(v);
            Yhi[off] = hb;
            Ylo[off] = __float2bfloat16(v - __bfloat162float(hb));
        }
    }
}

// ---------------- host launcher --------------------------------------------
extern "C" void kernel_launch(void* const* d_in, const int* in_sizes, int n_in,
                              void* d_out, int out_size)
{
    const float* hs    = (const float*)d_in[0];
    const int*   idx   = (const int*)  d_in[1];
    const float* gates = (const float*)d_in[2];
    const float* wq = (const float*)d_in[3];  const float* Aq = (const float*)d_in[4];
    const float* Bq = (const float*)d_in[5];  const float* bq = (const float*)d_in[6];
    const float* wk = (const float*)d_in[7];  const float* Ak = (const float*)d_in[8];
    const float* Bk = (const float*)d_in[9];  const float* bk = (const float*)d_in[10];
    const float* wv = (const float*)d_in[11]; const float* Av = (const float*)d_in[12];
    const float* Bv = (const float*)d_in[13]; const float* bv = (const float*)d_in[14];
    const float* wo = (const float*)d_in[15]; const float* Ao = (const float*)d_in[16];
    const float* Bo = (const float*)d_in[17]; const float* bo = (const float*)d_in[18];
    float* out = (float*)d_out;

    float *tmp, *x2, *xa;
    __nv_bfloat16 *xhi, *xlo, *whi, *wlo, *qhi, *qlo, *khi, *klo, *vhi, *vlo;
    cudaGetSymbolAddress((void**)&tmp, g_tmp);
    cudaGetSymbolAddress((void**)&x2,  g_x2);
    cudaGetSymbolAddress((void**)&xa,  g_xa);
    cudaGetSymbolAddress((void**)&xhi, g_xhi);
    cudaGetSymbolAddress((void**)&xlo, g_xlo);
    cudaGetSymbolAddress((void**)&whi, g_whi);
    cudaGetSymbolAddress((void**)&wlo, g_wlo);
    cudaGetSymbolAddress((void**)&qhi, g_qhi);
    cudaGetSymbolAddress((void**)&qlo, g_qlo);
    cudaGetSymbolAddress((void**)&khi, g_khi);
    cudaGetSymbolAddress((void**)&klo, g_klo);
    cudaGetSymbolAddress((void**)&vhi, g_vhi);
    cudaGetSymbolAddress((void**)&vlo, g_vlo);

    cudaFuncSetAttribute(mma_gemm_qkv, cudaFuncAttributeMaxDynamicSharedMemorySize, GEMM_SMEM);
    cudaFuncSetAttribute(mma_gemm, cudaFuncAttributeMaxDynamicSharedMemorySize, GEMM_SMEM);
    cudaFuncSetAttribute(flash_attn, cudaFuncAttributeMaxDynamicSharedMemorySize, FA_SMEM);
    cudaFuncSetAttribute(attn_tail, cudaFuncAttributeMaxDynamicSharedMemorySize, TAIL_SMEM);

    static cudaStream_t s1 = nullptr, s2 = nullptr, s3 = nullptr;
    static cudaEvent_t evR, evW, evXA[2], evQK[2], evLQK[2], evLV[2],
                       evT[2], evF[2], evXO[2], evEnd;
    if (!s1) {
        cudaStreamCreateWithFlags(&s1, cudaStreamNonBlocking);
        cudaStreamCreateWithFlags(&s2, cudaStreamNonBlocking);
        cudaStreamCreateWithFlags(&s3, cudaStreamNonBlocking);
        cudaEventCreateWithFlags(&evR, cudaEventDisableTiming);
        cudaEventCreateWithFlags(&evW, cudaEventDisableTiming);
        for (int i = 0; i < 2; ++i) {
            cudaEventCreateWithFlags(&evXA[i], cudaEventDisableTiming);
            cudaEventCreateWithFlags(&evQK[i], cudaEventDisableTiming);
            cudaEventCreateWithFlags(&evLQK[i], cudaEventDisableTiming);
            cudaEventCreateWithFlags(&evLV[i], cudaEventDisableTiming);
            cudaEventCreateWithFlags(&evT[i], cudaEventDisableTiming);
            cudaEventCreateWithFlags(&evF[i], cudaEventDisableTiming);
            cudaEventCreateWithFlags(&evXO[i], cudaEventDisableTiming);
        }
        cudaEventCreateWithFlags(&evEnd, cudaEventDisableTiming);
    }

    const int nw4 = D_ * D_ / 4;
    const int nh4 = MH_ * D_ / 4;
    cudaStream_t ws[2] = {s2, s3};

    // ---- initial forks: qkv W split on s2 (wo deferred); per-half xa ----
    cudaEventRecord(evR, 0);
    cudaStreamWaitEvent(s1, evR, 0);
    cudaStreamWaitEvent(s2, evR, 0);
    cudaStreamWaitEvent(s3, evR, 0);
    split_w3<<<dim3((nw4 + 255) / 256, 3), 256, 0, s2>>>(
        (const float4*)wq, (const float4*)wk, (const float4*)wv,
        (uint2*)whi, (uint2*)wlo);
    cudaEventRecord(evW, s2);
    split_bf16<<<(nw4 + 255) / 256, 256, 0, s2>>>(
        (const float4*)wo, (uint2*)(whi + (size_t)3 * D_ * D_),
        (uint2*)(wlo + (size_t)3 * D_ * D_), nw4);
    xa_kernel<<<dim3(BH_, KE_, 24), 256, 0, s2>>>(hs, Aq, Ak, Av, idx, xa, 0);
    cudaEventRecord(evXA[0], s2);
    xa_kernel<<<dim3(BH_, KE_, 24), 256, 0, s3>>>(hs, Aq, Ak, Av, idx, xa, BH_);
    cudaEventRecord(evXA[1], s3);

    // ---- per-half pipelines on stream 0 (half 0) and s1 (half 1) ----
    for (int h = 0; h < 2; ++h) {
        cudaStream_t st = h ? s1 : 0;
        cudaStream_t wk2 = ws[h];
        const int b0 = h * BH_;
        const int m0 = h * MH_;
        const int mmax = m0 + MH_;
        const int bh0 = b0 * H_;

        split_bf16<<<(nh4 + 255) / 256, 256, 0, st>>>(
            (const float4*)(hs + (size_t)m0 * D_),
            (uint2*)(xhi + (size_t)m0 * D_), (uint2*)(xlo + (size_t)m0 * D_), nh4);

        cudaStreamWaitEvent(st, evW, 0);
        // gemm q,k first
        mma_gemm_qkv<<<dim3(8, 33, 2), 256, GEMM_SMEM, st>>>(
            xhi, xlo, whi, wlo, bq, bk, bv, tmp, m0, mmax, 0);
        cudaEventRecord(evQK[h], st);

        // fork: lora_split(q,k) on worker, overlapping v-gemm
        cudaStreamWaitEvent(wk2, evQK[h], 0);
        cudaStreamWaitEvent(wk2, evXA[h], 0);
        lora_split3<<<dim3(BH_, 16, 2), 256, 0, wk2>>>(
            Bq, Bk, Bv, idx, gates, xa, tmp, qhi, qlo, khi, klo, vhi, vlo, b0, 0);
        cudaEventRecord(evLQK[h], wk2);

        // gemm v on main
        mma_gemm_qkv<<<dim3(8, 33, 1), 256, GEMM_SMEM, st>>>(
            xhi, xlo, whi, wlo, bq, bk, bv, tmp, m0, mmax, 2);

        cudaStreamWaitEvent(st, evXA[h], 0);
        lora_split3<<<dim3(BH_, 16, 1), 256, 0, st>>>(
            Bq, Bk, Bv, idx, gates, xa, tmp, qhi, qlo, khi, klo, vhi, vlo, b0, 2);
        cudaEventRecord(evLV[h], st);
        cudaStreamWaitEvent(st, evLQK[h], 0);

        // fork: attn_tail on worker concurrent with flash_attn
        cudaStreamWaitEvent(wk2, evLV[h], 0);
        attn_tail<<<BH_ * H_, 256, TAIL_SMEM, wk2>>>(
            qhi, qlo, khi, klo, vhi, vlo, x2, xhi, xlo, bh0);
        cudaEventRecord(evT[h], wk2);

        flash_attn<<<dim3(BH_ * H_, 4), 128, FA_SMEM, st>>>(
            qhi, qlo, khi, klo, vhi, vlo, x2, xhi, xlo, bh0);
        cudaStreamWaitEvent(st, evT[h], 0);

        // fork: xa(O) on worker concurrent with O GEMM
        cudaEventRecord(evF[h], st);
        cudaStreamWaitEvent(wk2, evF[h], 0);
        xa_kernel<<<dim3(BH_, KE_, 8), 256, 0, wk2>>>(x2, Ao, Ao, Ao, idx, xa, b0);
        cudaEventRecord(evXO[h], wk2);

        mma_gemm<<<dim3(8, 33), 256, GEMM_SMEM, st>>>(
            xhi, xlo, whi + (size_t)3 * D_ * D_, wlo + (size_t)3 * D_ * D_,
            bo, out, 1.f, m0, mmax);

        cudaStreamWaitEvent(st, evXO[h], 0);
        lora_add<<<dim3(BH_, 16), 256, 0, st>>>(Bo, idx, gates, xa, out, 1.f, b0);
    }

    cudaEventRecord(evEnd, s1);
    cudaStreamWaitEvent(0, evEnd, 0);
}